// round 10
// baseline (speedup 1.0000x reference)
#include <cuda_runtime.h>
#include <cuda_fp16.h>
#include <cstdint>
#include <cstddef>

#define D_MODEL 1024
#define NHEAD   16
#define DKH     64
#define BATCH   8
#define SEQ     1024
#define MROWS   (BATCH * SEQ)   // 8192

// ---------------- scratch (device globals: no cudaMalloc allowed) ----------------
__device__ float g_qh[MROWS * D_MODEL];    // carved as Q h/l split (ushort x2)
__device__ float g_vh[MROWS * D_MODEL];    // fp32 V (for vtrans)
__device__ float g_ctx[MROWS * D_MODEL];   // carved as ctx h/l split (ushort x2)
__device__ float g_fc[MROWS * D_MODEL];
// fp16 2-level split operands
__device__ __align__(16) unsigned short g_a0[MROWS * D_MODEL];
__device__ __align__(16) unsigned short g_a1[MROWS * D_MODEL];
__device__ __align__(16) unsigned short g_b0[D_MODEL * D_MODEL];
__device__ __align__(16) unsigned short g_b1[D_MODEL * D_MODEL];
__device__ __align__(16) unsigned short g_k0s[MROWS * D_MODEL];
__device__ __align__(16) unsigned short g_k1s[MROWS * D_MODEL];
__device__ __align__(16) unsigned short g_v0t[MROWS * D_MODEL];   // [bh][d][token]
__device__ __align__(16) unsigned short g_v1t[MROWS * D_MODEL];

// =================================================================================
// helpers
// =================================================================================
__device__ __forceinline__ uint32_t smem_u32(const void* p) {
    uint32_t a;
    asm("{ .reg .u64 t; cvta.to.shared.u64 t, %1; cvt.u32.u64 %0, t; }" : "=r"(a) : "l"(p));
    return a;
}
__device__ __forceinline__ void ldsm_x4(uint32_t* r, uint32_t addr) {
    asm volatile("ldmatrix.sync.aligned.m8n8.x4.shared.b16 {%0,%1,%2,%3}, [%4];"
        : "=r"(r[0]), "=r"(r[1]), "=r"(r[2]), "=r"(r[3]) : "r"(addr));
}
__device__ __forceinline__ void mma_f16(float* c, const uint32_t* a, const uint32_t* b) {
    asm volatile("mma.sync.aligned.m16n8k16.row.col.f32.f16.f16.f32 "
        "{%0,%1,%2,%3}, {%4,%5,%6,%7}, {%8,%9}, {%0,%1,%2,%3};"
        : "+f"(c[0]), "+f"(c[1]), "+f"(c[2]), "+f"(c[3])
        : "r"(a[0]), "r"(a[1]), "r"(a[2]), "r"(a[3]), "r"(b[0]), "r"(b[1]));
}
__device__ __forceinline__ void cp16(uint32_t dst, const void* src) {
    asm volatile("cp.async.cg.shared.global [%0], [%1], 16;" :: "r"(dst), "l"(src));
}
__device__ __forceinline__ ushort2 split_h(float x) {
    __half hb = __float2half_rn(x);
    float hf = __half2float(hb);
    __half lb = __float2half_rn(x - hf);
    return make_ushort2(__half_as_ushort(hb), __half_as_ushort(lb));
}

// =================================================================================
// fp32 -> fp16 2-level split (standalone, for raw inputs / weights)
// =================================================================================
__global__ __launch_bounds__(256) void split2h_kernel(
    const float* __restrict__ x, unsigned short* __restrict__ h,
    unsigned short* __restrict__ l, int n4)
{
    int i = blockIdx.x * 256 + threadIdx.x;
    if (i >= n4) return;
    float4 v = ((const float4*)x)[i];
    float vv[4] = { v.x, v.y, v.z, v.w };
    unsigned short hh[4], ll[4];
#pragma unroll
    for (int j = 0; j < 4; j++) {
        __half hb = __float2half_rn(vv[j]);
        float r1 = vv[j] - __half2float(hb);
        __half lb = __float2half_rn(r1);
        hh[j] = __half_as_ushort(hb);
        ll[j] = __half_as_ushort(lb);
    }
    ((ushort4*)h)[i] = make_ushort4(hh[0], hh[1], hh[2], hh[3]);
    ((ushort4*)l)[i] = make_ushort4(ll[0], ll[1], ll[2], ll[3]);
}

// =================================================================================
// V transpose + split:  g_vh[token][h*64+d] -> g_v{0,1}t[(bh*64+d)*1024 + token]
// =================================================================================
__global__ __launch_bounds__(256) void vtrans_kernel()
{
    __shared__ float ttile[32][33];
    const int bh = blockIdx.z, b = bh >> 4, h = bh & 15;
    const int t0 = blockIdx.x * 32, d0 = blockIdx.y * 32;
    const int tx = threadIdx.x, ty = threadIdx.y;
#pragma unroll
    for (int j = 0; j < 4; j++) {
        int tok = t0 + ty + j * 8;
        ttile[ty + j * 8][tx] =
            g_vh[(size_t)(b * SEQ + tok) * D_MODEL + h * DKH + d0 + tx];
    }
    __syncthreads();
#pragma unroll
    for (int j = 0; j < 4; j++) {
        int d = d0 + ty + j * 8;
        float x = ttile[tx][ty + j * 8];
        __half hb = __float2half_rn(x);
        __half lb = __float2half_rn(x - __half2float(hb));
        size_t o = ((size_t)bh * DKH + d) * SEQ + t0 + tx;
        g_v0t[o] = __half_as_ushort(hb);
        g_v1t[o] = __half_as_ushort(lb);
    }
}

// =================================================================================
// 2-level fp16 mma GEMM, tile 256(M) x 64(N), 8 warps each 32M x 64N.
// KC=32, 2-stage cp.async, 2 CTAs/SM. Passes: hh, lh, [hl], [ll].
// =================================================================================
#define KC      32
#define NCHUNK  (D_MODEL / KC)      // 32
#define TLD     80
#define A_ROWS  256
#define B_ROWS  64
#define A_LEV   (A_ROWS * TLD)      // 20480
#define B_LEV   (B_ROWS * TLD)      // 5120
#define STG     (2 * A_LEV + 2 * B_LEV)   // 51200
#define GSM     (2 * STG)                 // 102400

template<int NPASS, bool SPLIT_OUT>
__global__ void __launch_bounds__(256, 2) gemm_2h(
    const unsigned short* __restrict__ A0, const unsigned short* __restrict__ A1,
    const unsigned short* __restrict__ B0, const unsigned short* __restrict__ B1,
    const float* __restrict__ bias,
    float* __restrict__ C,
    unsigned short* __restrict__ H, unsigned short* __restrict__ L)
{
    extern __shared__ char smc[];
    const uint32_t sbase = smem_u32(smc);
    const int tid = threadIdx.x, wid = tid >> 5, lane = tid & 31;
    const int bn = blockIdx.x, bm = blockIdx.y;

    const unsigned short* srcs[4];
    srcs[0] = A0 + (size_t)bm * A_ROWS * D_MODEL;
    srcs[1] = A1 + (size_t)bm * A_ROWS * D_MODEL;
    srcs[2] = B0 + (size_t)bn * B_ROWS * D_MODEL;
    srcs[3] = B1 + (size_t)bn * B_ROWS * D_MODEL;

    float acc[2][8][4];
#pragma unroll
    for (int i = 0; i < 2; i++)
#pragma unroll
        for (int j = 0; j < 8; j++)
#pragma unroll
            for (int v = 0; v < 4; v++) acc[i][j][v] = 0.f;

    const uint32_t a_l = (uint32_t)(wid * 32 + (lane & 15)) * TLD + ((lane >> 4) & 1) * 16;
    const uint32_t b_l = (uint32_t)((lane & 7) + ((lane >> 4) & 1) * 8) * TLD
                       + ((lane >> 3) & 1) * 16;

    auto fill = [&](int c, int s) {
        const uint32_t base = sbase + (uint32_t)s * STG;
#pragma unroll
        for (int n = 0; n < 10; n++) {
            int i = tid + n * 256;                  // 0..2559
            const unsigned short* src;
            uint32_t dst;
            if (i < 2048) {                         // A: 2 lev x 256 rows
                int lev = i >> 10, j = i & 1023;
                int r = j >> 2, c16 = j & 3;
                src = srcs[lev] + (size_t)r * D_MODEL + c * KC + c16 * 8;
                dst = base + (uint32_t)lev * A_LEV + (uint32_t)r * TLD + c16 * 16;
            } else {                                // B: 2 lev x 64 rows
                int j = i - 2048;
                int lev = j >> 8, jj = j & 255;
                int r = jj >> 2, c16 = jj & 3;
                src = srcs[2 + lev] + (size_t)r * D_MODEL + c * KC + c16 * 8;
                dst = base + 2u * A_LEV + (uint32_t)lev * B_LEV + (uint32_t)r * TLD + c16 * 16;
            }
            cp16(dst, src);
        }
        asm volatile("cp.async.commit_group;" ::: "memory");
    };

    fill(0, 0);
    fill(1, 1);

    for (int c = 0; c < NCHUNK; c++) {
        if (c + 1 < NCHUNK)
            asm volatile("cp.async.wait_group 1;" ::: "memory");
        else
            asm volatile("cp.async.wait_group 0;" ::: "memory");
        __syncthreads();

        const uint32_t abase = sbase + (uint32_t)(c & 1) * STG;
        const uint32_t bbase = abase + 2 * A_LEV;

#pragma unroll
        for (int kb = 0; kb < 2; kb++) {
            const uint32_t kbyte = kb * 32;
            uint32_t af[2][2][4];
#pragma unroll
            for (int lv = 0; lv < 2; lv++)
#pragma unroll
                for (int mt = 0; mt < 2; mt++)
                    ldsm_x4(af[lv][mt], abase + lv * A_LEV + a_l + mt * (16 * TLD) + kbyte);

            uint32_t bfr[4][4];
#pragma unroll
            for (int np = 0; np < 4; np++)
                ldsm_x4(bfr[np], bbase + b_l + np * (16 * TLD) + kbyte);
#pragma unroll
            for (int mt = 0; mt < 2; mt++)
#pragma unroll
                for (int nt = 0; nt < 8; nt++)
                    mma_f16(acc[mt][nt], af[0][mt], &bfr[nt >> 1][(nt & 1) * 2]);   // hh
#pragma unroll
            for (int mt = 0; mt < 2; mt++)
#pragma unroll
                for (int nt = 0; nt < 8; nt++)
                    mma_f16(acc[mt][nt], af[1][mt], &bfr[nt >> 1][(nt & 1) * 2]);   // lh
            if (NPASS >= 3) {
#pragma unroll
                for (int np = 0; np < 4; np++)
                    ldsm_x4(bfr[np], bbase + B_LEV + b_l + np * (16 * TLD) + kbyte);
#pragma unroll
                for (int mt = 0; mt < 2; mt++)
#pragma unroll
                    for (int nt = 0; nt < 8; nt++)
                        mma_f16(acc[mt][nt], af[0][mt], &bfr[nt >> 1][(nt & 1) * 2]); // hl
                if (NPASS == 4) {
#pragma unroll
                    for (int mt = 0; mt < 2; mt++)
#pragma unroll
                        for (int nt = 0; nt < 8; nt++)
                            mma_f16(acc[mt][nt], af[1][mt], &bfr[nt >> 1][(nt & 1) * 2]); // ll
                }
            }
        }
        __syncthreads();
        if (c + 2 < NCHUNK) fill(c + 2, c & 1);
    }

    // epilogue
    const int qr = lane >> 2;
#pragma unroll
    for (int mt = 0; mt < 2; mt++) {
        int row0 = bm * A_ROWS + wid * 32 + mt * 16 + qr;
#pragma unroll
        for (int nt = 0; nt < 8; nt++) {
            int col = bn * B_ROWS + nt * 8 + (lane & 3) * 2;
            float v00 = acc[mt][nt][0] + bias[col];
            float v01 = acc[mt][nt][1] + bias[col + 1];
            float v10 = acc[mt][nt][2] + bias[col];
            float v11 = acc[mt][nt][3] + bias[col + 1];
            if (SPLIT_OUT) {
                ushort2 h0 = split_h(v00), h1 = split_h(v01);
                ushort2 h2 = split_h(v10), h3 = split_h(v11);
                *(ushort2*)(H + (size_t)row0 * D_MODEL + col)       = make_ushort2(h0.x, h1.x);
                *(ushort2*)(L + (size_t)row0 * D_MODEL + col)       = make_ushort2(h0.y, h1.y);
                *(ushort2*)(H + (size_t)(row0 + 8) * D_MODEL + col) = make_ushort2(h2.x, h3.x);
                *(ushort2*)(L + (size_t)(row0 + 8) * D_MODEL + col) = make_ushort2(h2.y, h3.y);
            } else {
                float2 v0 = { v00, v01 }, v1 = { v10, v11 };
                *(float2*)(C + (size_t)row0 * D_MODEL + col)       = v0;
                *(float2*)(C + (size_t)(row0 + 8) * D_MODEL + col) = v1;
            }
        }
    }
}

// =================================================================================
// mma attention: CTA = (b, h, 32 q-rows), 256 thr. O epilogue emits ctx h/l split.
// =================================================================================
#define PS_LD     1032
#define PS_BYTES  (32 * PS_LD * 4)       // 132096
#define KROWB     144
#define KLEV      (128 * KROWB)
#define KSTG      (2 * KLEV)             // 36864
#define VROWB     272
#define VLEV      (64 * VROWB)
#define VSTG      (2 * VLEV)             // 34816
#define ATTN_SMEM (PS_BYTES + 2 * KSTG)  // 205824

__global__ __launch_bounds__(256) void attn_mma(
    const unsigned char* __restrict__ mask, float* __restrict__ attn_out,
    const unsigned short* __restrict__ Q0, const unsigned short* __restrict__ Q1,
    unsigned short* __restrict__ C0, unsigned short* __restrict__ C1)
{
    extern __shared__ char smraw[];
    float* Ps = (float*)smraw;
    const uint32_t tbase = smem_u32(smraw) + PS_BYTES;

    const int t = threadIdx.x, w = t >> 5, lane = t & 31;
    const int qt = blockIdx.x, h = blockIdx.y, b = blockIdx.z;
    const int q0 = qt * 32;

    uint32_t af[2][2][4][4];
    {
        const unsigned short* qs[2] = { Q0, Q1 };
        const int r0 = lane >> 2;
        const int c0 = (lane & 3) * 2;
#pragma unroll
        for (int lv = 0; lv < 2; lv++)
#pragma unroll
            for (int mt = 0; mt < 2; mt++)
#pragma unroll
                for (int ks = 0; ks < 4; ks++) {
                    size_t base = (size_t)(b * SEQ + q0 + mt * 16 + r0) * D_MODEL
                                + h * DKH + ks * 16 + c0;
                    af[lv][mt][ks][0] = *(const uint32_t*)(qs[lv] + base);
                    af[lv][mt][ks][1] = *(const uint32_t*)(qs[lv] + base + 8 * D_MODEL);
                    af[lv][mt][ks][2] = *(const uint32_t*)(qs[lv] + base + 8);
                    af[lv][mt][ks][3] = *(const uint32_t*)(qs[lv] + base + 8 * D_MODEL + 8);
                }
    }

    auto kfill = [&](int kt, int s) {
#pragma unroll
        for (int n = 0; n < 8; n++) {
            int i = t + n * 256;
            int lv = i >> 10, j = i & 1023;
            int r = j >> 3, u = j & 7;
            const unsigned short* src = (lv ? g_k1s : g_k0s)
                + (size_t)(b * SEQ + kt * 128 + r) * D_MODEL + h * DKH + u * 8;
            cp16(tbase + s * KSTG + lv * KLEV + (uint32_t)r * KROWB + u * 16, src);
        }
        asm volatile("cp.async.commit_group;" ::: "memory");
    };
    const uint32_t krow = (uint32_t)(w * 16 + (lane & 7) + ((lane >> 4) & 1) * 8) * KROWB
                        + ((lane >> 3) & 1) * 16;
    kfill(0, 0);
    kfill(1, 1);

    for (int kt = 0; kt < 8; kt++) {
        if (kt < 7) asm volatile("cp.async.wait_group 1;" ::: "memory");
        else        asm volatile("cp.async.wait_group 0;" ::: "memory");
        __syncthreads();
        const uint32_t kb = tbase + (kt & 1) * KSTG;

        uint32_t bf[2][4][4];
#pragma unroll
        for (int lv = 0; lv < 2; lv++)
#pragma unroll
            for (int ks = 0; ks < 4; ks++)
                ldsm_x4(bf[lv][ks], kb + lv * KLEV + krow + ks * 32);

        float acc[2][2][4];
#pragma unroll
        for (int i = 0; i < 2; i++)
#pragma unroll
            for (int j = 0; j < 2; j++)
#pragma unroll
                for (int v = 0; v < 4; v++) acc[i][j][v] = 0.f;

#pragma unroll
        for (int ks = 0; ks < 4; ks++) {
#pragma unroll
            for (int mt = 0; mt < 2; mt++)
#pragma unroll
                for (int nt = 0; nt < 2; nt++) {
                    mma_f16(acc[mt][nt], af[0][mt][ks], &bf[0][ks][nt * 2]);
                    mma_f16(acc[mt][nt], af[0][mt][ks], &bf[1][ks][nt * 2]);
                    mma_f16(acc[mt][nt], af[1][mt][ks], &bf[0][ks][nt * 2]);
                }
        }

#pragma unroll
        for (int mt = 0; mt < 2; mt++) {
#pragma unroll
            for (int nt = 0; nt < 2; nt++) {
                int row = mt * 16 + (lane >> 2);
                int col = kt * 128 + w * 16 + nt * 8 + (lane & 3) * 2;
                const unsigned char* mp0 =
                    mask + (size_t)(b * SEQ + q0 + row) * SEQ + col;
                const unsigned char* mp1 = mp0 + 8 * SEQ;
                float2 v0, v1;
                v0.x = mp0[0] ? -1e9f : acc[mt][nt][0] * 0.125f;
                v0.y = mp0[1] ? -1e9f : acc[mt][nt][1] * 0.125f;
                v1.x = mp1[0] ? -1e9f : acc[mt][nt][2] * 0.125f;
                v1.y = mp1[1] ? -1e9f : acc[mt][nt][3] * 0.125f;
                *(float2*)&Ps[row * PS_LD + col]       = v0;
                *(float2*)&Ps[(row + 8) * PS_LD + col] = v1;
            }
        }
        __syncthreads();
        if (kt + 2 < 8) kfill(kt + 2, kt & 1);
    }
    __syncthreads();

    {
        int row = t >> 3, sub = t & 7;
        float* pr = Ps + row * PS_LD;
        float m = -1e30f;
        for (int cc = sub; cc < SEQ; cc += 8) m = fmaxf(m, pr[cc]);
#pragma unroll
        for (int o = 4; o > 0; o >>= 1) m = fmaxf(m, __shfl_xor_sync(0xffffffffu, m, o, 8));
        float s = 0.f;
        for (int cc = sub; cc < SEQ; cc += 8) { float e = __expf(pr[cc] - m); pr[cc] = e; s += e; }
#pragma unroll
        for (int o = 4; o > 0; o >>= 1) s += __shfl_xor_sync(0xffffffffu, s, o, 8);
        float inv = 1.0f / s;
        for (int cc = sub; cc < SEQ; cc += 8) pr[cc] *= inv;
    }
    __syncthreads();

    if (attn_out) {
        float* ab = attn_out + (((size_t)(b * NHEAD + h)) * SEQ + q0) * SEQ;
#pragma unroll
        for (int i = 0; i < 32; i++) {
            int idx = t + i * 256;
            int r  = idx >> 8;
            int c4 = (idx & 255) << 2;
            *(float4*)&ab[(size_t)r * SEQ + c4] = *(const float4*)&Ps[r * PS_LD + c4];
        }
    }
    __syncthreads();

    auto vfill = [&](int kt, int s) {
#pragma unroll
        for (int n = 0; n < 8; n++) {
            int i = t + n * 256;
            int lv = i >> 10, j = i & 1023;
            int r = j >> 4, u = j & 15;
            const unsigned short* src = (lv ? g_v1t : g_v0t)
                + ((size_t)(b * NHEAD + h) * DKH + r) * SEQ + kt * 128 + u * 8;
            cp16(tbase + s * VSTG + lv * VLEV + (uint32_t)r * VROWB + u * 16, src);
        }
        asm volatile("cp.async.commit_group;" ::: "memory");
    };
    const int mh = w & 1, nq = w >> 1;
    const uint32_t vrow = (uint32_t)(nq * 16 + (lane & 7) + ((lane >> 4) & 1) * 8) * VROWB
                        + ((lane >> 3) & 1) * 16;
    float oacc[2][4];
#pragma unroll
    for (int i = 0; i < 2; i++)
#pragma unroll
        for (int v = 0; v < 4; v++) oacc[i][v] = 0.f;

    vfill(0, 0);
    vfill(1, 1);

    const int pr0 = mh * 16 + (lane >> 2);
    const int pc0 = (lane & 3) * 2;

    for (int kt = 0; kt < 8; kt++) {
        if (kt < 7) asm volatile("cp.async.wait_group 1;" ::: "memory");
        else        asm volatile("cp.async.wait_group 0;" ::: "memory");
        __syncthreads();
        const uint32_t vb = tbase + (kt & 1) * VSTG;

#pragma unroll
        for (int ks = 0; ks < 8; ks++) {
            uint32_t bv[2][4];
            ldsm_x4(bv[0], vb + vrow + ks * 32);
            ldsm_x4(bv[1], vb + VLEV + vrow + ks * 32);

            int pc = kt * 128 + ks * 16 + pc0;
            float2 p00 = *(float2*)&Ps[pr0 * PS_LD + pc];
            float2 p10 = *(float2*)&Ps[(pr0 + 8) * PS_LD + pc];
            float2 p01 = *(float2*)&Ps[pr0 * PS_LD + pc + 8];
            float2 p11 = *(float2*)&Ps[(pr0 + 8) * PS_LD + pc + 8];

            uint32_t ph[4], pl[4];
            {
                __half2 h0 = __floats2half2_rn(p00.x, p00.y);
                __half2 h1 = __floats2half2_rn(p10.x, p10.y);
                __half2 h2 = __floats2half2_rn(p01.x, p01.y);
                __half2 h3 = __floats2half2_rn(p11.x, p11.y);
                ph[0] = *(uint32_t*)&h0; ph[1] = *(uint32_t*)&h1;
                ph[2] = *(uint32_t*)&h2; ph[3] = *(uint32_t*)&h3;
                float2 f0 = __half22float2(h0), f1 = __half22float2(h1);
                float2 f2 = __half22float2(h2), f3 = __half22float2(h3);
                __half2 l0 = __floats2half2_rn(p00.x - f0.x, p00.y - f0.y);
                __half2 l1 = __floats2half2_rn(p10.x - f1.x, p10.y - f1.y);
                __half2 l2 = __floats2half2_rn(p01.x - f2.x, p01.y - f2.y);
                __half2 l3 = __floats2half2_rn(p11.x - f3.x, p11.y - f3.y);
                pl[0] = *(uint32_t*)&l0; pl[1] = *(uint32_t*)&l1;
                pl[2] = *(uint32_t*)&l2; pl[3] = *(uint32_t*)&l3;
            }
            mma_f16(oacc[0], ph, &bv[0][0]);
            mma_f16(oacc[1], ph, &bv[0][2]);
            mma_f16(oacc[0], ph, &bv[1][0]);
            mma_f16(oacc[1], ph, &bv[1][2]);
            mma_f16(oacc[0], pl, &bv[0][0]);
            mma_f16(oacc[1], pl, &bv[0][2]);
        }
        __syncthreads();
        if (kt + 2 < 8) vfill(kt + 2, kt & 1);
    }

    {
        int orow = b * SEQ + q0 + pr0;
        int ocol = h * DKH + nq * 16 + pc0;
#pragma unroll
        for (int nt = 0; nt < 2; nt++) {
            ushort2 s0 = split_h(oacc[nt][0]), s1 = split_h(oacc[nt][1]);
            ushort2 s2 = split_h(oacc[nt][2]), s3 = split_h(oacc[nt][3]);
            *(ushort2*)&C0[(size_t)orow * D_MODEL + ocol + nt * 8]       = make_ushort2(s0.x, s1.x);
            *(ushort2*)&C1[(size_t)orow * D_MODEL + ocol + nt * 8]       = make_ushort2(s0.y, s1.y);
            *(ushort2*)&C0[(size_t)(orow + 8) * D_MODEL + ocol + nt * 8] = make_ushort2(s2.x, s3.x);
            *(ushort2*)&C1[(size_t)(orow + 8) * D_MODEL + ocol + nt * 8] = make_ushort2(s2.y, s3.y);
        }
    }
}

// =================================================================================
// Residual add + LayerNorm
// =================================================================================
__global__ __launch_bounds__(256) void ln_kernel(
    const float* __restrict__ fc, const float* __restrict__ resid,
    const float* __restrict__ gamma, const float* __restrict__ beta,
    float* __restrict__ out)
{
    __shared__ float xs[D_MODEL];
    __shared__ float rs[8], rss[8];

    const int row = blockIdx.x;
    const int t   = threadIdx.x;
    const float* f = fc    + (size_t)row * D_MODEL;
    const float* r = resid + (size_t)row * D_MODEL;

    float s = 0.f, ss = 0.f;
    for (int i = t; i < D_MODEL; i += 256) {
        float x = f[i] + r[i];
        xs[i] = x;
        s += x; ss += x * x;
    }
#pragma unroll
    for (int o = 16; o > 0; o >>= 1) {
        s  += __shfl_xor_sync(0xffffffffu, s, o);
        ss += __shfl_xor_sync(0xffffffffu, ss, o);
    }
    int w = t >> 5, lane = t & 31;
    if (lane == 0) { rs[w] = s; rss[w] = ss; }
    __syncthreads();
    float ts = 0.f, tss = 0.f;
#pragma unroll
    for (int i = 0; i < 8; i++) { ts += rs[i]; tss += rss[i]; }
    float mu  = ts * (1.0f / D_MODEL);
    float var = tss * (1.0f / D_MODEL) - mu * mu;
    float kk  = rsqrtf(var + 1e-5f);

    for (int i = t; i < D_MODEL; i += 256)
        out[(size_t)row * D_MODEL + i] = (xs[i] - mu) * kk * gamma[i] + beta[i];
}

// =================================================================================
// launch
// =================================================================================
extern "C" void kernel_launch(void* const* d_in, const int* in_sizes, int n_in,
                              void* d_out, int out_size)
{
    const float* q    = (const float*)d_in[0];
    const float* k    = (const float*)d_in[1];
    const float* v    = (const float*)d_in[2];
    const unsigned char* mask = (const unsigned char*)d_in[3];
    const float* w_q  = (const float*)d_in[4];
    const float* b_q  = (const float*)d_in[5];
    const float* w_k  = (const float*)d_in[6];
    const float* b_k  = (const float*)d_in[7];
    const float* w_v  = (const float*)d_in[8];
    const float* b_v  = (const float*)d_in[9];
    const float* w_fc = (const float*)d_in[10];
    const float* b_fc = (const float*)d_in[11];
    const float* ln_g = (const float*)d_in[12];
    const float* ln_b = (const float*)d_in[13];
    float* out = (float*)d_out;

    float *qh, *vh, *ctx, *fc;
    unsigned short *a0, *a1, *b0, *b1, *k0s, *k1s;
    cudaGetSymbolAddress((void**)&qh,  g_qh);
    cudaGetSymbolAddress((void**)&vh,  g_vh);
    cudaGetSymbolAddress((void**)&ctx, g_ctx);
    cudaGetSymbolAddress((void**)&fc,  g_fc);
    cudaGetSymbolAddress((void**)&a0,  g_a0);
    cudaGetSymbolAddress((void**)&a1,  g_a1);
    cudaGetSymbolAddress((void**)&b0,  g_b0);
    cudaGetSymbolAddress((void**)&b1,  g_b1);
    cudaGetSymbolAddress((void**)&k0s, g_k0s);
    cudaGetSymbolAddress((void**)&k1s, g_k1s);

    unsigned short* q0s = (unsigned short*)qh;
    unsigned short* q1s = q0s + (size_t)MROWS * D_MODEL;
    unsigned short* c0s = (unsigned short*)ctx;
    unsigned short* c1s = c0s + (size_t)MROWS * D_MODEL;

    const long long xe = (long long)MROWS * D_MODEL;
    const long long ae = (long long)BATCH * NHEAD * SEQ * SEQ;
    float* attn_out = nullptr;
    float* x_out    = out;
    if ((long long)out_size >= xe + ae) {
        attn_out = out + xe;
    } else if ((long long)out_size == ae) {
        attn_out = out;
        x_out = nullptr;
    }

    cudaFuncSetAttribute((void*)gemm_2h<3, true>,  cudaFuncAttributeMaxDynamicSharedMemorySize, GSM);
    cudaFuncSetAttribute((void*)gemm_2h<3, false>, cudaFuncAttributeMaxDynamicSharedMemorySize, GSM);
    cudaFuncSetAttribute((void*)attn_mma, cudaFuncAttributeMaxDynamicSharedMemorySize, ATTN_SMEM);

    const int nA4 = MROWS * D_MODEL / 4;
    const int nW4 = D_MODEL * D_MODEL / 4;
    dim3 gb(256);
    dim3 gg(D_MODEL / B_ROWS, MROWS / A_ROWS);   // (16, 32)

    // Q projection -> split output directly (3-pass: hh, lh, hl)
    split2h_kernel<<<nA4 / 256, gb>>>(q, a0, a1, nA4);
    split2h_kernel<<<nW4 / 256, gb>>>(w_q, b0, b1, nW4);
    gemm_2h<3, true><<<gg, gb, GSM>>>(a0, a1, b0, b1, b_q, nullptr, q0s, q1s);

    // K projection -> split output directly
    split2h_kernel<<<nA4 / 256, gb>>>(k, a0, a1, nA4);
    split2h_kernel<<<nW4 / 256, gb>>>(w_k, b0, b1, nW4);
    gemm_2h<3, true><<<gg, gb, GSM>>>(a0, a1, b0, b1, b_k, nullptr, k0s, k1s);

    // V projection -> fp32 (vtrans consumes it)
    split2h_kernel<<<nA4 / 256, gb>>>(v, a0, a1, nA4);
    split2h_kernel<<<nW4 / 256, gb>>>(w_v, b0, b1, nW4);
    gemm_2h<3, false><<<gg, gb, GSM>>>(a0, a1, b0, b1, b_v, vh, nullptr, nullptr);

    vtrans_kernel<<<dim3(SEQ / 32, DKH / 32, BATCH * NHEAD), dim3(32, 8)>>>();

    dim3 ag(SEQ / 32, NHEAD, BATCH);
    attn_mma<<<ag, gb, ATTN_SMEM>>>(mask, attn_out, q0s, q1s, c0s, c1s);

    // FC (ctx split produced by attention epilogue)
    split2h_kernel<<<nW4 / 256, gb>>>(w_fc, b0, b1, nW4);
    gemm_2h<3, false><<<gg, gb, GSM>>>(c0s, c1s, b0, b1, b_fc, fc, nullptr, nullptr);

    if (x_out)
        ln_kernel<<<MROWS, gb>>>(fc, q, ln_g, ln_b, x_out);
}

// round 12
// speedup vs baseline: 1.0388x; 1.0388x over previous
#include <cuda_runtime.h>
#include <cuda_fp16.h>
#include <cstdint>
#include <cstddef>

#define D_MODEL 1024
#define NHEAD   16
#define DKH     64
#define BATCH   8
#define SEQ     1024
#define MROWS   (BATCH * SEQ)   // 8192

// ---------------- scratch (device globals: no cudaMalloc allowed) ----------------
__device__ float g_qh[MROWS * D_MODEL];    // carved as Q h/l split (ushort x2)
__device__ float g_vh[MROWS * D_MODEL];    // fp32 V (for vtrans)
__device__ float g_ctx[MROWS * D_MODEL];   // carved as ctx h/l split (ushort x2)
__device__ float g_fc[MROWS * D_MODEL];
__device__ __align__(16) unsigned short g_a0[MROWS * D_MODEL];
__device__ __align__(16) unsigned short g_a1[MROWS * D_MODEL];
__device__ __align__(16) unsigned short g_b0[D_MODEL * D_MODEL];
__device__ __align__(16) unsigned short g_b1[D_MODEL * D_MODEL];
__device__ __align__(16) unsigned short g_k0s[MROWS * D_MODEL];
__device__ __align__(16) unsigned short g_k1s[MROWS * D_MODEL];
__device__ __align__(16) unsigned short g_v0t[MROWS * D_MODEL];   // [bh][d][token]
__device__ __align__(16) unsigned short g_v1t[MROWS * D_MODEL];

// =================================================================================
// helpers
// =================================================================================
__device__ __forceinline__ uint32_t smem_u32(const void* p) {
    uint32_t a;
    asm("{ .reg .u64 t; cvta.to.shared.u64 t, %1; cvt.u32.u64 %0, t; }" : "=r"(a) : "l"(p));
    return a;
}
__device__ __forceinline__ void ldsm_x4(uint32_t* r, uint32_t addr) {
    asm volatile("ldmatrix.sync.aligned.m8n8.x4.shared.b16 {%0,%1,%2,%3}, [%4];"
        : "=r"(r[0]), "=r"(r[1]), "=r"(r[2]), "=r"(r[3]) : "r"(addr));
}
__device__ __forceinline__ void mma_f16(float* c, const uint32_t* a, const uint32_t* b) {
    asm volatile("mma.sync.aligned.m16n8k16.row.col.f32.f16.f16.f32 "
        "{%0,%1,%2,%3}, {%4,%5,%6,%7}, {%8,%9}, {%0,%1,%2,%3};"
        : "+f"(c[0]), "+f"(c[1]), "+f"(c[2]), "+f"(c[3])
        : "r"(a[0]), "r"(a[1]), "r"(a[2]), "r"(a[3]), "r"(b[0]), "r"(b[1]));
}
__device__ __forceinline__ void cp16(uint32_t dst, const void* src) {
    asm volatile("cp.async.cg.shared.global [%0], [%1], 16;" :: "r"(dst), "l"(src));
}
__device__ __forceinline__ ushort2 split_h(float x) {
    __half hb = __float2half_rn(x);
    float hf = __half2float(hb);
    __half lb = __float2half_rn(x - hf);
    return make_ushort2(__half_as_ushort(hb), __half_as_ushort(lb));
}

// =================================================================================
// fp32 -> fp16 2-level split
// =================================================================================
__global__ __launch_bounds__(256) void split2h_kernel(
    const float* __restrict__ x, unsigned short* __restrict__ h,
    unsigned short* __restrict__ l, int n4)
{
    int i = blockIdx.x * 256 + threadIdx.x;
    if (i >= n4) return;
    float4 v = ((const float4*)x)[i];
    float vv[4] = { v.x, v.y, v.z, v.w };
    unsigned short hh[4], ll[4];
#pragma unroll
    for (int j = 0; j < 4; j++) {
        __half hb = __float2half_rn(vv[j]);
        float r1 = vv[j] - __half2float(hb);
        __half lb = __float2half_rn(r1);
        hh[j] = __half_as_ushort(hb);
        ll[j] = __half_as_ushort(lb);
    }
    ((ushort4*)h)[i] = make_ushort4(hh[0], hh[1], hh[2], hh[3]);
    ((ushort4*)l)[i] = make_ushort4(ll[0], ll[1], ll[2], ll[3]);
}

// =================================================================================
// V transpose + split
// =================================================================================
__global__ __launch_bounds__(256) void vtrans_kernel()
{
    __shared__ float ttile[32][33];
    const int bh = blockIdx.z, b = bh >> 4, h = bh & 15;
    const int t0 = blockIdx.x * 32, d0 = blockIdx.y * 32;
    const int tx = threadIdx.x, ty = threadIdx.y;
#pragma unroll
    for (int j = 0; j < 4; j++) {
        int tok = t0 + ty + j * 8;
        ttile[ty + j * 8][tx] =
            g_vh[(size_t)(b * SEQ + tok) * D_MODEL + h * DKH + d0 + tx];
    }
    __syncthreads();
#pragma unroll
    for (int j = 0; j < 4; j++) {
        int d = d0 + ty + j * 8;
        float x = ttile[tx][ty + j * 8];
        __half hb = __float2half_rn(x);
        __half lb = __float2half_rn(x - __half2float(hb));
        size_t o = ((size_t)bh * DKH + d) * SEQ + t0 + tx;
        g_v0t[o] = __half_as_ushort(hb);
        g_v1t[o] = __half_as_ushort(lb);
    }
}

// =================================================================================
// 2-level fp16 mma GEMM — round-9 build (3-stage ring, 128x64 tile)
// =================================================================================
#define KC         32
#define NCHUNK     (D_MODEL / KC)
#define TLD        80
#define AT_BYTES   (128 * TLD)
#define BT_BYTES   (64 * TLD)
#define STAGE      (2 * AT_BYTES + 2 * BT_BYTES)   // 30720
#define GSMEM3     (3 * STAGE)                     // 92160

template<int NPASS, bool SPLIT_OUT>
__global__ void __launch_bounds__(256, 2) gemm_2h(
    const unsigned short* __restrict__ A0, const unsigned short* __restrict__ A1,
    const unsigned short* __restrict__ B0, const unsigned short* __restrict__ B1,
    const float* __restrict__ bias,
    float* __restrict__ C,
    unsigned short* __restrict__ H, unsigned short* __restrict__ L)
{
    extern __shared__ char smc[];
    const uint32_t sbase = smem_u32(smc);
    const int tid = threadIdx.x, wid = tid >> 5, lane = tid & 31;
    const int bn = blockIdx.x, bm = blockIdx.y;
    const int wm = wid & 3, wn = wid >> 2;

    const unsigned short* srcs[4];
    srcs[0] = A0 + (size_t)bm * 128 * D_MODEL;
    srcs[1] = A1 + (size_t)bm * 128 * D_MODEL;
    srcs[2] = B0 + (size_t)bn * 64 * D_MODEL;
    srcs[3] = B1 + (size_t)bn * 64 * D_MODEL;

    float acc[2][4][4];
#pragma unroll
    for (int i = 0; i < 2; i++)
#pragma unroll
        for (int j = 0; j < 4; j++)
#pragma unroll
            for (int v = 0; v < 4; v++) acc[i][j][v] = 0.f;

    const uint32_t a_l = (uint32_t)(wm * 32 + (lane & 15)) * TLD + ((lane >> 4) & 1) * 16;
    const uint32_t b_l = (uint32_t)(wn * 32 + (lane & 7) + ((lane >> 4) & 1) * 8) * TLD
                       + ((lane >> 3) & 1) * 16;

    auto fill = [&](int c, int s) {
        const uint32_t base = sbase + (uint32_t)s * STAGE;
#pragma unroll
        for (int n = 0; n < 6; n++) {
            int i = tid + n * 256;
            bool isA = i < 1024;
            int j   = isA ? i : i - 1024;
            int lev = isA ? (j >> 9) : (j >> 8);
            int r   = isA ? ((j >> 2) & 127) : ((j >> 2) & 63);
            int c16 = j & 3;
            const unsigned short* src = srcs[(isA ? 0 : 2) + lev]
                + (size_t)r * D_MODEL + c * KC + c16 * 8;
            uint32_t dst = base + (isA ? (uint32_t)lev * AT_BYTES
                                       : 2u * AT_BYTES + (uint32_t)lev * BT_BYTES)
                         + (uint32_t)r * TLD + c16 * 16;
            cp16(dst, src);
        }
        asm volatile("cp.async.commit_group;" ::: "memory");
    };

    fill(0, 0);
    fill(1, 1);

    constexpr int PA[4] = { 0, 0, 1, 1 };
    constexpr int PB[4] = { 0, 1, 0, 1 };

    int stage = 0;
    for (int c = 0; c < NCHUNK; c++) {
        if (c + 1 < NCHUNK)
            asm volatile("cp.async.wait_group 1;" ::: "memory");
        else
            asm volatile("cp.async.wait_group 0;" ::: "memory");
        __syncthreads();

        if (c + 2 < NCHUNK) {
            int fs = stage + 2; if (fs >= 3) fs -= 3;
            fill(c + 2, fs);
        }

        const uint32_t abase = sbase + (uint32_t)stage * STAGE;
        const uint32_t bbase = abase + 2 * AT_BYTES;

#pragma unroll
        for (int kb = 0; kb < 2; kb++) {
            const uint32_t kbyte = kb * 32;
            uint32_t af[2][2][4], bfr[2][2][4];
#pragma unroll
            for (int lv = 0; lv < 2; lv++) {
#pragma unroll
                for (int mt = 0; mt < 2; mt++)
                    ldsm_x4(af[lv][mt], abase + lv * AT_BYTES + a_l + mt * (16 * TLD) + kbyte);
#pragma unroll
                for (int np = 0; np < 2; np++)
                    ldsm_x4(bfr[lv][np], bbase + lv * BT_BYTES + b_l + np * (16 * TLD) + kbyte);
            }
#pragma unroll
            for (int p = 0; p < NPASS; p++) {
#pragma unroll
                for (int mt = 0; mt < 2; mt++)
#pragma unroll
                    for (int nt = 0; nt < 4; nt++)
                        mma_f16(acc[mt][nt], af[PA[p]][mt],
                                &bfr[PB[p]][nt >> 1][(nt & 1) * 2]);
            }
        }
        if (++stage == 3) stage = 0;
    }

    const int qr = lane >> 2;
#pragma unroll
    for (int mt = 0; mt < 2; mt++) {
        int row0 = bm * 128 + wm * 32 + mt * 16 + qr;
#pragma unroll
        for (int nt = 0; nt < 4; nt++) {
            int col = bn * 64 + wn * 32 + nt * 8 + (lane & 3) * 2;
            float v00 = acc[mt][nt][0] + bias[col];
            float v01 = acc[mt][nt][1] + bias[col + 1];
            float v10 = acc[mt][nt][2] + bias[col];
            float v11 = acc[mt][nt][3] + bias[col + 1];
            if (SPLIT_OUT) {
                ushort2 h0 = split_h(v00), h1 = split_h(v01);
                ushort2 h2 = split_h(v10), h3 = split_h(v11);
                *(ushort2*)(H + (size_t)row0 * D_MODEL + col)       = make_ushort2(h0.x, h1.x);
                *(ushort2*)(L + (size_t)row0 * D_MODEL + col)       = make_ushort2(h0.y, h1.y);
                *(ushort2*)(H + (size_t)(row0 + 8) * D_MODEL + col) = make_ushort2(h2.x, h3.x);
                *(ushort2*)(L + (size_t)(row0 + 8) * D_MODEL + col) = make_ushort2(h2.y, h3.y);
            } else {
                float2 v0 = { v00, v01 }, v1 = { v10, v11 };
                *(float2*)(C + (size_t)row0 * D_MODEL + col)       = v0;
                *(float2*)(C + (size_t)(row0 + 8) * D_MODEL + col) = v1;
            }
        }
    }
}

// =================================================================================
// mma attention — round-9 proven build, PV reduced to 2 passes (Ph*Vh + Ph*Vl).
// fp32 scores in smem (REQUIRED: score sigma ~65k exceeds fp16 range/precision);
// P quantized to fp16 only post-softmax.
// =================================================================================
#define PS_LD     1032
#define PS_BYTES  (32 * PS_LD * 4)       // 132096
#define KROWB     144
#define KLEV      (128 * KROWB)
#define KSTG      (2 * KLEV)             // 36864
#define VROWB     272
#define VLEV      (64 * VROWB)
#define VSTG      (2 * VLEV)             // 34816
#define ATTN_SMEM (PS_BYTES + 2 * KSTG)  // 205824

__global__ __launch_bounds__(256) void attn_mma(
    const unsigned char* __restrict__ mask, float* __restrict__ attn_out,
    const unsigned short* __restrict__ Q0, const unsigned short* __restrict__ Q1,
    unsigned short* __restrict__ C0, unsigned short* __restrict__ C1)
{
    extern __shared__ char smraw[];
    float* Ps = (float*)smraw;
    const uint32_t tbase = smem_u32(smraw) + PS_BYTES;

    const int t = threadIdx.x, w = t >> 5, lane = t & 31;
    const int qt = blockIdx.x, h = blockIdx.y, b = blockIdx.z;
    const int q0 = qt * 32;

    uint32_t af[2][2][4][4];
    {
        const unsigned short* qs[2] = { Q0, Q1 };
        const int r0 = lane >> 2;
        const int c0 = (lane & 3) * 2;
#pragma unroll
        for (int lv = 0; lv < 2; lv++)
#pragma unroll
            for (int mt = 0; mt < 2; mt++)
#pragma unroll
                for (int ks = 0; ks < 4; ks++) {
                    size_t base = (size_t)(b * SEQ + q0 + mt * 16 + r0) * D_MODEL
                                + h * DKH + ks * 16 + c0;
                    af[lv][mt][ks][0] = *(const uint32_t*)(qs[lv] + base);
                    af[lv][mt][ks][1] = *(const uint32_t*)(qs[lv] + base + 8 * D_MODEL);
                    af[lv][mt][ks][2] = *(const uint32_t*)(qs[lv] + base + 8);
                    af[lv][mt][ks][3] = *(const uint32_t*)(qs[lv] + base + 8 * D_MODEL + 8);
                }
    }

    auto kfill = [&](int kt, int s) {
#pragma unroll
        for (int n = 0; n < 8; n++) {
            int i = t + n * 256;
            int lv = i >> 10, j = i & 1023;
            int r = j >> 3, u = j & 7;
            const unsigned short* src = (lv ? g_k1s : g_k0s)
                + (size_t)(b * SEQ + kt * 128 + r) * D_MODEL + h * DKH + u * 8;
            cp16(tbase + s * KSTG + lv * KLEV + (uint32_t)r * KROWB + u * 16, src);
        }
        asm volatile("cp.async.commit_group;" ::: "memory");
    };
    const uint32_t krow = (uint32_t)(w * 16 + (lane & 7) + ((lane >> 4) & 1) * 8) * KROWB
                        + ((lane >> 3) & 1) * 16;
    kfill(0, 0);
    kfill(1, 1);

    for (int kt = 0; kt < 8; kt++) {
        if (kt < 7) asm volatile("cp.async.wait_group 1;" ::: "memory");
        else        asm volatile("cp.async.wait_group 0;" ::: "memory");
        __syncthreads();
        const uint32_t kb = tbase + (kt & 1) * KSTG;

        uint32_t bf[2][4][4];
#pragma unroll
        for (int lv = 0; lv < 2; lv++)
#pragma unroll
            for (int ks = 0; ks < 4; ks++)
                ldsm_x4(bf[lv][ks], kb + lv * KLEV + krow + ks * 32);

        float acc[2][2][4];
#pragma unroll
        for (int i = 0; i < 2; i++)
#pragma unroll
            for (int j = 0; j < 2; j++)
#pragma unroll
                for (int v = 0; v < 4; v++) acc[i][j][v] = 0.f;

#pragma unroll
        for (int ks = 0; ks < 4; ks++) {
#pragma unroll
            for (int mt = 0; mt < 2; mt++)
#pragma unroll
                for (int nt = 0; nt < 2; nt++) {
                    mma_f16(acc[mt][nt], af[0][mt][ks], &bf[0][ks][nt * 2]);
                    mma_f16(acc[mt][nt], af[0][mt][ks], &bf[1][ks][nt * 2]);
                    mma_f16(acc[mt][nt], af[1][mt][ks], &bf[0][ks][nt * 2]);
                }
        }

#pragma unroll
        for (int mt = 0; mt < 2; mt++) {
#pragma unroll
            for (int nt = 0; nt < 2; nt++) {
                int row = mt * 16 + (lane >> 2);
                int col = kt * 128 + w * 16 + nt * 8 + (lane & 3) * 2;
                const unsigned char* mp0 =
                    mask + (size_t)(b * SEQ + q0 + row) * SEQ + col;
                const unsigned char* mp1 = mp0 + 8 * SEQ;
                float2 v0, v1;
                v0.x = mp0[0] ? -1e9f : acc[mt][nt][0] * 0.125f;
                v0.y = mp0[1] ? -1e9f : acc[mt][nt][1] * 0.125f;
                v1.x = mp1[0] ? -1e9f : acc[mt][nt][2] * 0.125f;
                v1.y = mp1[1] ? -1e9f : acc[mt][nt][3] * 0.125f;
                *(float2*)&Ps[row * PS_LD + col]       = v0;
                *(float2*)&Ps[(row + 8) * PS_LD + col] = v1;
            }
        }
        __syncthreads();
        if (kt + 2 < 8) kfill(kt + 2, kt & 1);
    }
    __syncthreads();

    {
        int row = t >> 3, sub = t & 7;
        float* pr = Ps + row * PS_LD;
        float m = -1e30f;
        for (int cc = sub; cc < SEQ; cc += 8) m = fmaxf(m, pr[cc]);
#pragma unroll
        for (int o = 4; o > 0; o >>= 1) m = fmaxf(m, __shfl_xor_sync(0xffffffffu, m, o, 8));
        float s = 0.f;
        for (int cc = sub; cc < SEQ; cc += 8) { float e = __expf(pr[cc] - m); pr[cc] = e; s += e; }
#pragma unroll
        for (int o = 4; o > 0; o >>= 1) s += __shfl_xor_sync(0xffffffffu, s, o, 8);
        float inv = 1.0f / s;
        for (int cc = sub; cc < SEQ; cc += 8) pr[cc] *= inv;
    }
    __syncthreads();

    if (attn_out) {
        float* ab = attn_out + (((size_t)(b * NHEAD + h)) * SEQ + q0) * SEQ;
#pragma unroll
        for (int i = 0; i < 32; i++) {
            int idx = t + i * 256;
            int r  = idx >> 8;
            int c4 = (idx & 255) << 2;
            *(float4*)&ab[(size_t)r * SEQ + c4] = *(const float4*)&Ps[r * PS_LD + c4];
        }
    }
    __syncthreads();

    // ---- PV phase: 2 passes (Ph*Vh + Ph*Vl); P fp16 quantized post-softmax ----
    auto vfill = [&](int kt, int s) {
#pragma unroll
        for (int n = 0; n < 8; n++) {
            int i = t + n * 256;
            int lv = i >> 10, j = i & 1023;
            int r = j >> 4, u = j & 15;
            const unsigned short* src = (lv ? g_v1t : g_v0t)
                + ((size_t)(b * NHEAD + h) * DKH + r) * SEQ + kt * 128 + u * 8;
            cp16(tbase + s * VSTG + lv * VLEV + (uint32_t)r * VROWB + u * 16, src);
        }
        asm volatile("cp.async.commit_group;" ::: "memory");
    };
    const int mh = w & 1, nq = w >> 1;
    const uint32_t vrow = (uint32_t)(nq * 16 + (lane & 7) + ((lane >> 4) & 1) * 8) * VROWB
                        + ((lane >> 3) & 1) * 16;
    float oacc[2][4];
#pragma unroll
    for (int i = 0; i < 2; i++)
#pragma unroll
        for (int v = 0; v < 4; v++) oacc[i][v] = 0.f;

    vfill(0, 0);
    vfill(1, 1);

    const int pr0 = mh * 16 + (lane >> 2);
    const int pc0 = (lane & 3) * 2;

    for (int kt = 0; kt < 8; kt++) {
        if (kt < 7) asm volatile("cp.async.wait_group 1;" ::: "memory");
        else        asm volatile("cp.async.wait_group 0;" ::: "memory");
        __syncthreads();
        const uint32_t vb = tbase + (kt & 1) * VSTG;

#pragma unroll
        for (int ks = 0; ks < 8; ks++) {
            uint32_t bv[2][4];
            ldsm_x4(bv[0], vb + vrow + ks * 32);
            ldsm_x4(bv[1], vb + VLEV + vrow + ks * 32);

            int pc = kt * 128 + ks * 16 + pc0;
            float2 p00 = *(float2*)&Ps[pr0 * PS_LD + pc];
            float2 p10 = *(float2*)&Ps[(pr0 + 8) * PS_LD + pc];
            float2 p01 = *(float2*)&Ps[pr0 * PS_LD + pc + 8];
            float2 p11 = *(float2*)&Ps[(pr0 + 8) * PS_LD + pc + 8];

            uint32_t ph[4];
            {
                __half2 h0 = __floats2half2_rn(p00.x, p00.y);
                __half2 h1 = __floats2half2_rn(p10.x, p10.y);
                __half2 h2 = __floats2half2_rn(p01.x, p01.y);
                __half2 h3 = __floats2half2_rn(p11.x, p11.y);
                ph[0] = *(uint32_t*)&h0; ph[1] = *(uint32_t*)&h1;
                ph[2] = *(uint32_t*)&h2; ph[3] = *(uint32_t*)&h3;
            }
            mma_f16(oacc[0], ph, &bv[0][0]);
            mma_f16(oacc[1], ph, &bv[0][2]);
            mma_f16(oacc[0], ph, &bv[1][0]);
            mma_f16(oacc[1], ph, &bv[1][2]);
        }
        __syncthreads();
        if (kt + 2 < 8) vfill(kt + 2, kt & 1);
    }

    {
        int orow = b * SEQ + q0 + pr0;
        int ocol = h * DKH + nq * 16 + pc0;
#pragma unroll
        for (int nt = 0; nt < 2; nt++) {
            ushort2 s0 = split_h(oacc[nt][0]), s1 = split_h(oacc[nt][1]);
            ushort2 s2 = split_h(oacc[nt][2]), s3 = split_h(oacc[nt][3]);
            *(ushort2*)&C0[(size_t)orow * D_MODEL + ocol + nt * 8]       = make_ushort2(s0.x, s1.x);
            *(ushort2*)&C1[(size_t)orow * D_MODEL + ocol + nt * 8]       = make_ushort2(s0.y, s1.y);
            *(ushort2*)&C0[(size_t)(orow + 8) * D_MODEL + ocol + nt * 8] = make_ushort2(s2.x, s3.x);
            *(ushort2*)&C1[(size_t)(orow + 8) * D_MODEL + ocol + nt * 8] = make_ushort2(s2.y, s3.y);
        }
    }
}

// =================================================================================
// Residual add + LayerNorm
// =================================================================================
__global__ __launch_bounds__(256) void ln_kernel(
    const float* __restrict__ fc, const float* __restrict__ resid,
    const float* __restrict__ gamma, const float* __restrict__ beta,
    float* __restrict__ out)
{
    __shared__ float xs[D_MODEL];
    __shared__ float rs[8], rss[8];

    const int row = blockIdx.x;
    const int t   = threadIdx.x;
    const float* f = fc    + (size_t)row * D_MODEL;
    const float* r = resid + (size_t)row * D_MODEL;

    float s = 0.f, ss = 0.f;
    for (int i = t; i < D_MODEL; i += 256) {
        float x = f[i] + r[i];
        xs[i] = x;
        s += x; ss += x * x;
    }
#pragma unroll
    for (int o = 16; o > 0; o >>= 1) {
        s  += __shfl_xor_sync(0xffffffffu, s, o);
        ss += __shfl_xor_sync(0xffffffffu, ss, o);
    }
    int w = t >> 5, lane = t & 31;
    if (lane == 0) { rs[w] = s; rss[w] = ss; }
    __syncthreads();
    float ts = 0.f, tss = 0.f;
#pragma unroll
    for (int i = 0; i < 8; i++) { ts += rs[i]; tss += rss[i]; }
    float mu  = ts * (1.0f / D_MODEL);
    float var = tss * (1.0f / D_MODEL) - mu * mu;
    float kk  = rsqrtf(var + 1e-5f);

    for (int i = t; i < D_MODEL; i += 256)
        out[(size_t)row * D_MODEL + i] = (xs[i] - mu) * kk * gamma[i] + beta[i];
}

// =================================================================================
// launch
// =================================================================================
extern "C" void kernel_launch(void* const* d_in, const int* in_sizes, int n_in,
                              void* d_out, int out_size)
{
    const float* q    = (const float*)d_in[0];
    const float* k    = (const float*)d_in[1];
    const float* v    = (const float*)d_in[2];
    const unsigned char* mask = (const unsigned char*)d_in[3];
    const float* w_q  = (const float*)d_in[4];
    const float* b_q  = (const float*)d_in[5];
    const float* w_k  = (const float*)d_in[6];
    const float* b_k  = (const float*)d_in[7];
    const float* w_v  = (const float*)d_in[8];
    const float* b_v  = (const float*)d_in[9];
    const float* w_fc = (const float*)d_in[10];
    const float* b_fc = (const float*)d_in[11];
    const float* ln_g = (const float*)d_in[12];
    const float* ln_b = (const float*)d_in[13];
    float* out = (float*)d_out;

    float *qh, *vh, *ctx, *fc;
    unsigned short *a0, *a1, *b0, *b1, *k0s, *k1s;
    cudaGetSymbolAddress((void**)&qh,  g_qh);
    cudaGetSymbolAddress((void**)&vh,  g_vh);
    cudaGetSymbolAddress((void**)&ctx, g_ctx);
    cudaGetSymbolAddress((void**)&fc,  g_fc);
    cudaGetSymbolAddress((void**)&a0,  g_a0);
    cudaGetSymbolAddress((void**)&a1,  g_a1);
    cudaGetSymbolAddress((void**)&b0,  g_b0);
    cudaGetSymbolAddress((void**)&b1,  g_b1);
    cudaGetSymbolAddress((void**)&k0s, g_k0s);
    cudaGetSymbolAddress((void**)&k1s, g_k1s);

    unsigned short* q0s = (unsigned short*)qh;
    unsigned short* q1s = q0s + (size_t)MROWS * D_MODEL;
    unsigned short* c0s = (unsigned short*)ctx;
    unsigned short* c1s = c0s + (size_t)MROWS * D_MODEL;

    const long long xe = (long long)MROWS * D_MODEL;
    const long long ae = (long long)BATCH * NHEAD * SEQ * SEQ;
    float* attn_out = nullptr;
    float* x_out    = out;
    if ((long long)out_size >= xe + ae) {
        attn_out = out + xe;
    } else if ((long long)out_size == ae) {
        attn_out = out;
        x_out = nullptr;
    }

    cudaFuncSetAttribute((void*)gemm_2h<3, true>,  cudaFuncAttributeMaxDynamicSharedMemorySize, GSMEM3);
    cudaFuncSetAttribute((void*)gemm_2h<3, false>, cudaFuncAttributeMaxDynamicSharedMemorySize, GSMEM3);
    cudaFuncSetAttribute((void*)attn_mma, cudaFuncAttributeMaxDynamicSharedMemorySize, ATTN_SMEM);

    const int nA4 = MROWS * D_MODEL / 4;
    const int nW4 = D_MODEL * D_MODEL / 4;
    dim3 gb(256);
    dim3 gg(D_MODEL / 64, MROWS / 128);    // (16, 64)

    // Q projection -> split output directly (3-pass: hh, lh, hl)
    split2h_kernel<<<nA4 / 256, gb>>>(q, a0, a1, nA4);
    split2h_kernel<<<nW4 / 256, gb>>>(w_q, b0, b1, nW4);
    gemm_2h<3, true><<<gg, gb, GSMEM3>>>(a0, a1, b0, b1, b_q, nullptr, q0s, q1s);

    // K projection -> split output directly
    split2h_kernel<<<nA4 / 256, gb>>>(k, a0, a1, nA4);
    split2h_kernel<<<nW4 / 256, gb>>>(w_k, b0, b1, nW4);
    gemm_2h<3, true><<<gg, gb, GSMEM3>>>(a0, a1, b0, b1, b_k, nullptr, k0s, k1s);

    // V projection -> fp32 (vtrans consumes it)
    split2h_kernel<<<nA4 / 256, gb>>>(v, a0, a1, nA4);
    split2h_kernel<<<nW4 / 256, gb>>>(w_v, b0, b1, nW4);
    gemm_2h<3, false><<<gg, gb, GSMEM3>>>(a0, a1, b0, b1, b_v, vh, nullptr, nullptr);

    vtrans_kernel<<<dim3(SEQ / 32, DKH / 32, BATCH * NHEAD), dim3(32, 8)>>>();

    dim3 ag(SEQ / 32, NHEAD, BATCH);
    attn_mma<<<ag, gb, ATTN_SMEM>>>(mask, attn_out, q0s, q1s, c0s, c1s);

    // FC (ctx split produced by attention epilogue)
    split2h_kernel<<<nW4 / 256, gb>>>(w_fc, b0, b1, nW4);
    gemm_2h<3, false><<<gg, gb, GSMEM3>>>(c0s, c1s, b0, b1, b_fc, fc, nullptr, nullptr);

    if (x_out)
        ln_kernel<<<MROWS, gb>>>(fc, q, ln_g, ln_b, x_out);
}

// round 13
// speedup vs baseline: 1.1097x; 1.0683x over previous
#include <cuda_runtime.h>
#include <cuda_fp16.h>
#include <cstdint>
#include <cstddef>

#define D_MODEL 1024
#define NHEAD   16
#define DKH     64
#define BATCH   8
#define SEQ     1024
#define MROWS   (BATCH * SEQ)   // 8192

// ---------------- scratch (device globals: no cudaMalloc allowed) ----------------
__device__ float g_qh[MROWS * D_MODEL];    // carved as Q h/l split (ushort x2)
__device__ float g_vh[MROWS * D_MODEL];    // fp32 V (for vtrans)
__device__ float g_ctx[MROWS * D_MODEL];   // carved as ctx h/l split (ushort x2)
__device__ float g_fc[MROWS * D_MODEL];
__device__ __align__(16) unsigned short g_a0[MROWS * D_MODEL];
__device__ __align__(16) unsigned short g_a1[MROWS * D_MODEL];
__device__ __align__(16) unsigned short g_b0[D_MODEL * D_MODEL];
__device__ __align__(16) unsigned short g_b1[D_MODEL * D_MODEL];
__device__ __align__(16) unsigned short g_k0s[MROWS * D_MODEL];
__device__ __align__(16) unsigned short g_k1s[MROWS * D_MODEL];
__device__ __align__(16) unsigned short g_v0t[MROWS * D_MODEL];   // [bh][d][token]

// =================================================================================
// helpers
// =================================================================================
__device__ __forceinline__ uint32_t smem_u32(const void* p) {
    uint32_t a;
    asm("{ .reg .u64 t; cvta.to.shared.u64 t, %1; cvt.u32.u64 %0, t; }" : "=r"(a) : "l"(p));
    return a;
}
__device__ __forceinline__ void ldsm_x4(uint32_t* r, uint32_t addr) {
    asm volatile("ldmatrix.sync.aligned.m8n8.x4.shared.b16 {%0,%1,%2,%3}, [%4];"
        : "=r"(r[0]), "=r"(r[1]), "=r"(r[2]), "=r"(r[3]) : "r"(addr));
}
__device__ __forceinline__ void mma_f16(float* c, const uint32_t* a, const uint32_t* b) {
    asm volatile("mma.sync.aligned.m16n8k16.row.col.f32.f16.f16.f32 "
        "{%0,%1,%2,%3}, {%4,%5,%6,%7}, {%8,%9}, {%0,%1,%2,%3};"
        : "+f"(c[0]), "+f"(c[1]), "+f"(c[2]), "+f"(c[3])
        : "r"(a[0]), "r"(a[1]), "r"(a[2]), "r"(a[3]), "r"(b[0]), "r"(b[1]));
}
__device__ __forceinline__ void cp16(uint32_t dst, const void* src) {
    asm volatile("cp.async.cg.shared.global [%0], [%1], 16;" :: "r"(dst), "l"(src));
}
__device__ __forceinline__ ushort2 split_h(float x) {
    __half hb = __float2half_rn(x);
    float hf = __half2float(hb);
    __half lb = __float2half_rn(x - hf);
    return make_ushort2(__half_as_ushort(hb), __half_as_ushort(lb));
}

// =================================================================================
// fp32 -> fp16 2-level split
// =================================================================================
__global__ __launch_bounds__(256) void split2h_kernel(
    const float* __restrict__ x, unsigned short* __restrict__ h,
    unsigned short* __restrict__ l, int n4)
{
    int i = blockIdx.x * 256 + threadIdx.x;
    if (i >= n4) return;
    float4 v = ((const float4*)x)[i];
    float vv[4] = { v.x, v.y, v.z, v.w };
    unsigned short hh[4], ll[4];
#pragma unroll
    for (int j = 0; j < 4; j++) {
        __half hb = __float2half_rn(vv[j]);
        float r1 = vv[j] - __half2float(hb);
        __half lb = __float2half_rn(r1);
        hh[j] = __half_as_ushort(hb);
        ll[j] = __half_as_ushort(lb);
    }
    ((ushort4*)h)[i] = make_ushort4(hh[0], hh[1], hh[2], hh[3]);
    ((ushort4*)l)[i] = make_ushort4(ll[0], ll[1], ll[2], ll[3]);
}

// =================================================================================
// V transpose + fp16 quantize:  g_vh[token][h*64+d] -> g_v0t[(bh*64+d)*1024 + token]
// =================================================================================
__global__ __launch_bounds__(256) void vtrans_kernel()
{
    __shared__ float ttile[32][33];
    const int bh = blockIdx.z, b = bh >> 4, h = bh & 15;
    const int t0 = blockIdx.x * 32, d0 = blockIdx.y * 32;
    const int tx = threadIdx.x, ty = threadIdx.y;
#pragma unroll
    for (int j = 0; j < 4; j++) {
        int tok = t0 + ty + j * 8;
        ttile[ty + j * 8][tx] =
            g_vh[(size_t)(b * SEQ + tok) * D_MODEL + h * DKH + d0 + tx];
    }
    __syncthreads();
#pragma unroll
    for (int j = 0; j < 4; j++) {
        int d = d0 + ty + j * 8;
        float x = ttile[tx][ty + j * 8];
        size_t o = ((size_t)bh * DKH + d) * SEQ + t0 + tx;
        g_v0t[o] = __half_as_ushort(__float2half_rn(x));
    }
}

// =================================================================================
// 2-level fp16 mma GEMM — round-9 build (3-stage ring, 128x64 tile)
// NPASS=3: hh,hl,lh.  NPASS=2: hh,hl.
// =================================================================================
#define KC         32
#define NCHUNK     (D_MODEL / KC)
#define TLD        80
#define AT_BYTES   (128 * TLD)
#define BT_BYTES   (64 * TLD)
#define STAGE      (2 * AT_BYTES + 2 * BT_BYTES)   // 30720
#define GSMEM3     (3 * STAGE)                     // 92160

template<int NPASS, bool SPLIT_OUT>
__global__ void __launch_bounds__(256, 2) gemm_2h(
    const unsigned short* __restrict__ A0, const unsigned short* __restrict__ A1,
    const unsigned short* __restrict__ B0, const unsigned short* __restrict__ B1,
    const float* __restrict__ bias,
    float* __restrict__ C,
    unsigned short* __restrict__ H, unsigned short* __restrict__ L)
{
    extern __shared__ char smc[];
    const uint32_t sbase = smem_u32(smc);
    const int tid = threadIdx.x, wid = tid >> 5, lane = tid & 31;
    const int bn = blockIdx.x, bm = blockIdx.y;
    const int wm = wid & 3, wn = wid >> 2;

    const unsigned short* srcs[4];
    srcs[0] = A0 + (size_t)bm * 128 * D_MODEL;
    srcs[1] = A1 + (size_t)bm * 128 * D_MODEL;
    srcs[2] = B0 + (size_t)bn * 64 * D_MODEL;
    srcs[3] = B1 + (size_t)bn * 64 * D_MODEL;

    float acc[2][4][4];
#pragma unroll
    for (int i = 0; i < 2; i++)
#pragma unroll
        for (int j = 0; j < 4; j++)
#pragma unroll
            for (int v = 0; v < 4; v++) acc[i][j][v] = 0.f;

    const uint32_t a_l = (uint32_t)(wm * 32 + (lane & 15)) * TLD + ((lane >> 4) & 1) * 16;
    const uint32_t b_l = (uint32_t)(wn * 32 + (lane & 7) + ((lane >> 4) & 1) * 8) * TLD
                       + ((lane >> 3) & 1) * 16;

    auto fill = [&](int c, int s) {
        const uint32_t base = sbase + (uint32_t)s * STAGE;
#pragma unroll
        for (int n = 0; n < 6; n++) {
            int i = tid + n * 256;
            bool isA = i < 1024;
            int j   = isA ? i : i - 1024;
            int lev = isA ? (j >> 9) : (j >> 8);
            int r   = isA ? ((j >> 2) & 127) : ((j >> 2) & 63);
            int c16 = j & 3;
            const unsigned short* src = srcs[(isA ? 0 : 2) + lev]
                + (size_t)r * D_MODEL + c * KC + c16 * 8;
            uint32_t dst = base + (isA ? (uint32_t)lev * AT_BYTES
                                       : 2u * AT_BYTES + (uint32_t)lev * BT_BYTES)
                         + (uint32_t)r * TLD + c16 * 16;
            cp16(dst, src);
        }
        asm volatile("cp.async.commit_group;" ::: "memory");
    };

    fill(0, 0);
    fill(1, 1);

    constexpr int PA[4] = { 0, 0, 1, 1 };
    constexpr int PB[4] = { 0, 1, 0, 1 };

    int stage = 0;
    for (int c = 0; c < NCHUNK; c++) {
        if (c + 1 < NCHUNK)
            asm volatile("cp.async.wait_group 1;" ::: "memory");
        else
            asm volatile("cp.async.wait_group 0;" ::: "memory");
        __syncthreads();

        if (c + 2 < NCHUNK) {
            int fs = stage + 2; if (fs >= 3) fs -= 3;
            fill(c + 2, fs);
        }

        const uint32_t abase = sbase + (uint32_t)stage * STAGE;
        const uint32_t bbase = abase + 2 * AT_BYTES;

#pragma unroll
        for (int kb = 0; kb < 2; kb++) {
            const uint32_t kbyte = kb * 32;
            uint32_t af[2][2][4], bfr[2][2][4];
#pragma unroll
            for (int lv = 0; lv < 2; lv++) {
#pragma unroll
                for (int mt = 0; mt < 2; mt++)
                    ldsm_x4(af[lv][mt], abase + lv * AT_BYTES + a_l + mt * (16 * TLD) + kbyte);
#pragma unroll
                for (int np = 0; np < 2; np++)
                    ldsm_x4(bfr[lv][np], bbase + lv * BT_BYTES + b_l + np * (16 * TLD) + kbyte);
            }
#pragma unroll
            for (int p = 0; p < NPASS; p++) {
#pragma unroll
                for (int mt = 0; mt < 2; mt++)
#pragma unroll
                    for (int nt = 0; nt < 4; nt++)
                        mma_f16(acc[mt][nt], af[PA[p]][mt],
                                &bfr[PB[p]][nt >> 1][(nt & 1) * 2]);
            }
        }
        if (++stage == 3) stage = 0;
    }

    const int qr = lane >> 2;
#pragma unroll
    for (int mt = 0; mt < 2; mt++) {
        int row0 = bm * 128 + wm * 32 + mt * 16 + qr;
#pragma unroll
        for (int nt = 0; nt < 4; nt++) {
            int col = bn * 64 + wn * 32 + nt * 8 + (lane & 3) * 2;
            float v00 = acc[mt][nt][0] + bias[col];
            float v01 = acc[mt][nt][1] + bias[col + 1];
            float v10 = acc[mt][nt][2] + bias[col];
            float v11 = acc[mt][nt][3] + bias[col + 1];
            if (SPLIT_OUT) {
                ushort2 h0 = split_h(v00), h1 = split_h(v01);
                ushort2 h2 = split_h(v10), h3 = split_h(v11);
                *(ushort2*)(H + (size_t)row0 * D_MODEL + col)       = make_ushort2(h0.x, h1.x);
                *(ushort2*)(L + (size_t)row0 * D_MODEL + col)       = make_ushort2(h0.y, h1.y);
                *(ushort2*)(H + (size_t)(row0 + 8) * D_MODEL + col) = make_ushort2(h2.x, h3.x);
                *(ushort2*)(L + (size_t)(row0 + 8) * D_MODEL + col) = make_ushort2(h2.y, h3.y);
            } else {
                float2 v0 = { v00, v01 }, v1 = { v10, v11 };
                *(float2*)(C + (size_t)row0 * D_MODEL + col)       = v0;
                *(float2*)(C + (size_t)(row0 + 8) * D_MODEL + col) = v1;
            }
        }
    }
}

// =================================================================================
// mma attention — fp32 scores (required), PV single pass (Ph*Vh).
// =================================================================================
#define PS_LD     1032
#define PS_BYTES  (32 * PS_LD * 4)       // 132096
#define KROWB     144
#define KLEV      (128 * KROWB)
#define KSTG      (2 * KLEV)             // 36864
#define VROWB     272
#define VLEV      (64 * VROWB)           // 17408 (single level now)
#define ATTN_SMEM (PS_BYTES + 2 * KSTG)  // 205824

__global__ __launch_bounds__(256) void attn_mma(
    const unsigned char* __restrict__ mask, float* __restrict__ attn_out,
    const unsigned short* __restrict__ Q0, const unsigned short* __restrict__ Q1,
    unsigned short* __restrict__ C0, unsigned short* __restrict__ C1)
{
    extern __shared__ char smraw[];
    float* Ps = (float*)smraw;
    const uint32_t tbase = smem_u32(smraw) + PS_BYTES;

    const int t = threadIdx.x, w = t >> 5, lane = t & 31;
    const int qt = blockIdx.x, h = blockIdx.y, b = blockIdx.z;
    const int q0 = qt * 32;

    uint32_t af[2][2][4][4];
    {
        const unsigned short* qs[2] = { Q0, Q1 };
        const int r0 = lane >> 2;
        const int c0 = (lane & 3) * 2;
#pragma unroll
        for (int lv = 0; lv < 2; lv++)
#pragma unroll
            for (int mt = 0; mt < 2; mt++)
#pragma unroll
                for (int ks = 0; ks < 4; ks++) {
                    size_t base = (size_t)(b * SEQ + q0 + mt * 16 + r0) * D_MODEL
                                + h * DKH + ks * 16 + c0;
                    af[lv][mt][ks][0] = *(const uint32_t*)(qs[lv] + base);
                    af[lv][mt][ks][1] = *(const uint32_t*)(qs[lv] + base + 8 * D_MODEL);
                    af[lv][mt][ks][2] = *(const uint32_t*)(qs[lv] + base + 8);
                    af[lv][mt][ks][3] = *(const uint32_t*)(qs[lv] + base + 8 * D_MODEL + 8);
                }
    }

    auto kfill = [&](int kt, int s) {
#pragma unroll
        for (int n = 0; n < 8; n++) {
            int i = t + n * 256;
            int lv = i >> 10, j = i & 1023;
            int r = j >> 3, u = j & 7;
            const unsigned short* src = (lv ? g_k1s : g_k0s)
                + (size_t)(b * SEQ + kt * 128 + r) * D_MODEL + h * DKH + u * 8;
            cp16(tbase + s * KSTG + lv * KLEV + (uint32_t)r * KROWB + u * 16, src);
        }
        asm volatile("cp.async.commit_group;" ::: "memory");
    };
    const uint32_t krow = (uint32_t)(w * 16 + (lane & 7) + ((lane >> 4) & 1) * 8) * KROWB
                        + ((lane >> 3) & 1) * 16;
    kfill(0, 0);
    kfill(1, 1);

    for (int kt = 0; kt < 8; kt++) {
        if (kt < 7) asm volatile("cp.async.wait_group 1;" ::: "memory");
        else        asm volatile("cp.async.wait_group 0;" ::: "memory");
        __syncthreads();
        const uint32_t kb = tbase + (kt & 1) * KSTG;

        uint32_t bf[2][4][4];
#pragma unroll
        for (int lv = 0; lv < 2; lv++)
#pragma unroll
            for (int ks = 0; ks < 4; ks++)
                ldsm_x4(bf[lv][ks], kb + lv * KLEV + krow + ks * 32);

        float acc[2][2][4];
#pragma unroll
        for (int i = 0; i < 2; i++)
#pragma unroll
            for (int j = 0; j < 2; j++)
#pragma unroll
                for (int v = 0; v < 4; v++) acc[i][j][v] = 0.f;

#pragma unroll
        for (int ks = 0; ks < 4; ks++) {
#pragma unroll
            for (int mt = 0; mt < 2; mt++)
#pragma unroll
                for (int nt = 0; nt < 2; nt++) {
                    mma_f16(acc[mt][nt], af[0][mt][ks], &bf[0][ks][nt * 2]);
                    mma_f16(acc[mt][nt], af[0][mt][ks], &bf[1][ks][nt * 2]);
                    mma_f16(acc[mt][nt], af[1][mt][ks], &bf[0][ks][nt * 2]);
                }
        }

#pragma unroll
        for (int mt = 0; mt < 2; mt++) {
#pragma unroll
            for (int nt = 0; nt < 2; nt++) {
                int row = mt * 16 + (lane >> 2);
                int col = kt * 128 + w * 16 + nt * 8 + (lane & 3) * 2;
                const unsigned char* mp0 =
                    mask + (size_t)(b * SEQ + q0 + row) * SEQ + col;
                const unsigned char* mp1 = mp0 + 8 * SEQ;
                float2 v0, v1;
                v0.x = mp0[0] ? -1e9f : acc[mt][nt][0] * 0.125f;
                v0.y = mp0[1] ? -1e9f : acc[mt][nt][1] * 0.125f;
                v1.x = mp1[0] ? -1e9f : acc[mt][nt][2] * 0.125f;
                v1.y = mp1[1] ? -1e9f : acc[mt][nt][3] * 0.125f;
                *(float2*)&Ps[row * PS_LD + col]       = v0;
                *(float2*)&Ps[(row + 8) * PS_LD + col] = v1;
            }
        }
        __syncthreads();
        if (kt + 2 < 8) kfill(kt + 2, kt & 1);
    }
    __syncthreads();

    {
        int row = t >> 3, sub = t & 7;
        float* pr = Ps + row * PS_LD;
        float m = -1e30f;
        for (int cc = sub; cc < SEQ; cc += 8) m = fmaxf(m, pr[cc]);
#pragma unroll
        for (int o = 4; o > 0; o >>= 1) m = fmaxf(m, __shfl_xor_sync(0xffffffffu, m, o, 8));
        float s = 0.f;
        for (int cc = sub; cc < SEQ; cc += 8) { float e = __expf(pr[cc] - m); pr[cc] = e; s += e; }
#pragma unroll
        for (int o = 4; o > 0; o >>= 1) s += __shfl_xor_sync(0xffffffffu, s, o, 8);
        float inv = 1.0f / s;
        for (int cc = sub; cc < SEQ; cc += 8) pr[cc] *= inv;
    }
    __syncthreads();

    if (attn_out) {
        float* ab = attn_out + (((size_t)(b * NHEAD + h)) * SEQ + q0) * SEQ;
#pragma unroll
        for (int i = 0; i < 32; i++) {
            int idx = t + i * 256;
            int r  = idx >> 8;
            int c4 = (idx & 255) << 2;
            *(float4*)&ab[(size_t)r * SEQ + c4] = *(const float4*)&Ps[r * PS_LD + c4];
        }
    }
    __syncthreads();

    // ---- PV phase: single pass Ph*Vh; only g_v0t staged ----
    auto vfill = [&](int kt, int s) {
#pragma unroll
        for (int n = 0; n < 4; n++) {
            int i = t + n * 256;                 // 0..1023
            int r = i >> 4, u = i & 15;          // 64 d-rows x 256B (128 tokens)
            const unsigned short* src = g_v0t
                + ((size_t)(b * NHEAD + h) * DKH + r) * SEQ + kt * 128 + u * 8;
            cp16(tbase + s * VLEV + (uint32_t)r * VROWB + u * 16, src);
        }
        asm volatile("cp.async.commit_group;" ::: "memory");
    };
    const int mh = w & 1, nq = w >> 1;
    const uint32_t vrow = (uint32_t)(nq * 16 + (lane & 7) + ((lane >> 4) & 1) * 8) * VROWB
                        + ((lane >> 3) & 1) * 16;
    float oacc[2][4];
#pragma unroll
    for (int i = 0; i < 2; i++)
#pragma unroll
        for (int v = 0; v < 4; v++) oacc[i][v] = 0.f;

    vfill(0, 0);
    vfill(1, 1);

    const int pr0 = mh * 16 + (lane >> 2);
    const int pc0 = (lane & 3) * 2;

    for (int kt = 0; kt < 8; kt++) {
        if (kt < 7) asm volatile("cp.async.wait_group 1;" ::: "memory");
        else        asm volatile("cp.async.wait_group 0;" ::: "memory");
        __syncthreads();
        const uint32_t vb = tbase + (kt & 1) * VLEV;

#pragma unroll
        for (int ks = 0; ks < 8; ks++) {
            uint32_t bv[4];
            ldsm_x4(bv, vb + vrow + ks * 32);

            int pc = kt * 128 + ks * 16 + pc0;
            float2 p00 = *(float2*)&Ps[pr0 * PS_LD + pc];
            float2 p10 = *(float2*)&Ps[(pr0 + 8) * PS_LD + pc];
            float2 p01 = *(float2*)&Ps[pr0 * PS_LD + pc + 8];
            float2 p11 = *(float2*)&Ps[(pr0 + 8) * PS_LD + pc + 8];

            uint32_t ph[4];
            {
                __half2 h0 = __floats2half2_rn(p00.x, p00.y);
                __half2 h1 = __floats2half2_rn(p10.x, p10.y);
                __half2 h2 = __floats2half2_rn(p01.x, p01.y);
                __half2 h3 = __floats2half2_rn(p11.x, p11.y);
                ph[0] = *(uint32_t*)&h0; ph[1] = *(uint32_t*)&h1;
                ph[2] = *(uint32_t*)&h2; ph[3] = *(uint32_t*)&h3;
            }
            mma_f16(oacc[0], ph, &bv[0]);
            mma_f16(oacc[1], ph, &bv[2]);
        }
        __syncthreads();
        if (kt + 2 < 8) vfill(kt + 2, kt & 1);
    }

    {
        int orow = b * SEQ + q0 + pr0;
        int ocol = h * DKH + nq * 16 + pc0;
#pragma unroll
        for (int nt = 0; nt < 2; nt++) {
            ushort2 s0 = split_h(oacc[nt][0]), s1 = split_h(oacc[nt][1]);
            ushort2 s2 = split_h(oacc[nt][2]), s3 = split_h(oacc[nt][3]);
            *(ushort2*)&C0[(size_t)orow * D_MODEL + ocol + nt * 8]       = make_ushort2(s0.x, s1.x);
            *(ushort2*)&C1[(size_t)orow * D_MODEL + ocol + nt * 8]       = make_ushort2(s0.y, s1.y);
            *(ushort2*)&C0[(size_t)(orow + 8) * D_MODEL + ocol + nt * 8] = make_ushort2(s2.x, s3.x);
            *(ushort2*)&C1[(size_t)(orow + 8) * D_MODEL + ocol + nt * 8] = make_ushort2(s2.y, s3.y);
        }
    }
}

// =================================================================================
// Residual add + LayerNorm
// =================================================================================
__global__ __launch_bounds__(256) void ln_kernel(
    const float* __restrict__ fc, const float* __restrict__ resid,
    const float* __restrict__ gamma, const float* __restrict__ beta,
    float* __restrict__ out)
{
    __shared__ float xs[D_MODEL];
    __shared__ float rs[8], rss[8];

    const int row = blockIdx.x;
    const int t   = threadIdx.x;
    const float* f = fc    + (size_t)row * D_MODEL;
    const float* r = resid + (size_t)row * D_MODEL;

    float s = 0.f, ss = 0.f;
    for (int i = t; i < D_MODEL; i += 256) {
        float x = f[i] + r[i];
        xs[i] = x;
        s += x; ss += x * x;
    }
#pragma unroll
    for (int o = 16; o > 0; o >>= 1) {
        s  += __shfl_xor_sync(0xffffffffu, s, o);
        ss += __shfl_xor_sync(0xffffffffu, ss, o);
    }
    int w = t >> 5, lane = t & 31;
    if (lane == 0) { rs[w] = s; rss[w] = ss; }
    __syncthreads();
    float ts = 0.f, tss = 0.f;
#pragma unroll
    for (int i = 0; i < 8; i++) { ts += rs[i]; tss += rss[i]; }
    float mu  = ts * (1.0f / D_MODEL);
    float var = tss * (1.0f / D_MODEL) - mu * mu;
    float kk  = rsqrtf(var + 1e-5f);

    for (int i = t; i < D_MODEL; i += 256)
        out[(size_t)row * D_MODEL + i] = (xs[i] - mu) * kk * gamma[i] + beta[i];
}

// =================================================================================
// launch
// =================================================================================
extern "C" void kernel_launch(void* const* d_in, const int* in_sizes, int n_in,
                              void* d_out, int out_size)
{
    const float* q    = (const float*)d_in[0];
    const float* k    = (const float*)d_in[1];
    const float* v    = (const float*)d_in[2];
    const unsigned char* mask = (const unsigned char*)d_in[3];
    const float* w_q  = (const float*)d_in[4];
    const float* b_q  = (const float*)d_in[5];
    const float* w_k  = (const float*)d_in[6];
    const float* b_k  = (const float*)d_in[7];
    const float* w_v  = (const float*)d_in[8];
    const float* b_v  = (const float*)d_in[9];
    const float* w_fc = (const float*)d_in[10];
    const float* b_fc = (const float*)d_in[11];
    const float* ln_g = (const float*)d_in[12];
    const float* ln_b = (const float*)d_in[13];
    float* out = (float*)d_out;

    float *qh, *vh, *ctx, *fc;
    unsigned short *a0, *a1, *b0, *b1, *k0s, *k1s;
    cudaGetSymbolAddress((void**)&qh,  g_qh);
    cudaGetSymbolAddress((void**)&vh,  g_vh);
    cudaGetSymbolAddress((void**)&ctx, g_ctx);
    cudaGetSymbolAddress((void**)&fc,  g_fc);
    cudaGetSymbolAddress((void**)&a0,  g_a0);
    cudaGetSymbolAddress((void**)&a1,  g_a1);
    cudaGetSymbolAddress((void**)&b0,  g_b0);
    cudaGetSymbolAddress((void**)&b1,  g_b1);
    cudaGetSymbolAddress((void**)&k0s, g_k0s);
    cudaGetSymbolAddress((void**)&k1s, g_k1s);

    unsigned short* q0s = (unsigned short*)qh;
    unsigned short* q1s = q0s + (size_t)MROWS * D_MODEL;
    unsigned short* c0s = (unsigned short*)ctx;
    unsigned short* c1s = c0s + (size_t)MROWS * D_MODEL;

    const long long xe = (long long)MROWS * D_MODEL;
    const long long ae = (long long)BATCH * NHEAD * SEQ * SEQ;
    float* attn_out = nullptr;
    float* x_out    = out;
    if ((long long)out_size >= xe + ae) {
        attn_out = out + xe;
    } else if ((long long)out_size == ae) {
        attn_out = out;
        x_out = nullptr;
    }

    cudaFuncSetAttribute((void*)gemm_2h<3, true>,  cudaFuncAttributeMaxDynamicSharedMemorySize, GSMEM3);
    cudaFuncSetAttribute((void*)gemm_2h<2, false>, cudaFuncAttributeMaxDynamicSharedMemorySize, GSMEM3);
    cudaFuncSetAttribute((void*)attn_mma, cudaFuncAttributeMaxDynamicSharedMemorySize, ATTN_SMEM);

    const int nA4 = MROWS * D_MODEL / 4;
    const int nW4 = D_MODEL * D_MODEL / 4;
    dim3 gb(256);
    dim3 gg(D_MODEL / 64, MROWS / 128);    // (16, 64)

    // Q projection -> split output directly (3-pass: hh, hl, lh)
    split2h_kernel<<<nA4 / 256, gb>>>(q, a0, a1, nA4);
    split2h_kernel<<<nW4 / 256, gb>>>(w_q, b0, b1, nW4);
    gemm_2h<3, true><<<gg, gb, GSMEM3>>>(a0, a1, b0, b1, b_q, nullptr, q0s, q1s);

    // K projection -> split output directly (3-pass)
    split2h_kernel<<<nA4 / 256, gb>>>(k, a0, a1, nA4);
    split2h_kernel<<<nW4 / 256, gb>>>(w_k, b0, b1, nW4);
    gemm_2h<3, true><<<gg, gb, GSMEM3>>>(a0, a1, b0, b1, b_k, nullptr, k0s, k1s);

    // V projection -> fp32 (2-pass: hh, hl)
    split2h_kernel<<<nA4 / 256, gb>>>(v, a0, a1, nA4);
    split2h_kernel<<<nW4 / 256, gb>>>(w_v, b0, b1, nW4);
    gemm_2h<2, false><<<gg, gb, GSMEM3>>>(a0, a1, b0, b1, b_v, vh, nullptr, nullptr);

    vtrans_kernel<<<dim3(SEQ / 32, DKH / 32, BATCH * NHEAD), dim3(32, 8)>>>();

    dim3 ag(SEQ / 32, NHEAD, BATCH);
    attn_mma<<<ag, gb, ATTN_SMEM>>>(mask, attn_out, q0s, q1s, c0s, c1s);

    // FC (2-pass: hh, hl)
    split2h_kernel<<<nW4 / 256, gb>>>(w_fc, b0, b1, nW4);
    gemm_2h<2, false><<<gg, gb, GSMEM3>>>(c0s, c1s, b0, b1, b_fc, fc, nullptr, nullptr);

    if (x_out)
        ln_kernel<<<MROWS, gb>>>(fc, q, ln_g, ln_b, x_out);
}

// round 14
// speedup vs baseline: 1.1419x; 1.0290x over previous
#include <cuda_runtime.h>
#include <cuda_fp16.h>
#include <cstdint>
#include <cstddef>

#define D_MODEL 1024
#define NHEAD   16
#define DKH     64
#define BATCH   8
#define SEQ     1024
#define MROWS   (BATCH * SEQ)   // 8192

// ---------------- scratch (device globals: no cudaMalloc allowed) ----------------
__device__ float g_qh[MROWS * D_MODEL];    // carved as Q h/l split (ushort x2)
__device__ float g_vh[MROWS * D_MODEL];    // fp32 V (for vtrans)
__device__ float g_ctx[MROWS * D_MODEL];   // carved as ctx h/l split (ushort x2)
__device__ float g_fc[MROWS * D_MODEL];
__device__ __align__(16) unsigned short g_a0[MROWS * D_MODEL];
__device__ __align__(16) unsigned short g_a1[MROWS * D_MODEL];
__device__ __align__(16) unsigned short g_b0[D_MODEL * D_MODEL];
__device__ __align__(16) unsigned short g_b1[D_MODEL * D_MODEL];
__device__ __align__(16) unsigned short g_k0s[MROWS * D_MODEL];
__device__ __align__(16) unsigned short g_k1s[MROWS * D_MODEL];
__device__ __align__(16) unsigned short g_v0t[MROWS * D_MODEL];   // [bh][d][token]

// =================================================================================
// helpers
// =================================================================================
__device__ __forceinline__ uint32_t smem_u32(const void* p) {
    uint32_t a;
    asm("{ .reg .u64 t; cvta.to.shared.u64 t, %1; cvt.u32.u64 %0, t; }" : "=r"(a) : "l"(p));
    return a;
}
__device__ __forceinline__ void ldsm_x4(uint32_t* r, uint32_t addr) {
    asm volatile("ldmatrix.sync.aligned.m8n8.x4.shared.b16 {%0,%1,%2,%3}, [%4];"
        : "=r"(r[0]), "=r"(r[1]), "=r"(r[2]), "=r"(r[3]) : "r"(addr));
}
__device__ __forceinline__ void mma_f16(float* c, const uint32_t* a, const uint32_t* b) {
    asm volatile("mma.sync.aligned.m16n8k16.row.col.f32.f16.f16.f32 "
        "{%0,%1,%2,%3}, {%4,%5,%6,%7}, {%8,%9}, {%0,%1,%2,%3};"
        : "+f"(c[0]), "+f"(c[1]), "+f"(c[2]), "+f"(c[3])
        : "r"(a[0]), "r"(a[1]), "r"(a[2]), "r"(a[3]), "r"(b[0]), "r"(b[1]));
}
__device__ __forceinline__ void cp16(uint32_t dst, const void* src) {
    asm volatile("cp.async.cg.shared.global [%0], [%1], 16;" :: "r"(dst), "l"(src));
}
__device__ __forceinline__ ushort2 split_h(float x) {
    __half hb = __float2half_rn(x);
    float hf = __half2float(hb);
    __half lb = __float2half_rn(x - hf);
    return make_ushort2(__half_as_ushort(hb), __half_as_ushort(lb));
}

// =================================================================================
// fp32 -> fp16 2-level split
// =================================================================================
__global__ __launch_bounds__(256) void split2h_kernel(
    const float* __restrict__ x, unsigned short* __restrict__ h,
    unsigned short* __restrict__ l, int n4)
{
    int i = blockIdx.x * 256 + threadIdx.x;
    if (i >= n4) return;
    float4 v = ((const float4*)x)[i];
    float vv[4] = { v.x, v.y, v.z, v.w };
    unsigned short hh[4], ll[4];
#pragma unroll
    for (int j = 0; j < 4; j++) {
        __half hb = __float2half_rn(vv[j]);
        float r1 = vv[j] - __half2float(hb);
        __half lb = __float2half_rn(r1);
        hh[j] = __half_as_ushort(hb);
        ll[j] = __half_as_ushort(lb);
    }
    ((ushort4*)h)[i] = make_ushort4(hh[0], hh[1], hh[2], hh[3]);
    ((ushort4*)l)[i] = make_ushort4(ll[0], ll[1], ll[2], ll[3]);
}

// =================================================================================
// V transpose + fp16 quantize:  g_vh[token][h*64+d] -> g_v0t[(bh*64+d)*1024 + token]
// =================================================================================
__global__ __launch_bounds__(256) void vtrans_kernel()
{
    __shared__ float ttile[32][33];
    const int bh = blockIdx.z, b = bh >> 4, h = bh & 15;
    const int t0 = blockIdx.x * 32, d0 = blockIdx.y * 32;
    const int tx = threadIdx.x, ty = threadIdx.y;
#pragma unroll
    for (int j = 0; j < 4; j++) {
        int tok = t0 + ty + j * 8;
        ttile[ty + j * 8][tx] =
            g_vh[(size_t)(b * SEQ + tok) * D_MODEL + h * DKH + d0 + tx];
    }
    __syncthreads();
#pragma unroll
    for (int j = 0; j < 4; j++) {
        int d = d0 + ty + j * 8;
        float x = ttile[tx][ty + j * 8];
        size_t o = ((size_t)bh * DKH + d) * SEQ + t0 + tx;
        g_v0t[o] = __half_as_ushort(__float2half_rn(x));
    }
}

// =================================================================================
// 2-level fp16 mma GEMM — 3-stage ring, 128x64 tile, 2 CTAs/SM.
// NPASS=3: hh,hl,lh.  NPASS=2: hh,hl.
// =================================================================================
#define KC         32
#define NCHUNK     (D_MODEL / KC)
#define TLD        80
#define AT_BYTES   (128 * TLD)
#define BT_BYTES   (64 * TLD)
#define STAGE      (2 * AT_BYTES + 2 * BT_BYTES)   // 30720
#define GSMEM3     (3 * STAGE)                     // 92160

template<int NPASS, bool SPLIT_OUT>
__global__ void __launch_bounds__(256, 2) gemm_2h(
    const unsigned short* __restrict__ A0, const unsigned short* __restrict__ A1,
    const unsigned short* __restrict__ B0, const unsigned short* __restrict__ B1,
    const float* __restrict__ bias,
    float* __restrict__ C,
    unsigned short* __restrict__ H, unsigned short* __restrict__ L)
{
    extern __shared__ char smc[];
    const uint32_t sbase = smem_u32(smc);
    const int tid = threadIdx.x, wid = tid >> 5, lane = tid & 31;
    const int bn = blockIdx.x, bm = blockIdx.y;
    const int wm = wid & 3, wn = wid >> 2;

    const unsigned short* srcs[4];
    srcs[0] = A0 + (size_t)bm * 128 * D_MODEL;
    srcs[1] = A1 + (size_t)bm * 128 * D_MODEL;
    srcs[2] = B0 + (size_t)bn * 64 * D_MODEL;
    srcs[3] = B1 + (size_t)bn * 64 * D_MODEL;

    float acc[2][4][4];
#pragma unroll
    for (int i = 0; i < 2; i++)
#pragma unroll
        for (int j = 0; j < 4; j++)
#pragma unroll
            for (int v = 0; v < 4; v++) acc[i][j][v] = 0.f;

    const uint32_t a_l = (uint32_t)(wm * 32 + (lane & 15)) * TLD + ((lane >> 4) & 1) * 16;
    const uint32_t b_l = (uint32_t)(wn * 32 + (lane & 7) + ((lane >> 4) & 1) * 8) * TLD
                       + ((lane >> 3) & 1) * 16;

    auto fill = [&](int c, int s) {
        const uint32_t base = sbase + (uint32_t)s * STAGE;
#pragma unroll
        for (int n = 0; n < 6; n++) {
            int i = tid + n * 256;
            bool isA = i < 1024;
            int j   = isA ? i : i - 1024;
            int lev = isA ? (j >> 9) : (j >> 8);
            int r   = isA ? ((j >> 2) & 127) : ((j >> 2) & 63);
            int c16 = j & 3;
            const unsigned short* src = srcs[(isA ? 0 : 2) + lev]
                + (size_t)r * D_MODEL + c * KC + c16 * 8;
            uint32_t dst = base + (isA ? (uint32_t)lev * AT_BYTES
                                       : 2u * AT_BYTES + (uint32_t)lev * BT_BYTES)
                         + (uint32_t)r * TLD + c16 * 16;
            cp16(dst, src);
        }
        asm volatile("cp.async.commit_group;" ::: "memory");
    };

    fill(0, 0);
    fill(1, 1);

    constexpr int PA[4] = { 0, 0, 1, 1 };
    constexpr int PB[4] = { 0, 1, 0, 1 };

    int stage = 0;
    for (int c = 0; c < NCHUNK; c++) {
        if (c + 1 < NCHUNK)
            asm volatile("cp.async.wait_group 1;" ::: "memory");
        else
            asm volatile("cp.async.wait_group 0;" ::: "memory");
        __syncthreads();

        if (c + 2 < NCHUNK) {
            int fs = stage + 2; if (fs >= 3) fs -= 3;
            fill(c + 2, fs);
        }

        const uint32_t abase = sbase + (uint32_t)stage * STAGE;
        const uint32_t bbase = abase + 2 * AT_BYTES;

#pragma unroll
        for (int kb = 0; kb < 2; kb++) {
            const uint32_t kbyte = kb * 32;
            uint32_t af[2][2][4], bfr[2][2][4];
#pragma unroll
            for (int lv = 0; lv < 2; lv++) {
#pragma unroll
                for (int mt = 0; mt < 2; mt++)
                    ldsm_x4(af[lv][mt], abase + lv * AT_BYTES + a_l + mt * (16 * TLD) + kbyte);
#pragma unroll
                for (int np = 0; np < 2; np++)
                    ldsm_x4(bfr[lv][np], bbase + lv * BT_BYTES + b_l + np * (16 * TLD) + kbyte);
            }
#pragma unroll
            for (int p = 0; p < NPASS; p++) {
#pragma unroll
                for (int mt = 0; mt < 2; mt++)
#pragma unroll
                    for (int nt = 0; nt < 4; nt++)
                        mma_f16(acc[mt][nt], af[PA[p]][mt],
                                &bfr[PB[p]][nt >> 1][(nt & 1) * 2]);
            }
        }
        if (++stage == 3) stage = 0;
    }

    const int qr = lane >> 2;
#pragma unroll
    for (int mt = 0; mt < 2; mt++) {
        int row0 = bm * 128 + wm * 32 + mt * 16 + qr;
#pragma unroll
        for (int nt = 0; nt < 4; nt++) {
            int col = bn * 64 + wn * 32 + nt * 8 + (lane & 3) * 2;
            float v00 = acc[mt][nt][0] + bias[col];
            float v01 = acc[mt][nt][1] + bias[col + 1];
            float v10 = acc[mt][nt][2] + bias[col];
            float v11 = acc[mt][nt][3] + bias[col + 1];
            if (SPLIT_OUT) {
                ushort2 h0 = split_h(v00), h1 = split_h(v01);
                ushort2 h2 = split_h(v10), h3 = split_h(v11);
                *(ushort2*)(H + (size_t)row0 * D_MODEL + col)       = make_ushort2(h0.x, h1.x);
                *(ushort2*)(L + (size_t)row0 * D_MODEL + col)       = make_ushort2(h0.y, h1.y);
                *(ushort2*)(H + (size_t)(row0 + 8) * D_MODEL + col) = make_ushort2(h2.x, h3.x);
                *(ushort2*)(L + (size_t)(row0 + 8) * D_MODEL + col) = make_ushort2(h2.y, h3.y);
            } else {
                float2 v0 = { v00, v01 }, v1 = { v10, v11 };
                *(float2*)(C + (size_t)row0 * D_MODEL + col)       = v0;
                *(float2*)(C + (size_t)(row0 + 8) * D_MODEL + col) = v1;
            }
        }
    }
}

// =================================================================================
// mma attention — fp32 scores, PV single pass (Ph*Vh).
// attn-out write INTERLEAVED into the PV kt-loop (overlaps DRAM stores with mma).
// =================================================================================
#define PS_LD     1032
#define PS_BYTES  (32 * PS_LD * 4)       // 132096
#define KROWB     144
#define KLEV      (128 * KROWB)
#define KSTG      (2 * KLEV)             // 36864
#define VROWB     272
#define VLEV      (64 * VROWB)           // 17408 (single level)
#define ATTN_SMEM (PS_BYTES + 2 * KSTG)  // 205824

__global__ __launch_bounds__(256) void attn_mma(
    const unsigned char* __restrict__ mask, float* __restrict__ attn_out,
    const unsigned short* __restrict__ Q0, const unsigned short* __restrict__ Q1,
    unsigned short* __restrict__ C0, unsigned short* __restrict__ C1)
{
    extern __shared__ char smraw[];
    float* Ps = (float*)smraw;
    const uint32_t tbase = smem_u32(smraw) + PS_BYTES;

    const int t = threadIdx.x, w = t >> 5, lane = t & 31;
    const int qt = blockIdx.x, h = blockIdx.y, b = blockIdx.z;
    const int q0 = qt * 32;

    uint32_t af[2][2][4][4];
    {
        const unsigned short* qs[2] = { Q0, Q1 };
        const int r0 = lane >> 2;
        const int c0 = (lane & 3) * 2;
#pragma unroll
        for (int lv = 0; lv < 2; lv++)
#pragma unroll
            for (int mt = 0; mt < 2; mt++)
#pragma unroll
                for (int ks = 0; ks < 4; ks++) {
                    size_t base = (size_t)(b * SEQ + q0 + mt * 16 + r0) * D_MODEL
                                + h * DKH + ks * 16 + c0;
                    af[lv][mt][ks][0] = *(const uint32_t*)(qs[lv] + base);
                    af[lv][mt][ks][1] = *(const uint32_t*)(qs[lv] + base + 8 * D_MODEL);
                    af[lv][mt][ks][2] = *(const uint32_t*)(qs[lv] + base + 8);
                    af[lv][mt][ks][3] = *(const uint32_t*)(qs[lv] + base + 8 * D_MODEL + 8);
                }
    }

    auto kfill = [&](int kt, int s) {
#pragma unroll
        for (int n = 0; n < 8; n++) {
            int i = t + n * 256;
            int lv = i >> 10, j = i & 1023;
            int r = j >> 3, u = j & 7;
            const unsigned short* src = (lv ? g_k1s : g_k0s)
                + (size_t)(b * SEQ + kt * 128 + r) * D_MODEL + h * DKH + u * 8;
            cp16(tbase + s * KSTG + lv * KLEV + (uint32_t)r * KROWB + u * 16, src);
        }
        asm volatile("cp.async.commit_group;" ::: "memory");
    };
    const uint32_t krow = (uint32_t)(w * 16 + (lane & 7) + ((lane >> 4) & 1) * 8) * KROWB
                        + ((lane >> 3) & 1) * 16;
    kfill(0, 0);
    kfill(1, 1);

    for (int kt = 0; kt < 8; kt++) {
        if (kt < 7) asm volatile("cp.async.wait_group 1;" ::: "memory");
        else        asm volatile("cp.async.wait_group 0;" ::: "memory");
        __syncthreads();
        const uint32_t kb = tbase + (kt & 1) * KSTG;

        uint32_t bf[2][4][4];
#pragma unroll
        for (int lv = 0; lv < 2; lv++)
#pragma unroll
            for (int ks = 0; ks < 4; ks++)
                ldsm_x4(bf[lv][ks], kb + lv * KLEV + krow + ks * 32);

        float acc[2][2][4];
#pragma unroll
        for (int i = 0; i < 2; i++)
#pragma unroll
            for (int j = 0; j < 2; j++)
#pragma unroll
                for (int v = 0; v < 4; v++) acc[i][j][v] = 0.f;

#pragma unroll
        for (int ks = 0; ks < 4; ks++) {
#pragma unroll
            for (int mt = 0; mt < 2; mt++)
#pragma unroll
                for (int nt = 0; nt < 2; nt++) {
                    mma_f16(acc[mt][nt], af[0][mt][ks], &bf[0][ks][nt * 2]);
                    mma_f16(acc[mt][nt], af[0][mt][ks], &bf[1][ks][nt * 2]);
                    mma_f16(acc[mt][nt], af[1][mt][ks], &bf[0][ks][nt * 2]);
                }
        }

#pragma unroll
        for (int mt = 0; mt < 2; mt++) {
#pragma unroll
            for (int nt = 0; nt < 2; nt++) {
                int row = mt * 16 + (lane >> 2);
                int col = kt * 128 + w * 16 + nt * 8 + (lane & 3) * 2;
                const unsigned char* mp0 =
                    mask + (size_t)(b * SEQ + q0 + row) * SEQ + col;
                const unsigned char* mp1 = mp0 + 8 * SEQ;
                float2 v0, v1;
                v0.x = mp0[0] ? -1e9f : acc[mt][nt][0] * 0.125f;
                v0.y = mp0[1] ? -1e9f : acc[mt][nt][1] * 0.125f;
                v1.x = mp1[0] ? -1e9f : acc[mt][nt][2] * 0.125f;
                v1.y = mp1[1] ? -1e9f : acc[mt][nt][3] * 0.125f;
                *(float2*)&Ps[row * PS_LD + col]       = v0;
                *(float2*)&Ps[(row + 8) * PS_LD + col] = v1;
            }
        }
        __syncthreads();
        if (kt + 2 < 8) kfill(kt + 2, kt & 1);
    }
    __syncthreads();

    {
        int row = t >> 3, sub = t & 7;
        float* pr = Ps + row * PS_LD;
        float m = -1e30f;
        for (int cc = sub; cc < SEQ; cc += 8) m = fmaxf(m, pr[cc]);
#pragma unroll
        for (int o = 4; o > 0; o >>= 1) m = fmaxf(m, __shfl_xor_sync(0xffffffffu, m, o, 8));
        float s = 0.f;
        for (int cc = sub; cc < SEQ; cc += 8) { float e = __expf(pr[cc] - m); pr[cc] = e; s += e; }
#pragma unroll
        for (int o = 4; o > 0; o >>= 1) s += __shfl_xor_sync(0xffffffffu, s, o, 8);
        float inv = 1.0f / s;
        for (int cc = sub; cc < SEQ; cc += 8) pr[cc] *= inv;
    }
    __syncthreads();   // softmax complete; Ps is read-only from here on

    // ---- PV phase with interleaved attn-out stores ----
    auto vfill = [&](int kt, int s) {
#pragma unroll
        for (int n = 0; n < 4; n++) {
            int i = t + n * 256;                 // 0..1023
            int r = i >> 4, u = i & 15;          // 64 d-rows x 256B (128 tokens)
            const unsigned short* src = g_v0t
                + ((size_t)(b * NHEAD + h) * DKH + r) * SEQ + kt * 128 + u * 8;
            cp16(tbase + s * VLEV + (uint32_t)r * VROWB + u * 16, src);
        }
        asm volatile("cp.async.commit_group;" ::: "memory");
    };
    const int mh = w & 1, nq = w >> 1;
    const uint32_t vrow = (uint32_t)(nq * 16 + (lane & 7) + ((lane >> 4) & 1) * 8) * VROWB
                        + ((lane >> 3) & 1) * 16;
    float oacc[2][4];
#pragma unroll
    for (int i = 0; i < 2; i++)
#pragma unroll
        for (int v = 0; v < 4; v++) oacc[i][v] = 0.f;

    vfill(0, 0);
    vfill(1, 1);

    const int pr0 = mh * 16 + (lane >> 2);
    const int pc0 = (lane & 3) * 2;
    float* ab = attn_out ? attn_out + (((size_t)(b * NHEAD + h)) * SEQ + q0) * SEQ : nullptr;

    for (int kt = 0; kt < 8; kt++) {
        if (kt < 7) asm volatile("cp.async.wait_group 1;" ::: "memory");
        else        asm volatile("cp.async.wait_group 0;" ::: "memory");
        __syncthreads();
        const uint32_t vb = tbase + (kt & 1) * VLEV;

        // interleaved attn write for this token block (Ps stable, no sync needed)
        if (ab) {
#pragma unroll
            for (int i = 0; i < 4; i++) {
                int idx = t + i * 256;           // 0..1023
                int r  = idx >> 5;
                int c4 = (idx & 31) << 2;
                *(float4*)&ab[(size_t)r * SEQ + kt * 128 + c4] =
                    *(const float4*)&Ps[r * PS_LD + kt * 128 + c4];
            }
        }

#pragma unroll
        for (int ks = 0; ks < 8; ks++) {
            uint32_t bv[4];
            ldsm_x4(bv, vb + vrow + ks * 32);

            int pc = kt * 128 + ks * 16 + pc0;
            float2 p00 = *(float2*)&Ps[pr0 * PS_LD + pc];
            float2 p10 = *(float2*)&Ps[(pr0 + 8) * PS_LD + pc];
            float2 p01 = *(float2*)&Ps[pr0 * PS_LD + pc + 8];
            float2 p11 = *(float2*)&Ps[(pr0 + 8) * PS_LD + pc + 8];

            uint32_t ph[4];
            {
                __half2 h0 = __floats2half2_rn(p00.x, p00.y);
                __half2 h1 = __floats2half2_rn(p10.x, p10.y);
                __half2 h2 = __floats2half2_rn(p01.x, p01.y);
                __half2 h3 = __floats2half2_rn(p11.x, p11.y);
                ph[0] = *(uint32_t*)&h0; ph[1] = *(uint32_t*)&h1;
                ph[2] = *(uint32_t*)&h2; ph[3] = *(uint32_t*)&h3;
            }
            mma_f16(oacc[0], ph, &bv[0]);
            mma_f16(oacc[1], ph, &bv[2]);
        }
        __syncthreads();
        if (kt + 2 < 8) vfill(kt + 2, kt & 1);
    }

    {
        int orow = b * SEQ + q0 + pr0;
        int ocol = h * DKH + nq * 16 + pc0;
#pragma unroll
        for (int nt = 0; nt < 2; nt++) {
            ushort2 s0 = split_h(oacc[nt][0]), s1 = split_h(oacc[nt][1]);
            ushort2 s2 = split_h(oacc[nt][2]), s3 = split_h(oacc[nt][3]);
            *(ushort2*)&C0[(size_t)orow * D_MODEL + ocol + nt * 8]       = make_ushort2(s0.x, s1.x);
            *(ushort2*)&C1[(size_t)orow * D_MODEL + ocol + nt * 8]       = make_ushort2(s0.y, s1.y);
            *(ushort2*)&C0[(size_t)(orow + 8) * D_MODEL + ocol + nt * 8] = make_ushort2(s2.x, s3.x);
            *(ushort2*)&C1[(size_t)(orow + 8) * D_MODEL + ocol + nt * 8] = make_ushort2(s2.y, s3.y);
        }
    }
}

// =================================================================================
// Residual add + LayerNorm
// =================================================================================
__global__ __launch_bounds__(256) void ln_kernel(
    const float* __restrict__ fc, const float* __restrict__ resid,
    const float* __restrict__ gamma, const float* __restrict__ beta,
    float* __restrict__ out)
{
    __shared__ float xs[D_MODEL];
    __shared__ float rs[8], rss[8];

    const int row = blockIdx.x;
    const int t   = threadIdx.x;
    const float* f = fc    + (size_t)row * D_MODEL;
    const float* r = resid + (size_t)row * D_MODEL;

    float s = 0.f, ss = 0.f;
    for (int i = t; i < D_MODEL; i += 256) {
        float x = f[i] + r[i];
        xs[i] = x;
        s += x; ss += x * x;
    }
#pragma unroll
    for (int o = 16; o > 0; o >>= 1) {
        s  += __shfl_xor_sync(0xffffffffu, s, o);
        ss += __shfl_xor_sync(0xffffffffu, ss, o);
    }
    int w = t >> 5, lane = t & 31;
    if (lane == 0) { rs[w] = s; rss[w] = ss; }
    __syncthreads();
    float ts = 0.f, tss = 0.f;
#pragma unroll
    for (int i = 0; i < 8; i++) { ts += rs[i]; tss += rss[i]; }
    float mu  = ts * (1.0f / D_MODEL);
    float var = tss * (1.0f / D_MODEL) - mu * mu;
    float kk  = rsqrtf(var + 1e-5f);

    for (int i = t; i < D_MODEL; i += 256)
        out[(size_t)row * D_MODEL + i] = (xs[i] - mu) * kk * gamma[i] + beta[i];
}

// =================================================================================
// launch
// =================================================================================
extern "C" void kernel_launch(void* const* d_in, const int* in_sizes, int n_in,
                              void* d_out, int out_size)
{
    const float* q    = (const float*)d_in[0];
    const float* k    = (const float*)d_in[1];
    const float* v    = (const float*)d_in[2];
    const unsigned char* mask = (const unsigned char*)d_in[3];
    const float* w_q  = (const float*)d_in[4];
    const float* b_q  = (const float*)d_in[5];
    const float* w_k  = (const float*)d_in[6];
    const float* b_k  = (const float*)d_in[7];
    const float* w_v  = (const float*)d_in[8];
    const float* b_v  = (const float*)d_in[9];
    const float* w_fc = (const float*)d_in[10];
    const float* b_fc = (const float*)d_in[11];
    const float* ln_g = (const float*)d_in[12];
    const float* ln_b = (const float*)d_in[13];
    float* out = (float*)d_out;

    float *qh, *vh, *ctx, *fc;
    unsigned short *a0, *a1, *b0, *b1, *k0s, *k1s;
    cudaGetSymbolAddress((void**)&qh,  g_qh);
    cudaGetSymbolAddress((void**)&vh,  g_vh);
    cudaGetSymbolAddress((void**)&ctx, g_ctx);
    cudaGetSymbolAddress((void**)&fc,  g_fc);
    cudaGetSymbolAddress((void**)&a0,  g_a0);
    cudaGetSymbolAddress((void**)&a1,  g_a1);
    cudaGetSymbolAddress((void**)&b0,  g_b0);
    cudaGetSymbolAddress((void**)&b1,  g_b1);
    cudaGetSymbolAddress((void**)&k0s, g_k0s);
    cudaGetSymbolAddress((void**)&k1s, g_k1s);

    unsigned short* q0s = (unsigned short*)qh;
    unsigned short* q1s = q0s + (size_t)MROWS * D_MODEL;
    unsigned short* c0s = (unsigned short*)ctx;
    unsigned short* c1s = c0s + (size_t)MROWS * D_MODEL;

    const long long xe = (long long)MROWS * D_MODEL;
    const long long ae = (long long)BATCH * NHEAD * SEQ * SEQ;
    float* attn_out = nullptr;
    float* x_out    = out;
    if ((long long)out_size >= xe + ae) {
        attn_out = out + xe;
    } else if ((long long)out_size == ae) {
        attn_out = out;
        x_out = nullptr;
    }

    cudaFuncSetAttribute((void*)gemm_2h<3, true>,  cudaFuncAttributeMaxDynamicSharedMemorySize, GSMEM3);
    cudaFuncSetAttribute((void*)gemm_2h<2, false>, cudaFuncAttributeMaxDynamicSharedMemorySize, GSMEM3);
    cudaFuncSetAttribute((void*)attn_mma, cudaFuncAttributeMaxDynamicSharedMemorySize, ATTN_SMEM);

    const int nA4 = MROWS * D_MODEL / 4;
    const int nW4 = D_MODEL * D_MODEL / 4;
    dim3 gb(256);
    dim3 gg(D_MODEL / 64, MROWS / 128);    // (16, 64)

    // Q projection -> split output directly (3-pass: hh, hl, lh)
    split2h_kernel<<<nA4 / 256, gb>>>(q, a0, a1, nA4);
    split2h_kernel<<<nW4 / 256, gb>>>(w_q, b0, b1, nW4);
    gemm_2h<3, true><<<gg, gb, GSMEM3>>>(a0, a1, b0, b1, b_q, nullptr, q0s, q1s);

    // K projection -> split output directly (3-pass)
    split2h_kernel<<<nA4 / 256, gb>>>(k, a0, a1, nA4);
    split2h_kernel<<<nW4 / 256, gb>>>(w_k, b0, b1, nW4);
    gemm_2h<3, true><<<gg, gb, GSMEM3>>>(a0, a1, b0, b1, b_k, nullptr, k0s, k1s);

    // V projection -> fp32 (2-pass: hh, hl)
    split2h_kernel<<<nA4 / 256, gb>>>(v, a0, a1, nA4);
    split2h_kernel<<<nW4 / 256, gb>>>(w_v, b0, b1, nW4);
    gemm_2h<2, false><<<gg, gb, GSMEM3>>>(a0, a1, b0, b1, b_v, vh, nullptr, nullptr);

    vtrans_kernel<<<dim3(SEQ / 32, DKH / 32, BATCH * NHEAD), dim3(32, 8)>>>();

    dim3 ag(SEQ / 32, NHEAD, BATCH);
    attn_mma<<<ag, gb, ATTN_SMEM>>>(mask, attn_out, q0s, q1s, c0s, c1s);

    // FC (2-pass: hh, hl)
    split2h_kernel<<<nW4 / 256, gb>>>(w_fc, b0, b1, nW4);
    gemm_2h<2, false><<<gg, gb, GSMEM3>>>(c0s, c1s, b0, b1, b_fc, fc, nullptr, nullptr);

    if (x_out)
        ln_kernel<<<MROWS, gb>>>(fc, q, ln_g, ln_b, x_out);
}

// round 15
// speedup vs baseline: 1.1731x; 1.0273x over previous
#include <cuda_runtime.h>
#include <cuda_fp16.h>
#include <cstdint>
#include <cstddef>

#define D_MODEL 1024
#define NHEAD   16
#define DKH     64
#define BATCH   8
#define SEQ     1024
#define MROWS   (BATCH * SEQ)   // 8192

// ---------------- scratch (device globals: no cudaMalloc allowed) ----------------
__device__ float g_qh[MROWS * D_MODEL];    // carved as Q h/l split (ushort x2)
__device__ float g_vh[MROWS * D_MODEL];    // fp32 V (for vtrans)
__device__ float g_ctx[MROWS * D_MODEL];   // carved as ctx h/l split (ushort x2)
__device__ float g_fc[MROWS * D_MODEL];
__device__ __align__(16) unsigned short g_a0[MROWS * D_MODEL];
__device__ __align__(16) unsigned short g_a1[MROWS * D_MODEL];
__device__ __align__(16) unsigned short g_a2[MROWS * D_MODEL];
__device__ __align__(16) unsigned short g_a3[MROWS * D_MODEL];
__device__ __align__(16) unsigned short g_b0[D_MODEL * D_MODEL];
__device__ __align__(16) unsigned short g_b1[D_MODEL * D_MODEL];
__device__ __align__(16) unsigned short g_b2[D_MODEL * D_MODEL];
__device__ __align__(16) unsigned short g_b3[D_MODEL * D_MODEL];
__device__ __align__(16) unsigned short g_k0s[MROWS * D_MODEL];
__device__ __align__(16) unsigned short g_k1s[MROWS * D_MODEL];
__device__ __align__(16) unsigned short g_v0t[MROWS * D_MODEL];   // [bh][d][token]

// =================================================================================
// helpers
// =================================================================================
__device__ __forceinline__ uint32_t smem_u32(const void* p) {
    uint32_t a;
    asm("{ .reg .u64 t; cvta.to.shared.u64 t, %1; cvt.u32.u64 %0, t; }" : "=r"(a) : "l"(p));
    return a;
}
__device__ __forceinline__ void ldsm_x4(uint32_t* r, uint32_t addr) {
    asm volatile("ldmatrix.sync.aligned.m8n8.x4.shared.b16 {%0,%1,%2,%3}, [%4];"
        : "=r"(r[0]), "=r"(r[1]), "=r"(r[2]), "=r"(r[3]) : "r"(addr));
}
__device__ __forceinline__ void mma_f16(float* c, const uint32_t* a, const uint32_t* b) {
    asm volatile("mma.sync.aligned.m16n8k16.row.col.f32.f16.f16.f32 "
        "{%0,%1,%2,%3}, {%4,%5,%6,%7}, {%8,%9}, {%0,%1,%2,%3};"
        : "+f"(c[0]), "+f"(c[1]), "+f"(c[2]), "+f"(c[3])
        : "r"(a[0]), "r"(a[1]), "r"(a[2]), "r"(a[3]), "r"(b[0]), "r"(b[1]));
}
__device__ __forceinline__ void cp16(uint32_t dst, const void* src) {
    asm volatile("cp.async.cg.shared.global [%0], [%1], 16;" :: "r"(dst), "l"(src));
}
__device__ __forceinline__ ushort2 split_h(float x) {
    __half hb = __float2half_rn(x);
    float hf = __half2float(hb);
    __half lb = __float2half_rn(x - hf);
    return make_ushort2(__half_as_ushort(hb), __half_as_ushort(lb));
}
__device__ __forceinline__ void split_f4(const float* __restrict__ x,
                                         unsigned short* __restrict__ h,
                                         unsigned short* __restrict__ l, int i)
{
    float4 v = ((const float4*)x)[i];
    ushort2 s0 = split_h(v.x), s1 = split_h(v.y);
    ushort2 s2 = split_h(v.z), s3 = split_h(v.w);
    ((ushort4*)h)[i] = make_ushort4(s0.x, s1.x, s2.x, s3.x);
    ((ushort4*)l)[i] = make_ushort4(s0.y, s1.y, s2.y, s3.y);
}

// =================================================================================
// fp32 -> fp16 2-level split (grid-stride, 4 f4/thread for MLP)
// =================================================================================
__global__ __launch_bounds__(256) void split2h_kernel(
    const float* __restrict__ x, unsigned short* __restrict__ h,
    unsigned short* __restrict__ l, int n4)
{
    int gid = blockIdx.x * 256 + threadIdx.x;
    int stride = gridDim.x * 256;
    for (int i = gid; i < n4; i += stride)
        split_f4(x, h, l, i);
}

// =================================================================================
// V transpose + fp16 quantize
// =================================================================================
__global__ __launch_bounds__(256) void vtrans_kernel()
{
    __shared__ float ttile[32][33];
    const int bh = blockIdx.z, b = bh >> 4, h = bh & 15;
    const int t0 = blockIdx.x * 32, d0 = blockIdx.y * 32;
    const int tx = threadIdx.x, ty = threadIdx.y;
#pragma unroll
    for (int j = 0; j < 4; j++) {
        int tok = t0 + ty + j * 8;
        ttile[ty + j * 8][tx] =
            g_vh[(size_t)(b * SEQ + tok) * D_MODEL + h * DKH + d0 + tx];
    }
    __syncthreads();
#pragma unroll
    for (int j = 0; j < 4; j++) {
        int d = d0 + ty + j * 8;
        float x = ttile[tx][ty + j * 8];
        size_t o = ((size_t)bh * DKH + d) * SEQ + t0 + tx;
        g_v0t[o] = __half_as_ushort(__float2half_rn(x));
    }
}

// =================================================================================
// 2-level fp16 mma GEMM — 3-stage ring, 128x64 tile, 2 CTAs/SM.
// blockIdx.z==1 CTAs instead run the NEXT stage's input splits (overlap DRAM
// work under mma work). FA: activation split (8 f4/thr), FW: weight (1 f4/thr).
// =================================================================================
#define KC         32
#define NCHUNK     (D_MODEL / KC)
#define TLD        80
#define AT_BYTES   (128 * TLD)
#define BT_BYTES   (64 * TLD)
#define STAGE      (2 * AT_BYTES + 2 * BT_BYTES)   // 30720
#define GSMEM3     (3 * STAGE)                     // 92160

template<int NPASS, bool SPLIT_OUT>
__global__ void __launch_bounds__(256, 2) gemm_2h(
    const unsigned short* __restrict__ A0, const unsigned short* __restrict__ A1,
    const unsigned short* __restrict__ B0, const unsigned short* __restrict__ B1,
    const float* __restrict__ bias,
    float* __restrict__ C,
    unsigned short* __restrict__ H, unsigned short* __restrict__ L,
    const float* __restrict__ FA, unsigned short* __restrict__ FA0,
    unsigned short* __restrict__ FA1,
    const float* __restrict__ FW, unsigned short* __restrict__ FW0,
    unsigned short* __restrict__ FW1)
{
    const int tid = threadIdx.x;

    // ---- fused split duty (extra CTAs) ----
    if (blockIdx.z == 1) {
        int gid = (blockIdx.y * gridDim.x + blockIdx.x) * 256 + tid;  // 0..262143
        if (FA) {
#pragma unroll
            for (int j = 0; j < 8; j++)
                split_f4(FA, FA0, FA1, gid + j * 262144);
        }
        if (FW)
            split_f4(FW, FW0, FW1, gid);
        return;
    }

    extern __shared__ char smc[];
    const uint32_t sbase = smem_u32(smc);
    const int wid = tid >> 5, lane = tid & 31;
    const int bn = blockIdx.x, bm = blockIdx.y;
    const int wm = wid & 3, wn = wid >> 2;

    const unsigned short* srcs[4];
    srcs[0] = A0 + (size_t)bm * 128 * D_MODEL;
    srcs[1] = A1 + (size_t)bm * 128 * D_MODEL;
    srcs[2] = B0 + (size_t)bn * 64 * D_MODEL;
    srcs[3] = B1 + (size_t)bn * 64 * D_MODEL;

    float acc[2][4][4];
#pragma unroll
    for (int i = 0; i < 2; i++)
#pragma unroll
        for (int j = 0; j < 4; j++)
#pragma unroll
            for (int v = 0; v < 4; v++) acc[i][j][v] = 0.f;

    const uint32_t a_l = (uint32_t)(wm * 32 + (lane & 15)) * TLD + ((lane >> 4) & 1) * 16;
    const uint32_t b_l = (uint32_t)(wn * 32 + (lane & 7) + ((lane >> 4) & 1) * 8) * TLD
                       + ((lane >> 3) & 1) * 16;

    auto fill = [&](int c, int s) {
        const uint32_t base = sbase + (uint32_t)s * STAGE;
#pragma unroll
        for (int n = 0; n < 6; n++) {
            int i = tid + n * 256;
            bool isA = i < 1024;
            int j   = isA ? i : i - 1024;
            int lev = isA ? (j >> 9) : (j >> 8);
            int r   = isA ? ((j >> 2) & 127) : ((j >> 2) & 63);
            int c16 = j & 3;
            const unsigned short* src = srcs[(isA ? 0 : 2) + lev]
                + (size_t)r * D_MODEL + c * KC + c16 * 8;
            uint32_t dst = base + (isA ? (uint32_t)lev * AT_BYTES
                                       : 2u * AT_BYTES + (uint32_t)lev * BT_BYTES)
                         + (uint32_t)r * TLD + c16 * 16;
            cp16(dst, src);
        }
        asm volatile("cp.async.commit_group;" ::: "memory");
    };

    fill(0, 0);
    fill(1, 1);

    constexpr int PA[4] = { 0, 0, 1, 1 };
    constexpr int PB[4] = { 0, 1, 0, 1 };

    int stage = 0;
    for (int c = 0; c < NCHUNK; c++) {
        if (c + 1 < NCHUNK)
            asm volatile("cp.async.wait_group 1;" ::: "memory");
        else
            asm volatile("cp.async.wait_group 0;" ::: "memory");
        __syncthreads();

        if (c + 2 < NCHUNK) {
            int fs = stage + 2; if (fs >= 3) fs -= 3;
            fill(c + 2, fs);
        }

        const uint32_t abase = sbase + (uint32_t)stage * STAGE;
        const uint32_t bbase = abase + 2 * AT_BYTES;

#pragma unroll
        for (int kb = 0; kb < 2; kb++) {
            const uint32_t kbyte = kb * 32;
            uint32_t af[2][2][4], bfr[2][2][4];
#pragma unroll
            for (int lv = 0; lv < 2; lv++) {
#pragma unroll
                for (int mt = 0; mt < 2; mt++)
                    ldsm_x4(af[lv][mt], abase + lv * AT_BYTES + a_l + mt * (16 * TLD) + kbyte);
#pragma unroll
                for (int np = 0; np < 2; np++)
                    ldsm_x4(bfr[lv][np], bbase + lv * BT_BYTES + b_l + np * (16 * TLD) + kbyte);
            }
#pragma unroll
            for (int p = 0; p < NPASS; p++) {
#pragma unroll
                for (int mt = 0; mt < 2; mt++)
#pragma unroll
                    for (int nt = 0; nt < 4; nt++)
                        mma_f16(acc[mt][nt], af[PA[p]][mt],
                                &bfr[PB[p]][nt >> 1][(nt & 1) * 2]);
            }
        }
        if (++stage == 3) stage = 0;
    }

    const int qr = lane >> 2;
#pragma unroll
    for (int mt = 0; mt < 2; mt++) {
        int row0 = bm * 128 + wm * 32 + mt * 16 + qr;
#pragma unroll
        for (int nt = 0; nt < 4; nt++) {
            int col = bn * 64 + wn * 32 + nt * 8 + (lane & 3) * 2;
            float v00 = acc[mt][nt][0] + bias[col];
            float v01 = acc[mt][nt][1] + bias[col + 1];
            float v10 = acc[mt][nt][2] + bias[col];
            float v11 = acc[mt][nt][3] + bias[col + 1];
            if (SPLIT_OUT) {
                ushort2 h0 = split_h(v00), h1 = split_h(v01);
                ushort2 h2 = split_h(v10), h3 = split_h(v11);
                *(ushort2*)(H + (size_t)row0 * D_MODEL + col)       = make_ushort2(h0.x, h1.x);
                *(ushort2*)(L + (size_t)row0 * D_MODEL + col)       = make_ushort2(h0.y, h1.y);
                *(ushort2*)(H + (size_t)(row0 + 8) * D_MODEL + col) = make_ushort2(h2.x, h3.x);
                *(ushort2*)(L + (size_t)(row0 + 8) * D_MODEL + col) = make_ushort2(h2.y, h3.y);
            } else {
                float2 v0 = { v00, v01 }, v1 = { v10, v11 };
                *(float2*)(C + (size_t)row0 * D_MODEL + col)       = v0;
                *(float2*)(C + (size_t)(row0 + 8) * D_MODEL + col) = v1;
            }
        }
    }
}

// =================================================================================
// mma attention — fp32 scores, PV single pass, interleaved attn-out write.
// =================================================================================
#define PS_LD     1032
#define PS_BYTES  (32 * PS_LD * 4)       // 132096
#define KROWB     144
#define KLEV      (128 * KROWB)
#define KSTG      (2 * KLEV)             // 36864
#define VROWB     272
#define VLEV      (64 * VROWB)           // 17408
#define ATTN_SMEM (PS_BYTES + 2 * KSTG)  // 205824

__global__ __launch_bounds__(256) void attn_mma(
    const unsigned char* __restrict__ mask, float* __restrict__ attn_out,
    const unsigned short* __restrict__ Q0, const unsigned short* __restrict__ Q1,
    unsigned short* __restrict__ C0, unsigned short* __restrict__ C1)
{
    extern __shared__ char smraw[];
    float* Ps = (float*)smraw;
    const uint32_t tbase = smem_u32(smraw) + PS_BYTES;

    const int t = threadIdx.x, w = t >> 5, lane = t & 31;
    const int qt = blockIdx.x, h = blockIdx.y, b = blockIdx.z;
    const int q0 = qt * 32;

    uint32_t af[2][2][4][4];
    {
        const unsigned short* qs[2] = { Q0, Q1 };
        const int r0 = lane >> 2;
        const int c0 = (lane & 3) * 2;
#pragma unroll
        for (int lv = 0; lv < 2; lv++)
#pragma unroll
            for (int mt = 0; mt < 2; mt++)
#pragma unroll
                for (int ks = 0; ks < 4; ks++) {
                    size_t base = (size_t)(b * SEQ + q0 + mt * 16 + r0) * D_MODEL
                                + h * DKH + ks * 16 + c0;
                    af[lv][mt][ks][0] = *(const uint32_t*)(qs[lv] + base);
                    af[lv][mt][ks][1] = *(const uint32_t*)(qs[lv] + base + 8 * D_MODEL);
                    af[lv][mt][ks][2] = *(const uint32_t*)(qs[lv] + base + 8);
                    af[lv][mt][ks][3] = *(const uint32_t*)(qs[lv] + base + 8 * D_MODEL + 8);
                }
    }

    auto kfill = [&](int kt, int s) {
#pragma unroll
        for (int n = 0; n < 8; n++) {
            int i = t + n * 256;
            int lv = i >> 10, j = i & 1023;
            int r = j >> 3, u = j & 7;
            const unsigned short* src = (lv ? g_k1s : g_k0s)
                + (size_t)(b * SEQ + kt * 128 + r) * D_MODEL + h * DKH + u * 8;
            cp16(tbase + s * KSTG + lv * KLEV + (uint32_t)r * KROWB + u * 16, src);
        }
        asm volatile("cp.async.commit_group;" ::: "memory");
    };
    const uint32_t krow = (uint32_t)(w * 16 + (lane & 7) + ((lane >> 4) & 1) * 8) * KROWB
                        + ((lane >> 3) & 1) * 16;
    kfill(0, 0);
    kfill(1, 1);

    for (int kt = 0; kt < 8; kt++) {
        if (kt < 7) asm volatile("cp.async.wait_group 1;" ::: "memory");
        else        asm volatile("cp.async.wait_group 0;" ::: "memory");
        __syncthreads();
        const uint32_t kb = tbase + (kt & 1) * KSTG;

        uint32_t bf[2][4][4];
#pragma unroll
        for (int lv = 0; lv < 2; lv++)
#pragma unroll
            for (int ks = 0; ks < 4; ks++)
                ldsm_x4(bf[lv][ks], kb + lv * KLEV + krow + ks * 32);

        float acc[2][2][4];
#pragma unroll
        for (int i = 0; i < 2; i++)
#pragma unroll
            for (int j = 0; j < 2; j++)
#pragma unroll
                for (int v = 0; v < 4; v++) acc[i][j][v] = 0.f;

#pragma unroll
        for (int ks = 0; ks < 4; ks++) {
#pragma unroll
            for (int mt = 0; mt < 2; mt++)
#pragma unroll
                for (int nt = 0; nt < 2; nt++) {
                    mma_f16(acc[mt][nt], af[0][mt][ks], &bf[0][ks][nt * 2]);
                    mma_f16(acc[mt][nt], af[0][mt][ks], &bf[1][ks][nt * 2]);
                    mma_f16(acc[mt][nt], af[1][mt][ks], &bf[0][ks][nt * 2]);
                }
        }

#pragma unroll
        for (int mt = 0; mt < 2; mt++) {
#pragma unroll
            for (int nt = 0; nt < 2; nt++) {
                int row = mt * 16 + (lane >> 2);
                int col = kt * 128 + w * 16 + nt * 8 + (lane & 3) * 2;
                const unsigned char* mp0 =
                    mask + (size_t)(b * SEQ + q0 + row) * SEQ + col;
                const unsigned char* mp1 = mp0 + 8 * SEQ;
                float2 v0, v1;
                v0.x = mp0[0] ? -1e9f : acc[mt][nt][0] * 0.125f;
                v0.y = mp0[1] ? -1e9f : acc[mt][nt][1] * 0.125f;
                v1.x = mp1[0] ? -1e9f : acc[mt][nt][2] * 0.125f;
                v1.y = mp1[1] ? -1e9f : acc[mt][nt][3] * 0.125f;
                *(float2*)&Ps[row * PS_LD + col]       = v0;
                *(float2*)&Ps[(row + 8) * PS_LD + col] = v1;
            }
        }
        __syncthreads();
        if (kt + 2 < 8) kfill(kt + 2, kt & 1);
    }
    __syncthreads();

    {
        int row = t >> 3, sub = t & 7;
        float* pr = Ps + row * PS_LD;
        float m = -1e30f;
        for (int cc = sub; cc < SEQ; cc += 8) m = fmaxf(m, pr[cc]);
#pragma unroll
        for (int o = 4; o > 0; o >>= 1) m = fmaxf(m, __shfl_xor_sync(0xffffffffu, m, o, 8));
        float s = 0.f;
        for (int cc = sub; cc < SEQ; cc += 8) { float e = __expf(pr[cc] - m); pr[cc] = e; s += e; }
#pragma unroll
        for (int o = 4; o > 0; o >>= 1) s += __shfl_xor_sync(0xffffffffu, s, o, 8);
        float inv = 1.0f / s;
        for (int cc = sub; cc < SEQ; cc += 8) pr[cc] *= inv;
    }
    __syncthreads();   // softmax complete; Ps read-only from here

    auto vfill = [&](int kt, int s) {
#pragma unroll
        for (int n = 0; n < 4; n++) {
            int i = t + n * 256;
            int r = i >> 4, u = i & 15;
            const unsigned short* src = g_v0t
                + ((size_t)(b * NHEAD + h) * DKH + r) * SEQ + kt * 128 + u * 8;
            cp16(tbase + s * VLEV + (uint32_t)r * VROWB + u * 16, src);
        }
        asm volatile("cp.async.commit_group;" ::: "memory");
    };
    const int mh = w & 1, nq = w >> 1;
    const uint32_t vrow = (uint32_t)(nq * 16 + (lane & 7) + ((lane >> 4) & 1) * 8) * VROWB
                        + ((lane >> 3) & 1) * 16;
    float oacc[2][4];
#pragma unroll
    for (int i = 0; i < 2; i++)
#pragma unroll
        for (int v = 0; v < 4; v++) oacc[i][v] = 0.f;

    vfill(0, 0);
    vfill(1, 1);

    const int pr0 = mh * 16 + (lane >> 2);
    const int pc0 = (lane & 3) * 2;
    float* ab = attn_out ? attn_out + (((size_t)(b * NHEAD + h)) * SEQ + q0) * SEQ : nullptr;

    for (int kt = 0; kt < 8; kt++) {
        if (kt < 7) asm volatile("cp.async.wait_group 1;" ::: "memory");
        else        asm volatile("cp.async.wait_group 0;" ::: "memory");
        __syncthreads();
        const uint32_t vb = tbase + (kt & 1) * VLEV;

        if (ab) {
#pragma unroll
            for (int i = 0; i < 4; i++) {
                int idx = t + i * 256;
                int r  = idx >> 5;
                int c4 = (idx & 31) << 2;
                *(float4*)&ab[(size_t)r * SEQ + kt * 128 + c4] =
                    *(const float4*)&Ps[r * PS_LD + kt * 128 + c4];
            }
        }

#pragma unroll
        for (int ks = 0; ks < 8; ks++) {
            uint32_t bv[4];
            ldsm_x4(bv, vb + vrow + ks * 32);

            int pc = kt * 128 + ks * 16 + pc0;
            float2 p00 = *(float2*)&Ps[pr0 * PS_LD + pc];
            float2 p10 = *(float2*)&Ps[(pr0 + 8) * PS_LD + pc];
            float2 p01 = *(float2*)&Ps[pr0 * PS_LD + pc + 8];
            float2 p11 = *(float2*)&Ps[(pr0 + 8) * PS_LD + pc + 8];

            uint32_t ph[4];
            {
                __half2 h0 = __floats2half2_rn(p00.x, p00.y);
                __half2 h1 = __floats2half2_rn(p10.x, p10.y);
                __half2 h2 = __floats2half2_rn(p01.x, p01.y);
                __half2 h3 = __floats2half2_rn(p11.x, p11.y);
                ph[0] = *(uint32_t*)&h0; ph[1] = *(uint32_t*)&h1;
                ph[2] = *(uint32_t*)&h2; ph[3] = *(uint32_t*)&h3;
            }
            mma_f16(oacc[0], ph, &bv[0]);
            mma_f16(oacc[1], ph, &bv[2]);
        }
        __syncthreads();
        if (kt + 2 < 8) vfill(kt + 2, kt & 1);
    }

    {
        int orow = b * SEQ + q0 + pr0;
        int ocol = h * DKH + nq * 16 + pc0;
#pragma unroll
        for (int nt = 0; nt < 2; nt++) {
            ushort2 s0 = split_h(oacc[nt][0]), s1 = split_h(oacc[nt][1]);
            ushort2 s2 = split_h(oacc[nt][2]), s3 = split_h(oacc[nt][3]);
            *(ushort2*)&C0[(size_t)orow * D_MODEL + ocol + nt * 8]       = make_ushort2(s0.x, s1.x);
            *(ushort2*)&C1[(size_t)orow * D_MODEL + ocol + nt * 8]       = make_ushort2(s0.y, s1.y);
            *(ushort2*)&C0[(size_t)(orow + 8) * D_MODEL + ocol + nt * 8] = make_ushort2(s2.x, s3.x);
            *(ushort2*)&C1[(size_t)(orow + 8) * D_MODEL + ocol + nt * 8] = make_ushort2(s2.y, s3.y);
        }
    }
}

// =================================================================================
// Residual add + LayerNorm (float4)
// =================================================================================
__global__ __launch_bounds__(256) void ln_kernel(
    const float* __restrict__ fc, const float* __restrict__ resid,
    const float* __restrict__ gamma, const float* __restrict__ beta,
    float* __restrict__ out)
{
    __shared__ float4 xs[256];
    __shared__ float rs[8], rss[8];

    const int row = blockIdx.x;
    const int t   = threadIdx.x;
    const float4* f = (const float4*)(fc    + (size_t)row * D_MODEL);
    const float4* r = (const float4*)(resid + (size_t)row * D_MODEL);

    float4 fx = f[t], rx = r[t];
    float4 x = { fx.x + rx.x, fx.y + rx.y, fx.z + rx.z, fx.w + rx.w };
    xs[t] = x;
    float s  = x.x + x.y + x.z + x.w;
    float ss = x.x * x.x + x.y * x.y + x.z * x.z + x.w * x.w;
#pragma unroll
    for (int o = 16; o > 0; o >>= 1) {
        s  += __shfl_xor_sync(0xffffffffu, s, o);
        ss += __shfl_xor_sync(0xffffffffu, ss, o);
    }
    int w = t >> 5, lane = t & 31;
    if (lane == 0) { rs[w] = s; rss[w] = ss; }
    __syncthreads();
    float ts = 0.f, tss = 0.f;
#pragma unroll
    for (int i = 0; i < 8; i++) { ts += rs[i]; tss += rss[i]; }
    float mu  = ts * (1.0f / D_MODEL);
    float var = tss * (1.0f / D_MODEL) - mu * mu;
    float kk  = rsqrtf(var + 1e-5f);

    const float4 g4 = ((const float4*)gamma)[t];
    const float4 b4 = ((const float4*)beta)[t];
    float4 xv = xs[t];
    float4 o4;
    o4.x = (xv.x - mu) * kk * g4.x + b4.x;
    o4.y = (xv.y - mu) * kk * g4.y + b4.y;
    o4.z = (xv.z - mu) * kk * g4.z + b4.z;
    o4.w = (xv.w - mu) * kk * g4.w + b4.w;
    ((float4*)(out + (size_t)row * D_MODEL))[t] = o4;
}

// =================================================================================
// launch
// =================================================================================
extern "C" void kernel_launch(void* const* d_in, const int* in_sizes, int n_in,
                              void* d_out, int out_size)
{
    const float* q    = (const float*)d_in[0];
    const float* k    = (const float*)d_in[1];
    const float* v    = (const float*)d_in[2];
    const unsigned char* mask = (const unsigned char*)d_in[3];
    const float* w_q  = (const float*)d_in[4];
    const float* b_q  = (const float*)d_in[5];
    const float* w_k  = (const float*)d_in[6];
    const float* b_k  = (const float*)d_in[7];
    const float* w_v  = (const float*)d_in[8];
    const float* b_v  = (const float*)d_in[9];
    const float* w_fc = (const float*)d_in[10];
    const float* b_fc = (const float*)d_in[11];
    const float* ln_g = (const float*)d_in[12];
    const float* ln_b = (const float*)d_in[13];
    float* out = (float*)d_out;

    float *qh, *vh, *ctx, *fc;
    unsigned short *a0, *a1, *a2, *a3, *b0, *b1, *b2, *b3, *k0s, *k1s;
    cudaGetSymbolAddress((void**)&qh,  g_qh);
    cudaGetSymbolAddress((void**)&vh,  g_vh);
    cudaGetSymbolAddress((void**)&ctx, g_ctx);
    cudaGetSymbolAddress((void**)&fc,  g_fc);
    cudaGetSymbolAddress((void**)&a0,  g_a0);
    cudaGetSymbolAddress((void**)&a1,  g_a1);
    cudaGetSymbolAddress((void**)&a2,  g_a2);
    cudaGetSymbolAddress((void**)&a3,  g_a3);
    cudaGetSymbolAddress((void**)&b0,  g_b0);
    cudaGetSymbolAddress((void**)&b1,  g_b1);
    cudaGetSymbolAddress((void**)&b2,  g_b2);
    cudaGetSymbolAddress((void**)&b3,  g_b3);
    cudaGetSymbolAddress((void**)&k0s, g_k0s);
    cudaGetSymbolAddress((void**)&k1s, g_k1s);

    unsigned short* q0s = (unsigned short*)qh;
    unsigned short* q1s = q0s + (size_t)MROWS * D_MODEL;
    unsigned short* c0s = (unsigned short*)ctx;
    unsigned short* c1s = c0s + (size_t)MROWS * D_MODEL;

    const long long xe = (long long)MROWS * D_MODEL;
    const long long ae = (long long)BATCH * NHEAD * SEQ * SEQ;
    float* attn_out = nullptr;
    float* x_out    = out;
    if ((long long)out_size >= xe + ae) {
        attn_out = out + xe;
    } else if ((long long)out_size == ae) {
        attn_out = out;
        x_out = nullptr;
    }

    cudaFuncSetAttribute((void*)gemm_2h<3, true>,  cudaFuncAttributeMaxDynamicSharedMemorySize, GSMEM3);
    cudaFuncSetAttribute((void*)gemm_2h<2, false>, cudaFuncAttributeMaxDynamicSharedMemorySize, GSMEM3);
    cudaFuncSetAttribute((void*)attn_mma, cudaFuncAttributeMaxDynamicSharedMemorySize, ATTN_SMEM);

    const int nA4 = MROWS * D_MODEL / 4;     // 2097152
    const int nW4 = D_MODEL * D_MODEL / 4;   // 262144
    dim3 gb(256);
    dim3 gg1(D_MODEL / 64, MROWS / 128, 1);  // gemm only
    dim3 gg2(D_MODEL / 64, MROWS / 128, 2);  // gemm + fused next-stage splits

    // stage 0: standalone splits for Q inputs (4 f4/thread ILP)
    split2h_kernel<<<2048, gb>>>(q, a0, a1, nA4);
    split2h_kernel<<<256,  gb>>>(w_q, b0, b1, nW4);

    // gemm Q (+fused: split k->a2/a3, w_k->b2/b3)
    gemm_2h<3, true><<<gg2, gb, GSMEM3>>>(a0, a1, b0, b1, b_q, nullptr, q0s, q1s,
                                          k, a2, a3, w_k, b2, b3);
    // gemm K (+fused: split v->a0/a1, w_v->b0/b1)   [a0/a1,b0/b1 free after gemm Q]
    gemm_2h<3, true><<<gg2, gb, GSMEM3>>>(a2, a3, b2, b3, b_k, nullptr, k0s, k1s,
                                          v, a0, a1, w_v, b0, b1);
    // gemm V (+fused: split w_fc->b2/b3)            [b2/b3 free after gemm K]
    gemm_2h<2, false><<<gg2, gb, GSMEM3>>>(a0, a1, b0, b1, b_v, vh, nullptr, nullptr,
                                           nullptr, nullptr, nullptr, w_fc, b2, b3);

    vtrans_kernel<<<dim3(SEQ / 32, DKH / 32, BATCH * NHEAD), dim3(32, 8)>>>();

    dim3 ag(SEQ / 32, NHEAD, BATCH);
    attn_mma<<<ag, gb, ATTN_SMEM>>>(mask, attn_out, q0s, q1s, c0s, c1s);

    // FC (2-pass; weights pre-split during gemm V)
    gemm_2h<2, false><<<gg1, gb, GSMEM3>>>(c0s, c1s, b2, b3, b_fc, fc, nullptr, nullptr,
                                           nullptr, nullptr, nullptr,
                                           nullptr, nullptr, nullptr);

    if (x_out)
        ln_kernel<<<MROWS, gb>>>(fc, q, ln_g, ln_b, x_out);
}

// round 16
// speedup vs baseline: 1.1982x; 1.0214x over previous
#include <cuda_runtime.h>
#include <cuda_fp16.h>
#include <cstdint>
#include <cstddef>

#define D_MODEL 1024
#define NHEAD   16
#define DKH     64
#define BATCH   8
#define SEQ     1024
#define MROWS   (BATCH * SEQ)   // 8192

// ---------------- scratch (device globals: no cudaMalloc allowed) ----------------
__device__ float g_qh[MROWS * D_MODEL];    // carved as Q h/l split (ushort x2)
__device__ float g_vh[MROWS * D_MODEL];    // fp32 V (for vtrans)
__device__ float g_ctx[MROWS * D_MODEL];   // carved as ctx h/l split (ushort x2)
__device__ float g_fc[MROWS * D_MODEL];
__device__ __align__(16) unsigned short g_a0[MROWS * D_MODEL];
__device__ __align__(16) unsigned short g_a1[MROWS * D_MODEL];
__device__ __align__(16) unsigned short g_a2[MROWS * D_MODEL];
__device__ __align__(16) unsigned short g_a3[MROWS * D_MODEL];
__device__ __align__(16) unsigned short g_b0[D_MODEL * D_MODEL];
__device__ __align__(16) unsigned short g_b1[D_MODEL * D_MODEL];
__device__ __align__(16) unsigned short g_b2[D_MODEL * D_MODEL];
__device__ __align__(16) unsigned short g_b3[D_MODEL * D_MODEL];
__device__ __align__(16) unsigned short g_k0s[MROWS * D_MODEL];
__device__ __align__(16) unsigned short g_k1s[MROWS * D_MODEL];
__device__ __align__(16) unsigned short g_v0t[MROWS * D_MODEL];   // [bh][d][token]

// =================================================================================
// helpers
// =================================================================================
__device__ __forceinline__ uint32_t smem_u32(const void* p) {
    uint32_t a;
    asm("{ .reg .u64 t; cvta.to.shared.u64 t, %1; cvt.u32.u64 %0, t; }" : "=r"(a) : "l"(p));
    return a;
}
__device__ __forceinline__ void ldsm_x4(uint32_t* r, uint32_t addr) {
    asm volatile("ldmatrix.sync.aligned.m8n8.x4.shared.b16 {%0,%1,%2,%3}, [%4];"
        : "=r"(r[0]), "=r"(r[1]), "=r"(r[2]), "=r"(r[3]) : "r"(addr));
}
__device__ __forceinline__ void mma_f16(float* c, const uint32_t* a, const uint32_t* b) {
    asm volatile("mma.sync.aligned.m16n8k16.row.col.f32.f16.f16.f32 "
        "{%0,%1,%2,%3}, {%4,%5,%6,%7}, {%8,%9}, {%0,%1,%2,%3};"
        : "+f"(c[0]), "+f"(c[1]), "+f"(c[2]), "+f"(c[3])
        : "r"(a[0]), "r"(a[1]), "r"(a[2]), "r"(a[3]), "r"(b[0]), "r"(b[1]));
}
__device__ __forceinline__ void cp16(uint32_t dst, const void* src) {
    asm volatile("cp.async.cg.shared.global [%0], [%1], 16;" :: "r"(dst), "l"(src));
}
__device__ __forceinline__ ushort2 split_h(float x) {
    __half hb = __float2half_rn(x);
    float hf = __half2float(hb);
    __half lb = __float2half_rn(x - hf);
    return make_ushort2(__half_as_ushort(hb), __half_as_ushort(lb));
}
__device__ __forceinline__ void split_f4(const float* __restrict__ x,
                                         unsigned short* __restrict__ h,
                                         unsigned short* __restrict__ l, int i)
{
    float4 v = ((const float4*)x)[i];
    ushort2 s0 = split_h(v.x), s1 = split_h(v.y);
    ushort2 s2 = split_h(v.z), s3 = split_h(v.w);
    ((ushort4*)h)[i] = make_ushort4(s0.x, s1.x, s2.x, s3.x);
    ((ushort4*)l)[i] = make_ushort4(s0.y, s1.y, s2.y, s3.y);
}

// =================================================================================
// fp32 -> fp16 2-level split (grid-stride)
// =================================================================================
__global__ __launch_bounds__(256) void split2h_kernel(
    const float* __restrict__ x, unsigned short* __restrict__ h,
    unsigned short* __restrict__ l, int n4)
{
    int gid = blockIdx.x * 256 + threadIdx.x;
    int stride = gridDim.x * 256;
    for (int i = gid; i < n4; i += stride)
        split_f4(x, h, l, i);
}

// =================================================================================
// V transpose + fp16 quantize
// =================================================================================
__global__ __launch_bounds__(256) void vtrans_kernel()
{
    __shared__ float ttile[32][33];
    const int bh = blockIdx.z, b = bh >> 4, h = bh & 15;
    const int t0 = blockIdx.x * 32, d0 = blockIdx.y * 32;
    const int tx = threadIdx.x, ty = threadIdx.y;
#pragma unroll
    for (int j = 0; j < 4; j++) {
        int tok = t0 + ty + j * 8;
        ttile[ty + j * 8][tx] =
            g_vh[(size_t)(b * SEQ + tok) * D_MODEL + h * DKH + d0 + tx];
    }
    __syncthreads();
#pragma unroll
    for (int j = 0; j < 4; j++) {
        int d = d0 + ty + j * 8;
        float x = ttile[tx][ty + j * 8];
        size_t o = ((size_t)bh * DKH + d) * SEQ + t0 + tx;
        g_v0t[o] = __half_as_ushort(__float2half_rn(x));
    }
}

// =================================================================================
// 2-level fp16 mma GEMM — 2-stage pipeline, 128x64 tile, 3 CTAs/SM (occupancy
// was the binder: R15 profile showed tensor 49%, occ 24%).
// blockIdx.z==1 CTAs run the NEXT stage's input splits.
// =================================================================================
#define KC         32
#define NCHUNK     (D_MODEL / KC)
#define TLD        80
#define AT_BYTES   (128 * TLD)
#define BT_BYTES   (64 * TLD)
#define STAGE      (2 * AT_BYTES + 2 * BT_BYTES)   // 30720
#define GSMEM2     (2 * STAGE)                     // 61440

template<int NPASS, bool SPLIT_OUT>
__global__ void __launch_bounds__(256, 3) gemm_2h(
    const unsigned short* __restrict__ A0, const unsigned short* __restrict__ A1,
    const unsigned short* __restrict__ B0, const unsigned short* __restrict__ B1,
    const float* __restrict__ bias,
    float* __restrict__ C,
    unsigned short* __restrict__ H, unsigned short* __restrict__ L,
    const float* __restrict__ FA, unsigned short* __restrict__ FA0,
    unsigned short* __restrict__ FA1,
    const float* __restrict__ FW, unsigned short* __restrict__ FW0,
    unsigned short* __restrict__ FW1)
{
    const int tid = threadIdx.x;

    // ---- fused split duty (extra CTAs) ----
    if (blockIdx.z == 1) {
        int gid = (blockIdx.y * gridDim.x + blockIdx.x) * 256 + tid;  // 0..262143
        if (FA) {
#pragma unroll
            for (int j = 0; j < 8; j++)
                split_f4(FA, FA0, FA1, gid + j * 262144);
        }
        if (FW)
            split_f4(FW, FW0, FW1, gid);
        return;
    }

    extern __shared__ char smc[];
    const uint32_t sbase = smem_u32(smc);
    const int wid = tid >> 5, lane = tid & 31;
    const int bn = blockIdx.x, bm = blockIdx.y;
    const int wm = wid & 3, wn = wid >> 2;

    const unsigned short* srcs[4];
    srcs[0] = A0 + (size_t)bm * 128 * D_MODEL;
    srcs[1] = A1 + (size_t)bm * 128 * D_MODEL;
    srcs[2] = B0 + (size_t)bn * 64 * D_MODEL;
    srcs[3] = B1 + (size_t)bn * 64 * D_MODEL;

    float acc[2][4][4];
#pragma unroll
    for (int i = 0; i < 2; i++)
#pragma unroll
        for (int j = 0; j < 4; j++)
#pragma unroll
            for (int v = 0; v < 4; v++) acc[i][j][v] = 0.f;

    const uint32_t a_l = (uint32_t)(wm * 32 + (lane & 15)) * TLD + ((lane >> 4) & 1) * 16;
    const uint32_t b_l = (uint32_t)(wn * 32 + (lane & 7) + ((lane >> 4) & 1) * 8) * TLD
                       + ((lane >> 3) & 1) * 16;

    auto fill = [&](int c, int s) {
        const uint32_t base = sbase + (uint32_t)s * STAGE;
#pragma unroll
        for (int n = 0; n < 6; n++) {
            int i = tid + n * 256;
            bool isA = i < 1024;
            int j   = isA ? i : i - 1024;
            int lev = isA ? (j >> 9) : (j >> 8);
            int r   = isA ? ((j >> 2) & 127) : ((j >> 2) & 63);
            int c16 = j & 3;
            const unsigned short* src = srcs[(isA ? 0 : 2) + lev]
                + (size_t)r * D_MODEL + c * KC + c16 * 8;
            uint32_t dst = base + (isA ? (uint32_t)lev * AT_BYTES
                                       : 2u * AT_BYTES + (uint32_t)lev * BT_BYTES)
                         + (uint32_t)r * TLD + c16 * 16;
            cp16(dst, src);
        }
        asm volatile("cp.async.commit_group;" ::: "memory");
    };

    fill(0, 0);
    fill(1, 1);

    constexpr int PA[4] = { 0, 0, 1, 1 };
    constexpr int PB[4] = { 0, 1, 0, 1 };

    for (int c = 0; c < NCHUNK; c++) {
        if (c + 1 < NCHUNK)
            asm volatile("cp.async.wait_group 1;" ::: "memory");
        else
            asm volatile("cp.async.wait_group 0;" ::: "memory");
        __syncthreads();

        const int s = c & 1;
        const uint32_t abase = sbase + (uint32_t)s * STAGE;
        const uint32_t bbase = abase + 2 * AT_BYTES;

#pragma unroll
        for (int kb = 0; kb < 2; kb++) {
            const uint32_t kbyte = kb * 32;
            uint32_t af[2][2][4], bfr[2][2][4];
#pragma unroll
            for (int lv = 0; lv < 2; lv++) {
#pragma unroll
                for (int mt = 0; mt < 2; mt++)
                    ldsm_x4(af[lv][mt], abase + lv * AT_BYTES + a_l + mt * (16 * TLD) + kbyte);
#pragma unroll
                for (int np = 0; np < 2; np++)
                    ldsm_x4(bfr[lv][np], bbase + lv * BT_BYTES + b_l + np * (16 * TLD) + kbyte);
            }
#pragma unroll
            for (int p = 0; p < NPASS; p++) {
#pragma unroll
                for (int mt = 0; mt < 2; mt++)
#pragma unroll
                    for (int nt = 0; nt < 4; nt++)
                        mma_f16(acc[mt][nt], af[PA[p]][mt],
                                &bfr[PB[p]][nt >> 1][(nt & 1) * 2]);
            }
        }
        __syncthreads();
        if (c + 2 < NCHUNK) fill(c + 2, s);
    }

    const int qr = lane >> 2;
#pragma unroll
    for (int mt = 0; mt < 2; mt++) {
        int row0 = bm * 128 + wm * 32 + mt * 16 + qr;
#pragma unroll
        for (int nt = 0; nt < 4; nt++) {
            int col = bn * 64 + wn * 32 + nt * 8 + (lane & 3) * 2;
            float v00 = acc[mt][nt][0] + bias[col];
            float v01 = acc[mt][nt][1] + bias[col + 1];
            float v10 = acc[mt][nt][2] + bias[col];
            float v11 = acc[mt][nt][3] + bias[col + 1];
            if (SPLIT_OUT) {
                ushort2 h0 = split_h(v00), h1 = split_h(v01);
                ushort2 h2 = split_h(v10), h3 = split_h(v11);
                *(ushort2*)(H + (size_t)row0 * D_MODEL + col)       = make_ushort2(h0.x, h1.x);
                *(ushort2*)(L + (size_t)row0 * D_MODEL + col)       = make_ushort2(h0.y, h1.y);
                *(ushort2*)(H + (size_t)(row0 + 8) * D_MODEL + col) = make_ushort2(h2.x, h3.x);
                *(ushort2*)(L + (size_t)(row0 + 8) * D_MODEL + col) = make_ushort2(h2.y, h3.y);
            } else {
                float2 v0 = { v00, v01 }, v1 = { v10, v11 };
                *(float2*)(C + (size_t)row0 * D_MODEL + col)       = v0;
                *(float2*)(C + (size_t)(row0 + 8) * D_MODEL + col) = v1;
            }
        }
    }
}

// =================================================================================
// mma attention — fp32 scores, PV single pass, interleaved attn-out write.
// =================================================================================
#define PS_LD     1032
#define PS_BYTES  (32 * PS_LD * 4)       // 132096
#define KROWB     144
#define KLEV      (128 * KROWB)
#define KSTG      (2 * KLEV)             // 36864
#define VROWB     272
#define VLEV      (64 * VROWB)           // 17408
#define ATTN_SMEM (PS_BYTES + 2 * KSTG)  // 205824

__global__ __launch_bounds__(256) void attn_mma(
    const unsigned char* __restrict__ mask, float* __restrict__ attn_out,
    const unsigned short* __restrict__ Q0, const unsigned short* __restrict__ Q1,
    unsigned short* __restrict__ C0, unsigned short* __restrict__ C1)
{
    extern __shared__ char smraw[];
    float* Ps = (float*)smraw;
    const uint32_t tbase = smem_u32(smraw) + PS_BYTES;

    const int t = threadIdx.x, w = t >> 5, lane = t & 31;
    const int qt = blockIdx.x, h = blockIdx.y, b = blockIdx.z;
    const int q0 = qt * 32;

    uint32_t af[2][2][4][4];
    {
        const unsigned short* qs[2] = { Q0, Q1 };
        const int r0 = lane >> 2;
        const int c0 = (lane & 3) * 2;
#pragma unroll
        for (int lv = 0; lv < 2; lv++)
#pragma unroll
            for (int mt = 0; mt < 2; mt++)
#pragma unroll
                for (int ks = 0; ks < 4; ks++) {
                    size_t base = (size_t)(b * SEQ + q0 + mt * 16 + r0) * D_MODEL
                                + h * DKH + ks * 16 + c0;
                    af[lv][mt][ks][0] = *(const uint32_t*)(qs[lv] + base);
                    af[lv][mt][ks][1] = *(const uint32_t*)(qs[lv] + base + 8 * D_MODEL);
                    af[lv][mt][ks][2] = *(const uint32_t*)(qs[lv] + base + 8);
                    af[lv][mt][ks][3] = *(const uint32_t*)(qs[lv] + base + 8 * D_MODEL + 8);
                }
    }

    auto kfill = [&](int kt, int s) {
#pragma unroll
        for (int n = 0; n < 8; n++) {
            int i = t + n * 256;
            int lv = i >> 10, j = i & 1023;
            int r = j >> 3, u = j & 7;
            const unsigned short* src = (lv ? g_k1s : g_k0s)
                + (size_t)(b * SEQ + kt * 128 + r) * D_MODEL + h * DKH + u * 8;
            cp16(tbase + s * KSTG + lv * KLEV + (uint32_t)r * KROWB + u * 16, src);
        }
        asm volatile("cp.async.commit_group;" ::: "memory");
    };
    const uint32_t krow = (uint32_t)(w * 16 + (lane & 7) + ((lane >> 4) & 1) * 8) * KROWB
                        + ((lane >> 3) & 1) * 16;
    kfill(0, 0);
    kfill(1, 1);

    for (int kt = 0; kt < 8; kt++) {
        if (kt < 7) asm volatile("cp.async.wait_group 1;" ::: "memory");
        else        asm volatile("cp.async.wait_group 0;" ::: "memory");
        __syncthreads();
        const uint32_t kb = tbase + (kt & 1) * KSTG;

        uint32_t bf[2][4][4];
#pragma unroll
        for (int lv = 0; lv < 2; lv++)
#pragma unroll
            for (int ks = 0; ks < 4; ks++)
                ldsm_x4(bf[lv][ks], kb + lv * KLEV + krow + ks * 32);

        float acc[2][2][4];
#pragma unroll
        for (int i = 0; i < 2; i++)
#pragma unroll
            for (int j = 0; j < 2; j++)
#pragma unroll
                for (int v = 0; v < 4; v++) acc[i][j][v] = 0.f;

#pragma unroll
        for (int ks = 0; ks < 4; ks++) {
#pragma unroll
            for (int mt = 0; mt < 2; mt++)
#pragma unroll
                for (int nt = 0; nt < 2; nt++) {
                    mma_f16(acc[mt][nt], af[0][mt][ks], &bf[0][ks][nt * 2]);
                    mma_f16(acc[mt][nt], af[0][mt][ks], &bf[1][ks][nt * 2]);
                    mma_f16(acc[mt][nt], af[1][mt][ks], &bf[0][ks][nt * 2]);
                }
        }

#pragma unroll
        for (int mt = 0; mt < 2; mt++) {
#pragma unroll
            for (int nt = 0; nt < 2; nt++) {
                int row = mt * 16 + (lane >> 2);
                int col = kt * 128 + w * 16 + nt * 8 + (lane & 3) * 2;
                const unsigned char* mp0 =
                    mask + (size_t)(b * SEQ + q0 + row) * SEQ + col;
                const unsigned char* mp1 = mp0 + 8 * SEQ;
                float2 v0, v1;
                v0.x = mp0[0] ? -1e9f : acc[mt][nt][0] * 0.125f;
                v0.y = mp0[1] ? -1e9f : acc[mt][nt][1] * 0.125f;
                v1.x = mp1[0] ? -1e9f : acc[mt][nt][2] * 0.125f;
                v1.y = mp1[1] ? -1e9f : acc[mt][nt][3] * 0.125f;
                *(float2*)&Ps[row * PS_LD + col]       = v0;
                *(float2*)&Ps[(row + 8) * PS_LD + col] = v1;
            }
        }
        __syncthreads();
        if (kt + 2 < 8) kfill(kt + 2, kt & 1);
    }
    __syncthreads();

    {
        int row = t >> 3, sub = t & 7;
        float* pr = Ps + row * PS_LD;
        float m = -1e30f;
        for (int cc = sub; cc < SEQ; cc += 8) m = fmaxf(m, pr[cc]);
#pragma unroll
        for (int o = 4; o > 0; o >>= 1) m = fmaxf(m, __shfl_xor_sync(0xffffffffu, m, o, 8));
        float s = 0.f;
        for (int cc = sub; cc < SEQ; cc += 8) { float e = __expf(pr[cc] - m); pr[cc] = e; s += e; }
#pragma unroll
        for (int o = 4; o > 0; o >>= 1) s += __shfl_xor_sync(0xffffffffu, s, o, 8);
        float inv = 1.0f / s;
        for (int cc = sub; cc < SEQ; cc += 8) pr[cc] *= inv;
    }
    __syncthreads();   // softmax complete; Ps read-only from here

    auto vfill = [&](int kt, int s) {
#pragma unroll
        for (int n = 0; n < 4; n++) {
            int i = t + n * 256;
            int r = i >> 4, u = i & 15;
            const unsigned short* src = g_v0t
                + ((size_t)(b * NHEAD + h) * DKH + r) * SEQ + kt * 128 + u * 8;
            cp16(tbase + s * VLEV + (uint32_t)r * VROWB + u * 16, src);
        }
        asm volatile("cp.async.commit_group;" ::: "memory");
    };
    const int mh = w & 1, nq = w >> 1;
    const uint32_t vrow = (uint32_t)(nq * 16 + (lane & 7) + ((lane >> 4) & 1) * 8) * VROWB
                        + ((lane >> 3) & 1) * 16;
    float oacc[2][4];
#pragma unroll
    for (int i = 0; i < 2; i++)
#pragma unroll
        for (int v = 0; v < 4; v++) oacc[i][v] = 0.f;

    vfill(0, 0);
    vfill(1, 1);

    const int pr0 = mh * 16 + (lane >> 2);
    const int pc0 = (lane & 3) * 2;
    float* ab = attn_out ? attn_out + (((size_t)(b * NHEAD + h)) * SEQ + q0) * SEQ : nullptr;

    for (int kt = 0; kt < 8; kt++) {
        if (kt < 7) asm volatile("cp.async.wait_group 1;" ::: "memory");
        else        asm volatile("cp.async.wait_group 0;" ::: "memory");
        __syncthreads();
        const uint32_t vb = tbase + (kt & 1) * VLEV;

        if (ab) {
#pragma unroll
            for (int i = 0; i < 4; i++) {
                int idx = t + i * 256;
                int r  = idx >> 5;
                int c4 = (idx & 31) << 2;
                *(float4*)&ab[(size_t)r * SEQ + kt * 128 + c4] =
                    *(const float4*)&Ps[r * PS_LD + kt * 128 + c4];
            }
        }

#pragma unroll
        for (int ks = 0; ks < 8; ks++) {
            uint32_t bv[4];
            ldsm_x4(bv, vb + vrow + ks * 32);

            int pc = kt * 128 + ks * 16 + pc0;
            float2 p00 = *(float2*)&Ps[pr0 * PS_LD + pc];
            float2 p10 = *(float2*)&Ps[(pr0 + 8) * PS_LD + pc];
            float2 p01 = *(float2*)&Ps[pr0 * PS_LD + pc + 8];
            float2 p11 = *(float2*)&Ps[(pr0 + 8) * PS_LD + pc + 8];

            uint32_t ph[4];
            {
                __half2 h0 = __floats2half2_rn(p00.x, p00.y);
                __half2 h1 = __floats2half2_rn(p10.x, p10.y);
                __half2 h2 = __floats2half2_rn(p01.x, p01.y);
                __half2 h3 = __floats2half2_rn(p11.x, p11.y);
                ph[0] = *(uint32_t*)&h0; ph[1] = *(uint32_t*)&h1;
                ph[2] = *(uint32_t*)&h2; ph[3] = *(uint32_t*)&h3;
            }
            mma_f16(oacc[0], ph, &bv[0]);
            mma_f16(oacc[1], ph, &bv[2]);
        }
        __syncthreads();
        if (kt + 2 < 8) vfill(kt + 2, kt & 1);
    }

    {
        int orow = b * SEQ + q0 + pr0;
        int ocol = h * DKH + nq * 16 + pc0;
#pragma unroll
        for (int nt = 0; nt < 2; nt++) {
            ushort2 s0 = split_h(oacc[nt][0]), s1 = split_h(oacc[nt][1]);
            ushort2 s2 = split_h(oacc[nt][2]), s3 = split_h(oacc[nt][3]);
            *(ushort2*)&C0[(size_t)orow * D_MODEL + ocol + nt * 8]       = make_ushort2(s0.x, s1.x);
            *(ushort2*)&C1[(size_t)orow * D_MODEL + ocol + nt * 8]       = make_ushort2(s0.y, s1.y);
            *(ushort2*)&C0[(size_t)(orow + 8) * D_MODEL + ocol + nt * 8] = make_ushort2(s2.x, s3.x);
            *(ushort2*)&C1[(size_t)(orow + 8) * D_MODEL + ocol + nt * 8] = make_ushort2(s2.y, s3.y);
        }
    }
}

// =================================================================================
// Residual add + LayerNorm (float4)
// =================================================================================
__global__ __launch_bounds__(256) void ln_kernel(
    const float* __restrict__ fc, const float* __restrict__ resid,
    const float* __restrict__ gamma, const float* __restrict__ beta,
    float* __restrict__ out)
{
    __shared__ float4 xs[256];
    __shared__ float rs[8], rss[8];

    const int row = blockIdx.x;
    const int t   = threadIdx.x;
    const float4* f = (const float4*)(fc    + (size_t)row * D_MODEL);
    const float4* r = (const float4*)(resid + (size_t)row * D_MODEL);

    float4 fx = f[t], rx = r[t];
    float4 x = { fx.x + rx.x, fx.y + rx.y, fx.z + rx.z, fx.w + rx.w };
    xs[t] = x;
    float s  = x.x + x.y + x.z + x.w;
    float ss = x.x * x.x + x.y * x.y + x.z * x.z + x.w * x.w;
#pragma unroll
    for (int o = 16; o > 0; o >>= 1) {
        s  += __shfl_xor_sync(0xffffffffu, s, o);
        ss += __shfl_xor_sync(0xffffffffu, ss, o);
    }
    int w = t >> 5, lane = t & 31;
    if (lane == 0) { rs[w] = s; rss[w] = ss; }
    __syncthreads();
    float ts = 0.f, tss = 0.f;
#pragma unroll
    for (int i = 0; i < 8; i++) { ts += rs[i]; tss += rss[i]; }
    float mu  = ts * (1.0f / D_MODEL);
    float var = tss * (1.0f / D_MODEL) - mu * mu;
    float kk  = rsqrtf(var + 1e-5f);

    const float4 g4 = ((const float4*)gamma)[t];
    const float4 b4 = ((const float4*)beta)[t];
    float4 xv = xs[t];
    float4 o4;
    o4.x = (xv.x - mu) * kk * g4.x + b4.x;
    o4.y = (xv.y - mu) * kk * g4.y + b4.y;
    o4.z = (xv.z - mu) * kk * g4.z + b4.z;
    o4.w = (xv.w - mu) * kk * g4.w + b4.w;
    ((float4*)(out + (size_t)row * D_MODEL))[t] = o4;
}

// =================================================================================
// launch
// =================================================================================
extern "C" void kernel_launch(void* const* d_in, const int* in_sizes, int n_in,
                              void* d_out, int out_size)
{
    const float* q    = (const float*)d_in[0];
    const float* k    = (const float*)d_in[1];
    const float* v    = (const float*)d_in[2];
    const unsigned char* mask = (const unsigned char*)d_in[3];
    const float* w_q  = (const float*)d_in[4];
    const float* b_q  = (const float*)d_in[5];
    const float* w_k  = (const float*)d_in[6];
    const float* b_k  = (const float*)d_in[7];
    const float* w_v  = (const float*)d_in[8];
    const float* b_v  = (const float*)d_in[9];
    const float* w_fc = (const float*)d_in[10];
    const float* b_fc = (const float*)d_in[11];
    const float* ln_g = (const float*)d_in[12];
    const float* ln_b = (const float*)d_in[13];
    float* out = (float*)d_out;

    float *qh, *vh, *ctx, *fc;
    unsigned short *a0, *a1, *a2, *a3, *b0, *b1, *b2, *b3, *k0s, *k1s;
    cudaGetSymbolAddress((void**)&qh,  g_qh);
    cudaGetSymbolAddress((void**)&vh,  g_vh);
    cudaGetSymbolAddress((void**)&ctx, g_ctx);
    cudaGetSymbolAddress((void**)&fc,  g_fc);
    cudaGetSymbolAddress((void**)&a0,  g_a0);
    cudaGetSymbolAddress((void**)&a1,  g_a1);
    cudaGetSymbolAddress((void**)&a2,  g_a2);
    cudaGetSymbolAddress((void**)&a3,  g_a3);
    cudaGetSymbolAddress((void**)&b0,  g_b0);
    cudaGetSymbolAddress((void**)&b1,  g_b1);
    cudaGetSymbolAddress((void**)&b2,  g_b2);
    cudaGetSymbolAddress((void**)&b3,  g_b3);
    cudaGetSymbolAddress((void**)&k0s, g_k0s);
    cudaGetSymbolAddress((void**)&k1s, g_k1s);

    unsigned short* q0s = (unsigned short*)qh;
    unsigned short* q1s = q0s + (size_t)MROWS * D_MODEL;
    unsigned short* c0s = (unsigned short*)ctx;
    unsigned short* c1s = c0s + (size_t)MROWS * D_MODEL;

    const long long xe = (long long)MROWS * D_MODEL;
    const long long ae = (long long)BATCH * NHEAD * SEQ * SEQ;
    float* attn_out = nullptr;
    float* x_out    = out;
    if ((long long)out_size >= xe + ae) {
        attn_out = out + xe;
    } else if ((long long)out_size == ae) {
        attn_out = out;
        x_out = nullptr;
    }

    cudaFuncSetAttribute((void*)gemm_2h<3, true>,  cudaFuncAttributeMaxDynamicSharedMemorySize, GSMEM2);
    cudaFuncSetAttribute((void*)gemm_2h<2, false>, cudaFuncAttributeMaxDynamicSharedMemorySize, GSMEM2);
    cudaFuncSetAttribute((void*)attn_mma, cudaFuncAttributeMaxDynamicSharedMemorySize, ATTN_SMEM);

    const int nA4 = MROWS * D_MODEL / 4;     // 2097152
    const int nW4 = D_MODEL * D_MODEL / 4;   // 262144
    dim3 gb(256);
    dim3 gg1(D_MODEL / 64, MROWS / 128, 1);
    dim3 gg2(D_MODEL / 64, MROWS / 128, 2);

    // stage 0: standalone splits for Q inputs
    split2h_kernel<<<2048, gb>>>(q, a0, a1, nA4);
    split2h_kernel<<<256,  gb>>>(w_q, b0, b1, nW4);

    // gemm Q (+fused: split k->a2/a3, w_k->b2/b3)
    gemm_2h<3, true><<<gg2, gb, GSMEM2>>>(a0, a1, b0, b1, b_q, nullptr, q0s, q1s,
                                          k, a2, a3, w_k, b2, b3);
    // gemm K (+fused: split v->a0/a1, w_v->b0/b1)
    gemm_2h<3, true><<<gg2, gb, GSMEM2>>>(a2, a3, b2, b3, b_k, nullptr, k0s, k1s,
                                          v, a0, a1, w_v, b0, b1);
    // gemm V (+fused: split w_fc->b2/b3)
    gemm_2h<2, false><<<gg2, gb, GSMEM2>>>(a0, a1, b0, b1, b_v, vh, nullptr, nullptr,
                                           nullptr, nullptr, nullptr, w_fc, b2, b3);

    vtrans_kernel<<<dim3(SEQ / 32, DKH / 32, BATCH * NHEAD), dim3(32, 8)>>>();

    dim3 ag(SEQ / 32, NHEAD, BATCH);
    attn_mma<<<ag, gb, ATTN_SMEM>>>(mask, attn_out, q0s, q1s, c0s, c1s);

    // FC (2-pass; weights pre-split during gemm V)
    gemm_2h<2, false><<<gg1, gb, GSMEM2>>>(c0s, c1s, b2, b3, b_fc, fc, nullptr, nullptr,
                                           nullptr, nullptr, nullptr,
                                           nullptr, nullptr, nullptr);

    if (x_out)
        ln_kernel<<<MROWS, gb>>>(fc, q, ln_g, ln_b, x_out);
}

// round 17
// speedup vs baseline: 1.2991x; 1.0842x over previous
#include <cuda_runtime.h>
#include <cuda_fp16.h>
#include <cstdint>
#include <cstddef>

#define D_MODEL 1024
#define NHEAD   16
#define DKH     64
#define BATCH   8
#define SEQ     1024
#define MROWS   (BATCH * SEQ)   // 8192

// ---------------- scratch (device globals: no cudaMalloc allowed) ----------------
__device__ float g_qh[MROWS * D_MODEL];    // carved as Q h/l split (ushort x2)
__device__ float g_vh[MROWS * D_MODEL];    // fp32 V (for vtrans)
__device__ float g_ctx[MROWS * D_MODEL];   // carved as ctx h/l split (ushort x2)
__device__ float g_fc[MROWS * D_MODEL];
__device__ __align__(16) unsigned short g_a0[MROWS * D_MODEL];
__device__ __align__(16) unsigned short g_a1[MROWS * D_MODEL];
__device__ __align__(16) unsigned short g_a2[MROWS * D_MODEL];
__device__ __align__(16) unsigned short g_a3[MROWS * D_MODEL];
__device__ __align__(16) unsigned short g_b0[D_MODEL * D_MODEL];
__device__ __align__(16) unsigned short g_b1[D_MODEL * D_MODEL];
__device__ __align__(16) unsigned short g_b2[D_MODEL * D_MODEL];
__device__ __align__(16) unsigned short g_b3[D_MODEL * D_MODEL];
__device__ __align__(16) unsigned short g_k0s[MROWS * D_MODEL];
__device__ __align__(16) unsigned short g_k1s[MROWS * D_MODEL];
__device__ __align__(16) unsigned short g_v0t[MROWS * D_MODEL];   // [bh][d][token]

// =================================================================================
// helpers
// =================================================================================
__device__ __forceinline__ uint32_t smem_u32(const void* p) {
    uint32_t a;
    asm("{ .reg .u64 t; cvta.to.shared.u64 t, %1; cvt.u32.u64 %0, t; }" : "=r"(a) : "l"(p));
    return a;
}
__device__ __forceinline__ void ldsm_x4(uint32_t* r, uint32_t addr) {
    asm volatile("ldmatrix.sync.aligned.m8n8.x4.shared.b16 {%0,%1,%2,%3}, [%4];"
        : "=r"(r[0]), "=r"(r[1]), "=r"(r[2]), "=r"(r[3]) : "r"(addr));
}
__device__ __forceinline__ void mma_f16(float* c, const uint32_t* a, const uint32_t* b) {
    asm volatile("mma.sync.aligned.m16n8k16.row.col.f32.f16.f16.f32 "
        "{%0,%1,%2,%3}, {%4,%5,%6,%7}, {%8,%9}, {%0,%1,%2,%3};"
        : "+f"(c[0]), "+f"(c[1]), "+f"(c[2]), "+f"(c[3])
        : "r"(a[0]), "r"(a[1]), "r"(a[2]), "r"(a[3]), "r"(b[0]), "r"(b[1]));
}
__device__ __forceinline__ void cp16(uint32_t dst, const void* src) {
    asm volatile("cp.async.cg.shared.global [%0], [%1], 16;" :: "r"(dst), "l"(src));
}
__device__ __forceinline__ ushort2 split_h(float x) {
    __half hb = __float2half_rn(x);
    float hf = __half2float(hb);
    __half lb = __float2half_rn(x - hf);
    return make_ushort2(__half_as_ushort(hb), __half_as_ushort(lb));
}
__device__ __forceinline__ void split_f4(const float* __restrict__ x,
                                         unsigned short* __restrict__ h,
                                         unsigned short* __restrict__ l, int i)
{
    float4 v = ((const float4*)x)[i];
    ushort2 s0 = split_h(v.x), s1 = split_h(v.y);
    ushort2 s2 = split_h(v.z), s3 = split_h(v.w);
    ((ushort4*)h)[i] = make_ushort4(s0.x, s1.x, s2.x, s3.x);
    ((ushort4*)l)[i] = make_ushort4(s0.y, s1.y, s2.y, s3.y);
}
// swizzled tile offset: row r (64B rows), 16B unit u -> conflict-free map
__device__ __forceinline__ uint32_t swz(uint32_t r, uint32_t u) {
    return r * 64 + ((u ^ ((r >> 1) & 3)) << 4);
}

// =================================================================================
// fp32 -> fp16 2-level split (grid-stride)
// =================================================================================
__global__ __launch_bounds__(256) void split2h_kernel(
    const float* __restrict__ x, unsigned short* __restrict__ h,
    unsigned short* __restrict__ l, int n4)
{
    int gid = blockIdx.x * 256 + threadIdx.x;
    int stride = gridDim.x * 256;
    for (int i = gid; i < n4; i += stride)
        split_f4(x, h, l, i);
}

// =================================================================================
// V transpose + fp16 quantize
// =================================================================================
__global__ __launch_bounds__(256) void vtrans_kernel()
{
    __shared__ float ttile[32][33];
    const int bh = blockIdx.z, b = bh >> 4, h = bh & 15;
    const int t0 = blockIdx.x * 32, d0 = blockIdx.y * 32;
    const int tx = threadIdx.x, ty = threadIdx.y;
#pragma unroll
    for (int j = 0; j < 4; j++) {
        int tok = t0 + ty + j * 8;
        ttile[ty + j * 8][tx] =
            g_vh[(size_t)(b * SEQ + tok) * D_MODEL + h * DKH + d0 + tx];
    }
    __syncthreads();
#pragma unroll
    for (int j = 0; j < 4; j++) {
        int d = d0 + ty + j * 8;
        float x = ttile[tx][ty + j * 8];
        size_t o = ((size_t)bh * DKH + d) * SEQ + t0 + tx;
        g_v0t[o] = __half_as_ushort(__float2half_rn(x));
    }
}

// =================================================================================
// 2-level fp16 mma GEMM — swizzled (pad-free) tiles, 3-stage ring, ONE barrier
// per chunk, 3 CTAs/SM. blockIdx.z==1 CTAs run next stage's input splits.
// =================================================================================
#define KC         32
#define NCHUNK     (D_MODEL / KC)
#define A_LEV      (128 * 64)            // 8192
#define B_LEV      (64 * 64)             // 4096
#define STAGE      (2 * A_LEV + 2 * B_LEV)   // 24576
#define GSMEM3     (3 * STAGE)               // 73728

template<int NPASS, bool SPLIT_OUT>
__global__ void __launch_bounds__(256, 3) gemm_2h(
    const unsigned short* __restrict__ A0, const unsigned short* __restrict__ A1,
    const unsigned short* __restrict__ B0, const unsigned short* __restrict__ B1,
    const float* __restrict__ bias,
    float* __restrict__ C,
    unsigned short* __restrict__ H, unsigned short* __restrict__ L,
    const float* __restrict__ FA, unsigned short* __restrict__ FA0,
    unsigned short* __restrict__ FA1,
    const float* __restrict__ FW, unsigned short* __restrict__ FW0,
    unsigned short* __restrict__ FW1)
{
    const int tid = threadIdx.x;

    // ---- fused split duty (extra CTAs) ----
    if (blockIdx.z == 1) {
        int gid = (blockIdx.y * gridDim.x + blockIdx.x) * 256 + tid;  // 0..262143
        if (FA) {
#pragma unroll
            for (int j = 0; j < 8; j++)
                split_f4(FA, FA0, FA1, gid + j * 262144);
        }
        if (FW)
            split_f4(FW, FW0, FW1, gid);
        return;
    }

    extern __shared__ char smc[];
    const uint32_t sbase = smem_u32(smc);
    const int wid = tid >> 5, lane = tid & 31;
    const int bn = blockIdx.x, bm = blockIdx.y;
    const int wm = wid & 3, wn = wid >> 2;

    const unsigned short* srcs[4];
    srcs[0] = A0 + (size_t)bm * 128 * D_MODEL;
    srcs[1] = A1 + (size_t)bm * 128 * D_MODEL;
    srcs[2] = B0 + (size_t)bn * 64 * D_MODEL;
    srcs[3] = B1 + (size_t)bn * 64 * D_MODEL;

    float acc[2][4][4];
#pragma unroll
    for (int i = 0; i < 2; i++)
#pragma unroll
        for (int j = 0; j < 4; j++)
#pragma unroll
            for (int v = 0; v < 4; v++) acc[i][j][v] = 0.f;

    // logical fragment rows/units (swizzle applied at address formation)
    const uint32_t ar = (uint32_t)(wm * 32 + (lane & 15));     // + mt*16
    const uint32_t au = (lane >> 4) & 1;                       // + kb*2
    const uint32_t br = (uint32_t)(wn * 32 + (lane & 7) + ((lane >> 4) & 1) * 8); // + np*16
    const uint32_t bu = (lane >> 3) & 1;                       // + kb*2

    auto fill = [&](int c, int s) {
        const uint32_t base = sbase + (uint32_t)s * STAGE;
#pragma unroll
        for (int n = 0; n < 6; n++) {
            int i = tid + n * 256;
            bool isA = i < 1024;
            int j   = isA ? i : i - 1024;
            int lev = isA ? (j >> 9) : (j >> 8);
            int r   = isA ? ((j >> 2) & 127) : ((j >> 2) & 63);
            int c16 = j & 3;
            const unsigned short* src = srcs[(isA ? 0 : 2) + lev]
                + (size_t)r * D_MODEL + c * KC + c16 * 8;
            uint32_t dst = base + (isA ? (uint32_t)lev * A_LEV
                                       : 2u * A_LEV + (uint32_t)lev * B_LEV)
                         + swz((uint32_t)r, (uint32_t)c16);
            cp16(dst, src);
        }
        asm volatile("cp.async.commit_group;" ::: "memory");
    };

    fill(0, 0);
    fill(1, 1);

    constexpr int PA[4] = { 0, 0, 1, 1 };
    constexpr int PB[4] = { 0, 1, 0, 1 };

    int stage = 0;
    for (int c = 0; c < NCHUNK; c++) {
        if (c + 1 < NCHUNK)
            asm volatile("cp.async.wait_group 1;" ::: "memory");
        else
            asm volatile("cp.async.wait_group 0;" ::: "memory");
        __syncthreads();                        // single barrier per chunk

        if (c + 2 < NCHUNK) {
            int fs = stage + 2; if (fs >= 3) fs -= 3;
            fill(c + 2, fs);                    // stage consumed at iter c-1
        }

        const uint32_t abase = sbase + (uint32_t)stage * STAGE;
        const uint32_t bbase = abase + 2 * A_LEV;

#pragma unroll
        for (int kb = 0; kb < 2; kb++) {
            uint32_t af[2][2][4], bfr[2][2][4];
#pragma unroll
            for (int lv = 0; lv < 2; lv++) {
#pragma unroll
                for (int mt = 0; mt < 2; mt++)
                    ldsm_x4(af[lv][mt], abase + lv * A_LEV
                            + swz(ar + mt * 16, au + kb * 2));
#pragma unroll
                for (int np = 0; np < 2; np++)
                    ldsm_x4(bfr[lv][np], bbase + lv * B_LEV
                            + swz(br + np * 16, bu + kb * 2));
            }
#pragma unroll
            for (int p = 0; p < NPASS; p++) {
#pragma unroll
                for (int mt = 0; mt < 2; mt++)
#pragma unroll
                    for (int nt = 0; nt < 4; nt++)
                        mma_f16(acc[mt][nt], af[PA[p]][mt],
                                &bfr[PB[p]][nt >> 1][(nt & 1) * 2]);
            }
        }
        if (++stage == 3) stage = 0;
    }

    const int qr = lane >> 2;
#pragma unroll
    for (int mt = 0; mt < 2; mt++) {
        int row0 = bm * 128 + wm * 32 + mt * 16 + qr;
#pragma unroll
        for (int nt = 0; nt < 4; nt++) {
            int col = bn * 64 + wn * 32 + nt * 8 + (lane & 3) * 2;
            float v00 = acc[mt][nt][0] + bias[col];
            float v01 = acc[mt][nt][1] + bias[col + 1];
            float v10 = acc[mt][nt][2] + bias[col];
            float v11 = acc[mt][nt][3] + bias[col + 1];
            if (SPLIT_OUT) {
                ushort2 h0 = split_h(v00), h1 = split_h(v01);
                ushort2 h2 = split_h(v10), h3 = split_h(v11);
                *(ushort2*)(H + (size_t)row0 * D_MODEL + col)       = make_ushort2(h0.x, h1.x);
                *(ushort2*)(L + (size_t)row0 * D_MODEL + col)       = make_ushort2(h0.y, h1.y);
                *(ushort2*)(H + (size_t)(row0 + 8) * D_MODEL + col) = make_ushort2(h2.x, h3.x);
                *(ushort2*)(L + (size_t)(row0 + 8) * D_MODEL + col) = make_ushort2(h2.y, h3.y);
            } else {
                float2 v0 = { v00, v01 }, v1 = { v10, v11 };
                *(float2*)(C + (size_t)row0 * D_MODEL + col)       = v0;
                *(float2*)(C + (size_t)(row0 + 8) * D_MODEL + col) = v1;
            }
        }
    }
}

// =================================================================================
// mma attention — fp32 scores, PV single pass, interleaved attn-out write.
// =================================================================================
#define PS_LD     1032
#define PS_BYTES  (32 * PS_LD * 4)       // 132096
#define KROWB     144
#define KLEV      (128 * KROWB)
#define KSTG      (2 * KLEV)             // 36864
#define VROWB     272
#define VLEV      (64 * VROWB)           // 17408
#define ATTN_SMEM (PS_BYTES + 2 * KSTG)  // 205824

__global__ __launch_bounds__(256) void attn_mma(
    const unsigned char* __restrict__ mask, float* __restrict__ attn_out,
    const unsigned short* __restrict__ Q0, const unsigned short* __restrict__ Q1,
    unsigned short* __restrict__ C0, unsigned short* __restrict__ C1)
{
    extern __shared__ char smraw[];
    float* Ps = (float*)smraw;
    const uint32_t tbase = smem_u32(smraw) + PS_BYTES;

    const int t = threadIdx.x, w = t >> 5, lane = t & 31;
    const int qt = blockIdx.x, h = blockIdx.y, b = blockIdx.z;
    const int q0 = qt * 32;

    uint32_t af[2][2][4][4];
    {
        const unsigned short* qs[2] = { Q0, Q1 };
        const int r0 = lane >> 2;
        const int c0 = (lane & 3) * 2;
#pragma unroll
        for (int lv = 0; lv < 2; lv++)
#pragma unroll
            for (int mt = 0; mt < 2; mt++)
#pragma unroll
                for (int ks = 0; ks < 4; ks++) {
                    size_t base = (size_t)(b * SEQ + q0 + mt * 16 + r0) * D_MODEL
                                + h * DKH + ks * 16 + c0;
                    af[lv][mt][ks][0] = *(const uint32_t*)(qs[lv] + base);
                    af[lv][mt][ks][1] = *(const uint32_t*)(qs[lv] + base + 8 * D_MODEL);
                    af[lv][mt][ks][2] = *(const uint32_t*)(qs[lv] + base + 8);
                    af[lv][mt][ks][3] = *(const uint32_t*)(qs[lv] + base + 8 * D_MODEL + 8);
                }
    }

    auto kfill = [&](int kt, int s) {
#pragma unroll
        for (int n = 0; n < 8; n++) {
            int i = t + n * 256;
            int lv = i >> 10, j = i & 1023;
            int r = j >> 3, u = j & 7;
            const unsigned short* src = (lv ? g_k1s : g_k0s)
                + (size_t)(b * SEQ + kt * 128 + r) * D_MODEL + h * DKH + u * 8;
            cp16(tbase + s * KSTG + lv * KLEV + (uint32_t)r * KROWB + u * 16, src);
        }
        asm volatile("cp.async.commit_group;" ::: "memory");
    };
    const uint32_t krow = (uint32_t)(w * 16 + (lane & 7) + ((lane >> 4) & 1) * 8) * KROWB
                        + ((lane >> 3) & 1) * 16;
    kfill(0, 0);
    kfill(1, 1);

    for (int kt = 0; kt < 8; kt++) {
        if (kt < 7) asm volatile("cp.async.wait_group 1;" ::: "memory");
        else        asm volatile("cp.async.wait_group 0;" ::: "memory");
        __syncthreads();
        const uint32_t kb = tbase + (kt & 1) * KSTG;

        uint32_t bf[2][4][4];
#pragma unroll
        for (int lv = 0; lv < 2; lv++)
#pragma unroll
            for (int ks = 0; ks < 4; ks++)
                ldsm_x4(bf[lv][ks], kb + lv * KLEV + krow + ks * 32);

        float acc[2][2][4];
#pragma unroll
        for (int i = 0; i < 2; i++)
#pragma unroll
            for (int j = 0; j < 2; j++)
#pragma unroll
                for (int v = 0; v < 4; v++) acc[i][j][v] = 0.f;

#pragma unroll
        for (int ks = 0; ks < 4; ks++) {
#pragma unroll
            for (int mt = 0; mt < 2; mt++)
#pragma unroll
                for (int nt = 0; nt < 2; nt++) {
                    mma_f16(acc[mt][nt], af[0][mt][ks], &bf[0][ks][nt * 2]);
                    mma_f16(acc[mt][nt], af[0][mt][ks], &bf[1][ks][nt * 2]);
                    mma_f16(acc[mt][nt], af[1][mt][ks], &bf[0][ks][nt * 2]);
                }
        }

#pragma unroll
        for (int mt = 0; mt < 2; mt++) {
#pragma unroll
            for (int nt = 0; nt < 2; nt++) {
                int row = mt * 16 + (lane >> 2);
                int col = kt * 128 + w * 16 + nt * 8 + (lane & 3) * 2;
                const unsigned char* mp0 =
                    mask + (size_t)(b * SEQ + q0 + row) * SEQ + col;
                const unsigned char* mp1 = mp0 + 8 * SEQ;
                float2 v0, v1;
                v0.x = mp0[0] ? -1e9f : acc[mt][nt][0] * 0.125f;
                v0.y = mp0[1] ? -1e9f : acc[mt][nt][1] * 0.125f;
                v1.x = mp1[0] ? -1e9f : acc[mt][nt][2] * 0.125f;
                v1.y = mp1[1] ? -1e9f : acc[mt][nt][3] * 0.125f;
                *(float2*)&Ps[row * PS_LD + col]       = v0;
                *(float2*)&Ps[(row + 8) * PS_LD + col] = v1;
            }
        }
        __syncthreads();
        if (kt + 2 < 8) kfill(kt + 2, kt & 1);
    }
    __syncthreads();

    {
        int row = t >> 3, sub = t & 7;
        float* pr = Ps + row * PS_LD;
        float m = -1e30f;
        for (int cc = sub; cc < SEQ; cc += 8) m = fmaxf(m, pr[cc]);
#pragma unroll
        for (int o = 4; o > 0; o >>= 1) m = fmaxf(m, __shfl_xor_sync(0xffffffffu, m, o, 8));
        float s = 0.f;
        for (int cc = sub; cc < SEQ; cc += 8) { float e = __expf(pr[cc] - m); pr[cc] = e; s += e; }
#pragma unroll
        for (int o = 4; o > 0; o >>= 1) s += __shfl_xor_sync(0xffffffffu, s, o, 8);
        float inv = 1.0f / s;
        for (int cc = sub; cc < SEQ; cc += 8) pr[cc] *= inv;
    }
    __syncthreads();   // softmax complete; Ps read-only from here

    auto vfill = [&](int kt, int s) {
#pragma unroll
        for (int n = 0; n < 4; n++) {
            int i = t + n * 256;
            int r = i >> 4, u = i & 15;
            const unsigned short* src = g_v0t
                + ((size_t)(b * NHEAD + h) * DKH + r) * SEQ + kt * 128 + u * 8;
            cp16(tbase + s * VLEV + (uint32_t)r * VROWB + u * 16, src);
        }
        asm volatile("cp.async.commit_group;" ::: "memory");
    };
    const int mh = w & 1, nq = w >> 1;
    const uint32_t vrow = (uint32_t)(nq * 16 + (lane & 7) + ((lane >> 4) & 1) * 8) * VROWB
                        + ((lane >> 3) & 1) * 16;
    float oacc[2][4];
#pragma unroll
    for (int i = 0; i < 2; i++)
#pragma unroll
        for (int v = 0; v < 4; v++) oacc[i][v] = 0.f;

    vfill(0, 0);
    vfill(1, 1);

    const int pr0 = mh * 16 + (lane >> 2);
    const int pc0 = (lane & 3) * 2;
    float* ab = attn_out ? attn_out + (((size_t)(b * NHEAD + h)) * SEQ + q0) * SEQ : nullptr;

    for (int kt = 0; kt < 8; kt++) {
        if (kt < 7) asm volatile("cp.async.wait_group 1;" ::: "memory");
        else        asm volatile("cp.async.wait_group 0;" ::: "memory");
        __syncthreads();
        const uint32_t vb = tbase + (kt & 1) * VLEV;

        if (ab) {
#pragma unroll
            for (int i = 0; i < 4; i++) {
                int idx = t + i * 256;
                int r  = idx >> 5;
                int c4 = (idx & 31) << 2;
                *(float4*)&ab[(size_t)r * SEQ + kt * 128 + c4] =
                    *(const float4*)&Ps[r * PS_LD + kt * 128 + c4];
            }
        }

#pragma unroll
        for (int ks = 0; ks < 8; ks++) {
            uint32_t bv[4];
            ldsm_x4(bv, vb + vrow + ks * 32);

            int pc = kt * 128 + ks * 16 + pc0;
            float2 p00 = *(float2*)&Ps[pr0 * PS_LD + pc];
            float2 p10 = *(float2*)&Ps[(pr0 + 8) * PS_LD + pc];
            float2 p01 = *(float2*)&Ps[pr0 * PS_LD + pc + 8];
            float2 p11 = *(float2*)&Ps[(pr0 + 8) * PS_LD + pc + 8];

            uint32_t ph[4];
            {
                __half2 h0 = __floats2half2_rn(p00.x, p00.y);
                __half2 h1 = __floats2half2_rn(p10.x, p10.y);
                __half2 h2 = __floats2half2_rn(p01.x, p01.y);
                __half2 h3 = __floats2half2_rn(p11.x, p11.y);
                ph[0] = *(uint32_t*)&h0; ph[1] = *(uint32_t*)&h1;
                ph[2] = *(uint32_t*)&h2; ph[3] = *(uint32_t*)&h3;
            }
            mma_f16(oacc[0], ph, &bv[0]);
            mma_f16(oacc[1], ph, &bv[2]);
        }
        __syncthreads();
        if (kt + 2 < 8) vfill(kt + 2, kt & 1);
    }

    {
        int orow = b * SEQ + q0 + pr0;
        int ocol = h * DKH + nq * 16 + pc0;
#pragma unroll
        for (int nt = 0; nt < 2; nt++) {
            ushort2 s0 = split_h(oacc[nt][0]), s1 = split_h(oacc[nt][1]);
            ushort2 s2 = split_h(oacc[nt][2]), s3 = split_h(oacc[nt][3]);
            *(ushort2*)&C0[(size_t)orow * D_MODEL + ocol + nt * 8]       = make_ushort2(s0.x, s1.x);
            *(ushort2*)&C1[(size_t)orow * D_MODEL + ocol + nt * 8]       = make_ushort2(s0.y, s1.y);
            *(ushort2*)&C0[(size_t)(orow + 8) * D_MODEL + ocol + nt * 8] = make_ushort2(s2.x, s3.x);
            *(ushort2*)&C1[(size_t)(orow + 8) * D_MODEL + ocol + nt * 8] = make_ushort2(s2.y, s3.y);
        }
    }
}

// =================================================================================
// Residual add + LayerNorm (float4)
// =================================================================================
__global__ __launch_bounds__(256) void ln_kernel(
    const float* __restrict__ fc, const float* __restrict__ resid,
    const float* __restrict__ gamma, const float* __restrict__ beta,
    float* __restrict__ out)
{
    __shared__ float4 xs[256];
    __shared__ float rs[8], rss[8];

    const int row = blockIdx.x;
    const int t   = threadIdx.x;
    const float4* f = (const float4*)(fc    + (size_t)row * D_MODEL);
    const float4* r = (const float4*)(resid + (size_t)row * D_MODEL);

    float4 fx = f[t], rx = r[t];
    float4 x = { fx.x + rx.x, fx.y + rx.y, fx.z + rx.z, fx.w + rx.w };
    xs[t] = x;
    float s  = x.x + x.y + x.z + x.w;
    float ss = x.x * x.x + x.y * x.y + x.z * x.z + x.w * x.w;
#pragma unroll
    for (int o = 16; o > 0; o >>= 1) {
        s  += __shfl_xor_sync(0xffffffffu, s, o);
        ss += __shfl_xor_sync(0xffffffffu, ss, o);
    }
    int w = t >> 5, lane = t & 31;
    if (lane == 0) { rs[w] = s; rss[w] = ss; }
    __syncthreads();
    float ts = 0.f, tss = 0.f;
#pragma unroll
    for (int i = 0; i < 8; i++) { ts += rs[i]; tss += rss[i]; }
    float mu  = ts * (1.0f / D_MODEL);
    float var = tss * (1.0f / D_MODEL) - mu * mu;
    float kk  = rsqrtf(var + 1e-5f);

    const float4 g4 = ((const float4*)gamma)[t];
    const float4 b4 = ((const float4*)beta)[t];
    float4 xv = xs[t];
    float4 o4;
    o4.x = (xv.x - mu) * kk * g4.x + b4.x;
    o4.y = (xv.y - mu) * kk * g4.y + b4.y;
    o4.z = (xv.z - mu) * kk * g4.z + b4.z;
    o4.w = (xv.w - mu) * kk * g4.w + b4.w;
    ((float4*)(out + (size_t)row * D_MODEL))[t] = o4;
}

// =================================================================================
// launch
// =================================================================================
extern "C" void kernel_launch(void* const* d_in, const int* in_sizes, int n_in,
                              void* d_out, int out_size)
{
    const float* q    = (const float*)d_in[0];
    const float* k    = (const float*)d_in[1];
    const float* v    = (const float*)d_in[2];
    const unsigned char* mask = (const unsigned char*)d_in[3];
    const float* w_q  = (const float*)d_in[4];
    const float* b_q  = (const float*)d_in[5];
    const float* w_k  = (const float*)d_in[6];
    const float* b_k  = (const float*)d_in[7];
    const float* w_v  = (const float*)d_in[8];
    const float* b_v  = (const float*)d_in[9];
    const float* w_fc = (const float*)d_in[10];
    const float* b_fc = (const float*)d_in[11];
    const float* ln_g = (const float*)d_in[12];
    const float* ln_b = (const float*)d_in[13];
    float* out = (float*)d_out;

    float *qh, *vh, *ctx, *fc;
    unsigned short *a0, *a1, *a2, *a3, *b0, *b1, *b2, *b3, *k0s, *k1s;
    cudaGetSymbolAddress((void**)&qh,  g_qh);
    cudaGetSymbolAddress((void**)&vh,  g_vh);
    cudaGetSymbolAddress((void**)&ctx, g_ctx);
    cudaGetSymbolAddress((void**)&fc,  g_fc);
    cudaGetSymbolAddress((void**)&a0,  g_a0);
    cudaGetSymbolAddress((void**)&a1,  g_a1);
    cudaGetSymbolAddress((void**)&a2,  g_a2);
    cudaGetSymbolAddress((void**)&a3,  g_a3);
    cudaGetSymbolAddress((void**)&b0,  g_b0);
    cudaGetSymbolAddress((void**)&b1,  g_b1);
    cudaGetSymbolAddress((void**)&b2,  g_b2);
    cudaGetSymbolAddress((void**)&b3,  g_b3);
    cudaGetSymbolAddress((void**)&k0s, g_k0s);
    cudaGetSymbolAddress((void**)&k1s, g_k1s);

    unsigned short* q0s = (unsigned short*)qh;
    unsigned short* q1s = q0s + (size_t)MROWS * D_MODEL;
    unsigned short* c0s = (unsigned short*)ctx;
    unsigned short* c1s = c0s + (size_t)MROWS * D_MODEL;

    const long long xe = (long long)MROWS * D_MODEL;
    const long long ae = (long long)BATCH * NHEAD * SEQ * SEQ;
    float* attn_out = nullptr;
    float* x_out    = out;
    if ((long long)out_size >= xe + ae) {
        attn_out = out + xe;
    } else if ((long long)out_size == ae) {
        attn_out = out;
        x_out = nullptr;
    }

    cudaFuncSetAttribute((void*)gemm_2h<3, true>,  cudaFuncAttributeMaxDynamicSharedMemorySize, GSMEM3);
    cudaFuncSetAttribute((void*)gemm_2h<2, false>, cudaFuncAttributeMaxDynamicSharedMemorySize, GSMEM3);
    cudaFuncSetAttribute((void*)attn_mma, cudaFuncAttributeMaxDynamicSharedMemorySize, ATTN_SMEM);

    const int nA4 = MROWS * D_MODEL / 4;     // 2097152
    const int nW4 = D_MODEL * D_MODEL / 4;   // 262144
    dim3 gb(256);
    dim3 gg1(D_MODEL / 64, MROWS / 128, 1);
    dim3 gg2(D_MODEL / 64, MROWS / 128, 2);

    // stage 0: standalone splits for Q inputs
    split2h_kernel<<<2048, gb>>>(q, a0, a1, nA4);
    split2h_kernel<<<256,  gb>>>(w_q, b0, b1, nW4);

    // gemm Q (+fused: split k->a2/a3, w_k->b2/b3)
    gemm_2h<3, true><<<gg2, gb, GSMEM3>>>(a0, a1, b0, b1, b_q, nullptr, q0s, q1s,
                                          k, a2, a3, w_k, b2, b3);
    // gemm K (+fused: split v->a0/a1, w_v->b0/b1)
    gemm_2h<3, true><<<gg2, gb, GSMEM3>>>(a2, a3, b2, b3, b_k, nullptr, k0s, k1s,
                                          v, a0, a1, w_v, b0, b1);
    // gemm V (+fused: split w_fc->b2/b3)
    gemm_2h<2, false><<<gg2, gb, GSMEM3>>>(a0, a1, b0, b1, b_v, vh, nullptr, nullptr,
                                           nullptr, nullptr, nullptr, w_fc, b2, b3);

    vtrans_kernel<<<dim3(SEQ / 32, DKH / 32, BATCH * NHEAD), dim3(32, 8)>>>();

    dim3 ag(SEQ / 32, NHEAD, BATCH);
    attn_mma<<<ag, gb, ATTN_SMEM>>>(mask, attn_out, q0s, q1s, c0s, c1s);

    // FC (2-pass; weights pre-split during gemm V)
    gemm_2h<2, false><<<gg1, gb, GSMEM3>>>(c0s, c1s, b2, b3, b_fc, fc, nullptr, nullptr,
                                           nullptr, nullptr, nullptr,
                                           nullptr, nullptr, nullptr);

    if (x_out)
        ln_kernel<<<MROWS, gb>>>(fc, q, ln_g, ln_b, x_out);
}